// round 5
// baseline (speedup 1.0000x reference)
#include <cuda_runtime.h>
#include <cuda_bf16.h>
#include <cstdint>
#include <math.h>

#define BATCH 2
#define SEQ   2048
#define DMODEL 1024
#define NHEADS 16
#define HDIM  64
#define MTOT  (BATCH*SEQ)   // 4096

// ---------------- scratch (allocation-free rule: device globals) -----------
__device__ __nv_bfloat16 g_ahi[MTOT*DMODEL];
__device__ __nv_bfloat16 g_alo[MTOT*DMODEL];
__device__ __nv_bfloat16 g_whi[DMODEL*DMODEL];
__device__ __nv_bfloat16 g_wlo[DMODEL*DMODEL];
__device__ __nv_bfloat16 g_qhi[MTOT*DMODEL];
__device__ __nv_bfloat16 g_qlo[MTOT*DMODEL];
__device__ __nv_bfloat16 g_khi[MTOT*DMODEL];
__device__ __nv_bfloat16 g_klo[MTOT*DMODEL];
__device__ __nv_bfloat16 g_vhi[MTOT*DMODEL];
__device__ __nv_bfloat16 g_vlo[MTOT*DMODEL];

// ---------------- helpers ---------------------------------------------------
__device__ __forceinline__ uint32_t smem_u32(const void* p) {
    uint32_t a;
    asm("{ .reg .u64 t; cvta.to.shared.u64 t, %1; cvt.u32.u64 %0, t; }"
        : "=r"(a) : "l"(p));
    return a;
}
__device__ __forceinline__ void cp16(uint32_t s, const void* g) {
    asm volatile("cp.async.cg.shared.global [%0], [%1], 16;" :: "r"(s), "l"(g));
}
#define CP_COMMIT()  asm volatile("cp.async.commit_group;" ::: "memory")
#define CP_WAIT(n)   asm volatile("cp.async.wait_group %0;" :: "n"(n) : "memory")

__device__ __forceinline__ void ldsm_x4(uint32_t* r, uint32_t addr) {
    asm volatile("ldmatrix.sync.aligned.m8n8.x4.shared.b16 {%0,%1,%2,%3}, [%4];"
                 : "=r"(r[0]), "=r"(r[1]), "=r"(r[2]), "=r"(r[3]) : "r"(addr));
}
__device__ __forceinline__ void ldsm_x4_t(uint32_t* r, uint32_t addr) {
    asm volatile("ldmatrix.sync.aligned.m8n8.x4.trans.shared.b16 {%0,%1,%2,%3}, [%4];"
                 : "=r"(r[0]), "=r"(r[1]), "=r"(r[2]), "=r"(r[3]) : "r"(addr));
}
__device__ __forceinline__ void mma16816(float* d, const uint32_t* a,
                                         const uint32_t* b) {
    asm volatile(
        "mma.sync.aligned.m16n8k16.row.col.f32.bf16.bf16.f32 "
        "{%0,%1,%2,%3}, {%4,%5,%6,%7}, {%8,%9}, {%0,%1,%2,%3};"
        : "+f"(d[0]), "+f"(d[1]), "+f"(d[2]), "+f"(d[3])
        : "r"(a[0]), "r"(a[1]), "r"(a[2]), "r"(a[3]), "r"(b[0]), "r"(b[1]));
}
// pack (x,y) to bf16x2 hi plus residual lo
__device__ __forceinline__ void pack_split(float x, float y,
                                           uint32_t& hi, uint32_t& lo) {
    uint32_t h;
    asm("cvt.rn.bf16x2.f32 %0, %1, %2;" : "=r"(h) : "f"(y), "f"(x));
    float hx = __uint_as_float(h << 16);
    float hy = __uint_as_float(h & 0xffff0000u);
    float lx = x - hx, ly = y - hy;
    uint32_t l;
    asm("cvt.rn.bf16x2.f32 %0, %1, %2;" : "=r"(l) : "f"(ly), "f"(lx));
    hi = h; lo = l;
}

// ---------------------------------------------------------------------------
// split fp32 -> (bf16 hi, bf16 lo)   (inputs + weights only now)
// ---------------------------------------------------------------------------
__global__ __launch_bounds__(256)
void split_kernel(const float4* __restrict__ x, uint32_t* __restrict__ hi,
                  uint32_t* __restrict__ lo, int n4)
{
    int i = blockIdx.x * 256 + threadIdx.x;
    if (i >= n4) return;
    float4 v = x[i];
    uint32_t h0, l0, h1, l1;
    pack_split(v.x, v.y, h0, l0);
    pack_split(v.z, v.w, h1, l1);
    hi[2*i] = h0; hi[2*i+1] = h1;
    lo[2*i] = l0; lo[2*i+1] = l1;
}

// ---------------------------------------------------------------------------
// mma.sync bf16 GEMM: out = A*W^T + bias, split-bf16 3-MMA, 3-stage cp.async.
// Epilogue: fp32 out (outf != 0) OR bf16 hi/lo out with scale.
// ---------------------------------------------------------------------------
#define BM 128
#define BN 128
#define BK 32
#define NCHUNK (DMODEL / BK)        // 32
#define ROWB 80
#define MAT_B (128 * ROWB)
#define OFF_AH 0
#define OFF_AL (1 * MAT_B)
#define OFF_BH (2 * MAT_B)
#define OFF_BL (3 * MAT_B)
#define STAGE_B (4 * MAT_B)         // 40960
#define GEMM_SMEM (3 * STAGE_B)     // 122880

__global__ __launch_bounds__(256)
void gemm_mma_kernel(const __nv_bfloat16* __restrict__ Ahi,
                     const __nv_bfloat16* __restrict__ Alo,
                     const __nv_bfloat16* __restrict__ Bhi,
                     const __nv_bfloat16* __restrict__ Blo,
                     const float* __restrict__ bias,
                     float* __restrict__ outf,
                     uint32_t* __restrict__ outhi,
                     uint32_t* __restrict__ outlo,
                     float scale)
{
    extern __shared__ char smraw[];
    const uint32_t sbase = smem_u32(smraw);
    const int tid  = threadIdx.x;
    const int lane = tid & 31;
    const int wid  = tid >> 5;
    const int wm   = (wid & 3) * 32;
    const int wn   = (wid >> 2) * 64;
    const int n0   = blockIdx.x * BN;
    const int m0   = blockIdx.y * BM;

    float c[2][8][4];
    #pragma unroll
    for (int mt = 0; mt < 2; mt++)
        #pragma unroll
        for (int nt = 0; nt < 8; nt++)
            #pragma unroll
            for (int j = 0; j < 4; j++) c[mt][nt][j] = 0.0f;

    auto load_chunk = [&](int ck, int s) {
        uint32_t st = sbase + s * STAGE_B;
        int k0 = ck * BK;
        #pragma unroll
        for (int u = tid; u < 512; u += 256) {
            int r = u >> 2, c16 = u & 3;
            uint32_t d = st + r * ROWB + c16 * 16;
            size_t g = (size_t)(m0 + r) * DMODEL + k0 + c16 * 8;
            cp16(d + OFF_AH, Ahi + g);
            cp16(d + OFF_AL, Alo + g);
        }
        #pragma unroll
        for (int u = tid; u < 512; u += 256) {
            int r = u >> 2, c16 = u & 3;
            uint32_t d = st + r * ROWB + c16 * 16;
            size_t g = (size_t)(n0 + r) * DMODEL + k0 + c16 * 8;
            cp16(d + OFF_BH, Bhi + g);
            cp16(d + OFF_BL, Blo + g);
        }
    };

    load_chunk(0, 0); CP_COMMIT();
    load_chunk(1, 1); CP_COMMIT();

    const int a_row  = lane & 15;
    const int a_kb   = ((lane >> 4) & 1) * 16;
    const int b_row  = (lane & 7) + ((lane >> 4) & 1) * 8;
    const int b_kb   = ((lane >> 3) & 1) * 16;

    for (int ck = 0; ck < NCHUNK; ck++) {
        int s = ck % 3;
        if (ck + 2 < NCHUNK) {
            load_chunk(ck + 2, (ck + 2) % 3); CP_COMMIT();
            CP_WAIT(2);
        } else if (ck + 1 < NCHUNK) {
            CP_WAIT(1);
        } else {
            CP_WAIT(0);
        }
        __syncthreads();

        uint32_t st = sbase + s * STAGE_B;
        #pragma unroll
        for (int ks = 0; ks < 2; ks++) {
            int kb = ks * 32;
            uint32_t ah[2][4], al[2][4];
            #pragma unroll
            for (int mt = 0; mt < 2; mt++) {
                uint32_t addr = st + (wm + mt * 16 + a_row) * ROWB + kb + a_kb;
                ldsm_x4(ah[mt], addr + OFF_AH);
                ldsm_x4(al[mt], addr + OFF_AL);
            }
            #pragma unroll
            for (int np = 0; np < 4; np++) {
                uint32_t bh4[4], bl4[4];
                uint32_t addr = st + (wn + np * 16 + b_row) * ROWB + kb + b_kb;
                ldsm_x4(bh4, addr + OFF_BH);
                ldsm_x4(bl4, addr + OFF_BL);
                #pragma unroll
                for (int mt = 0; mt < 2; mt++) {
                    mma16816(c[mt][np*2],   ah[mt], bh4);
                    mma16816(c[mt][np*2],   ah[mt], bl4);
                    mma16816(c[mt][np*2],   al[mt], bh4);
                    mma16816(c[mt][np*2+1], ah[mt], bh4 + 2);
                    mma16816(c[mt][np*2+1], ah[mt], bl4 + 2);
                    mma16816(c[mt][np*2+1], al[mt], bh4 + 2);
                }
            }
        }
        __syncthreads();
    }

    const int g  = lane >> 2;
    const int cq = (lane & 3) * 2;
    #pragma unroll
    for (int mt = 0; mt < 2; mt++) {
        #pragma unroll
        for (int nt = 0; nt < 8; nt++) {
            int col = n0 + wn + nt * 8 + cq;
            float2 bv = *(const float2*)(bias + col);
            int r0 = m0 + wm + mt * 16 + g;
            float x0 = c[mt][nt][0] + bv.x, y0 = c[mt][nt][1] + bv.y;
            float x1 = c[mt][nt][2] + bv.x, y1 = c[mt][nt][3] + bv.y;
            if (outf) {
                *(float2*)(outf + (size_t)r0 * DMODEL + col) = make_float2(x0, y0);
                *(float2*)(outf + (size_t)(r0 + 8) * DMODEL + col) = make_float2(x1, y1);
            } else {
                uint32_t h, l;
                pack_split(x0 * scale, y0 * scale, h, l);
                size_t idx0 = ((size_t)r0 * DMODEL + col) >> 1;
                outhi[idx0] = h; outlo[idx0] = l;
                pack_split(x1 * scale, y1 * scale, h, l);
                size_t idx1 = ((size_t)(r0 + 8) * DMODEL + col) >> 1;
                outhi[idx1] = h; outlo[idx1] = l;
            }
        }
    }
}

// ---------------------------------------------------------------------------
// FA2-style mma.sync attention, split-bf16, 3-stage KV pipeline.
// Epilogue writes joint as bf16 hi/lo (feeds the output projection directly).
// ---------------------------------------------------------------------------
#define AROWB 144
#define AQ_B   (128 * AROWB)      // 18432
#define AKV_B  (64 * AROWB)       // 9216
#define A_OFF_QH 0
#define A_OFF_QL AQ_B
#define A_STAGE0 (2 * AQ_B)       // 36864
#define A_STAGE_B (4 * AKV_B)     // 36864
#define A_OFF_KH 0
#define A_OFF_KL AKV_B
#define A_OFF_VH (2 * AKV_B)
#define A_OFF_VL (3 * AKV_B)
#define ATTN_SMEM (A_STAGE0 + 3 * A_STAGE_B)   // 147456
#define NKT (SEQ / 64)            // 32

__global__ __launch_bounds__(256, 1)
void attn_mma_kernel(const __nv_bfloat16* __restrict__ qhi,
                     const __nv_bfloat16* __restrict__ qlo,
                     const __nv_bfloat16* __restrict__ khi,
                     const __nv_bfloat16* __restrict__ klo,
                     const __nv_bfloat16* __restrict__ vhi,
                     const __nv_bfloat16* __restrict__ vlo,
                     const int* __restrict__ mask,
                     uint32_t* __restrict__ jhi,
                     uint32_t* __restrict__ jlo)
{
    extern __shared__ char smraw[];
    const uint32_t sbase = smem_u32(smraw);
    const int tid  = threadIdx.x;
    const int lane = tid & 31;
    const int wid  = tid >> 5;
    const int wm   = wid * 16;
    const int b    = blockIdx.z;
    const int h    = blockIdx.y;
    const int q0   = blockIdx.x * 128;

    // ---- load Q tile (hi/lo) ----
    #pragma unroll
    for (int u = tid; u < 1024; u += 256) {
        int r = u >> 3, c16 = u & 7;
        uint32_t d = sbase + r * AROWB + c16 * 16;
        size_t g = ((size_t)(b * SEQ + q0 + r)) * DMODEL + h * HDIM + c16 * 8;
        cp16(d + A_OFF_QH, qhi + g);
        cp16(d + A_OFF_QL, qlo + g);
    }
    CP_COMMIT();

    auto load_kv = [&](int kt, int s) {
        uint32_t st = sbase + A_STAGE0 + s * A_STAGE_B;
        int k0 = kt * 64;
        #pragma unroll
        for (int u = tid; u < 512; u += 256) {
            int r = u >> 3, c16 = u & 7;
            uint32_t d = st + r * AROWB + c16 * 16;
            size_t g = ((size_t)(b * SEQ + k0 + r)) * DMODEL + h * HDIM + c16 * 8;
            cp16(d + A_OFF_KH, khi + g);
            cp16(d + A_OFF_KL, klo + g);
            cp16(d + A_OFF_VH, vhi + g);
            cp16(d + A_OFF_VL, vlo + g);
        }
    };

    load_kv(0, 0); CP_COMMIT();
    load_kv(1, 1); CP_COMMIT();

    // wait for Q (3 groups in flight: Q, kv0, kv1 -> wait until <=2 left)
    CP_WAIT(2);
    __syncthreads();

    // ---- preload Q fragments ----
    uint32_t aqh[4][4], aql[4][4];
    {
        const int a_row = lane & 15;
        const int a_kb  = ((lane >> 4) & 1) * 16;
        #pragma unroll
        for (int kc = 0; kc < 4; kc++) {
            uint32_t addr = sbase + (wm + a_row) * AROWB + kc * 32 + a_kb;
            ldsm_x4(aqh[kc], addr + A_OFF_QH);
            ldsm_x4(aql[kc], addr + A_OFF_QL);
        }
    }

    const int g_   = lane >> 2;
    const int cq   = (lane & 3) * 2;
    const int b_row = (lane & 7) + ((lane >> 4) & 1) * 8;
    const int b_kb  = ((lane >> 3) & 1) * 16;
    const int v_row = lane & 15;
    const int v_col = (lane >> 4) * 8;

    const size_t mrow0 = ((size_t)b * SEQ + q0 + wm + g_) * SEQ;
    const size_t mrow1 = mrow0 + (size_t)8 * SEQ;

    float o[8][4];
    #pragma unroll
    for (int i = 0; i < 8; i++)
        #pragma unroll
        for (int j = 0; j < 4; j++) o[i][j] = 0.0f;
    float m0r = -INFINITY, m1r = -INFINITY, l0r = 0.0f, l1r = 0.0f;

    for (int kt = 0; kt < NKT; kt++) {
        int s = kt % 3;
        if (kt + 2 < NKT) {
            load_kv(kt + 2, (kt + 2) % 3); CP_COMMIT();
            CP_WAIT(2);
        } else if (kt + 1 < NKT) {
            CP_WAIT(1);
        } else {
            CP_WAIT(0);
        }
        __syncthreads();

        uint32_t st = sbase + A_STAGE0 + s * A_STAGE_B;
        int k0 = kt * 64;

        // ---- S = Q K^T ----
        float sc[8][4];
        #pragma unroll
        for (int i = 0; i < 8; i++)
            #pragma unroll
            for (int j = 0; j < 4; j++) sc[i][j] = 0.0f;

        #pragma unroll
        for (int kc = 0; kc < 4; kc++) {
            #pragma unroll
            for (int np = 0; np < 4; np++) {
                uint32_t bh4[4], bl4[4];
                uint32_t addr = st + (np * 16 + b_row) * AROWB + kc * 32 + b_kb;
                ldsm_x4(bh4, addr + A_OFF_KH);
                ldsm_x4(bl4, addr + A_OFF_KL);
                mma16816(sc[np*2],   aqh[kc], bh4);
                mma16816(sc[np*2],   aqh[kc], bl4);
                mma16816(sc[np*2],   aql[kc], bh4);
                mma16816(sc[np*2+1], aqh[kc], bh4 + 2);
                mma16816(sc[np*2+1], aqh[kc], bl4 + 2);
                mma16816(sc[np*2+1], aql[kc], bh4 + 2);
            }
        }

        // ---- mask ----
        #pragma unroll
        for (int nt = 0; nt < 8; nt++) {
            int2 mm0 = *(const int2*)(mask + mrow0 + k0 + nt * 8 + cq);
            int2 mm1 = *(const int2*)(mask + mrow1 + k0 + nt * 8 + cq);
            if (mm0.x == 0) sc[nt][0] = -1000000000.0f;
            if (mm0.y == 0) sc[nt][1] = -1000000000.0f;
            if (mm1.x == 0) sc[nt][2] = -1000000000.0f;
            if (mm1.y == 0) sc[nt][3] = -1000000000.0f;
        }

        // ---- online softmax ----
        float mx0 = sc[0][0], mx1 = sc[0][2];
        #pragma unroll
        for (int nt = 0; nt < 8; nt++) {
            mx0 = fmaxf(mx0, fmaxf(sc[nt][0], sc[nt][1]));
            mx1 = fmaxf(mx1, fmaxf(sc[nt][2], sc[nt][3]));
        }
        mx0 = fmaxf(mx0, __shfl_xor_sync(0xffffffff, mx0, 1));
        mx0 = fmaxf(mx0, __shfl_xor_sync(0xffffffff, mx0, 2));
        mx1 = fmaxf(mx1, __shfl_xor_sync(0xffffffff, mx1, 1));
        mx1 = fmaxf(mx1, __shfl_xor_sync(0xffffffff, mx1, 2));

        float mn0 = fmaxf(m0r, mx0), mn1 = fmaxf(m1r, mx1);
        float al0 = __expf(m0r - mn0), al1 = __expf(m1r - mn1);
        m0r = mn0; m1r = mn1;

        float rs0 = 0.0f, rs1 = 0.0f;
        #pragma unroll
        for (int nt = 0; nt < 8; nt++) {
            sc[nt][0] = __expf(sc[nt][0] - mn0); rs0 += sc[nt][0];
            sc[nt][1] = __expf(sc[nt][1] - mn0); rs0 += sc[nt][1];
            sc[nt][2] = __expf(sc[nt][2] - mn1); rs1 += sc[nt][2];
            sc[nt][3] = __expf(sc[nt][3] - mn1); rs1 += sc[nt][3];
        }
        rs0 += __shfl_xor_sync(0xffffffff, rs0, 1);
        rs0 += __shfl_xor_sync(0xffffffff, rs0, 2);
        rs1 += __shfl_xor_sync(0xffffffff, rs1, 1);
        rs1 += __shfl_xor_sync(0xffffffff, rs1, 2);
        l0r = l0r * al0 + rs0;
        l1r = l1r * al1 + rs1;

        #pragma unroll
        for (int nt = 0; nt < 8; nt++) {
            o[nt][0] *= al0; o[nt][1] *= al0;
            o[nt][2] *= al1; o[nt][3] *= al1;
        }

        // ---- pack P into A-fragments ----
        uint32_t ph[4][4], pl[4][4];
        #pragma unroll
        for (int tp = 0; tp < 4; tp++) {
            pack_split(sc[2*tp][0],   sc[2*tp][1],   ph[tp][0], pl[tp][0]);
            pack_split(sc[2*tp][2],   sc[2*tp][3],   ph[tp][1], pl[tp][1]);
            pack_split(sc[2*tp+1][0], sc[2*tp+1][1], ph[tp][2], pl[tp][2]);
            pack_split(sc[2*tp+1][2], sc[2*tp+1][3], ph[tp][3], pl[tp][3]);
        }

        // ---- O += P V ----
        #pragma unroll
        for (int nt2 = 0; nt2 < 4; nt2++) {
            #pragma unroll
            for (int tp = 0; tp < 4; tp++) {
                uint32_t vh4[4], vl4[4];
                uint32_t addr = st + A_OFF_VH + (tp * 16 + v_row) * AROWB
                              + (nt2 * 16 + v_col) * 2;
                ldsm_x4_t(vh4, addr);
                ldsm_x4_t(vl4, addr + (A_OFF_VL - A_OFF_VH));
                mma16816(o[nt2*2],   ph[tp], vh4);
                mma16816(o[nt2*2],   ph[tp], vl4);
                mma16816(o[nt2*2],   pl[tp], vh4);
                mma16816(o[nt2*2+1], ph[tp], vh4 + 2);
                mma16816(o[nt2*2+1], ph[tp], vl4 + 2);
                mma16816(o[nt2*2+1], pl[tp], vh4 + 2);
            }
        }
        __syncthreads();   // done reading buffer s before it is refilled
    }

    // ---- epilogue: write joint as bf16 hi/lo ----
    float inv0 = 1.0f / l0r, inv1 = 1.0f / l1r;
    size_t row0 = ((size_t)(b * SEQ + q0 + wm + g_)) * DMODEL + h * HDIM;
    #pragma unroll
    for (int nt = 0; nt < 8; nt++) {
        int col = nt * 8 + cq;
        uint32_t hh, ll;
        pack_split(o[nt][0] * inv0, o[nt][1] * inv0, hh, ll);
        size_t i0 = (row0 + col) >> 1;
        jhi[i0] = hh; jlo[i0] = ll;
        pack_split(o[nt][2] * inv1, o[nt][3] * inv1, hh, ll);
        size_t i1 = (row0 + (size_t)8 * DMODEL + col) >> 1;
        jhi[i1] = hh; jlo[i1] = ll;
    }
}

// ---------------------------------------------------------------------------
extern "C" void kernel_launch(void* const* d_in, const int* in_sizes, int n_in,
                              void* d_out, int out_size)
{
    const float* q    = (const float*)d_in[0];
    const float* k    = (const float*)d_in[1];
    const float* v    = (const float*)d_in[2];
    const int*   mask = (const int*)  d_in[3];
    const float* Wq   = (const float*)d_in[4];
    const float* bq   = (const float*)d_in[5];
    const float* Wk   = (const float*)d_in[6];
    const float* bk   = (const float*)d_in[7];
    const float* Wv   = (const float*)d_in[8];
    const float* bv   = (const float*)d_in[9];
    const float* Wo   = (const float*)d_in[10];
    const float* bo   = (const float*)d_in[11];
    float* out = (float*)d_out;

    void *p_ahi, *p_alo, *p_whi, *p_wlo;
    void *p_qhi, *p_qlo, *p_khi, *p_klo, *p_vhi, *p_vlo;
    cudaGetSymbolAddress(&p_ahi, g_ahi);
    cudaGetSymbolAddress(&p_alo, g_alo);
    cudaGetSymbolAddress(&p_whi, g_whi);
    cudaGetSymbolAddress(&p_wlo, g_wlo);
    cudaGetSymbolAddress(&p_qhi, g_qhi);
    cudaGetSymbolAddress(&p_qlo, g_qlo);
    cudaGetSymbolAddress(&p_khi, g_khi);
    cudaGetSymbolAddress(&p_klo, g_klo);
    cudaGetSymbolAddress(&p_vhi, g_vhi);
    cudaGetSymbolAddress(&p_vlo, g_vlo);

    __nv_bfloat16* ahi = (__nv_bfloat16*)p_ahi;
    __nv_bfloat16* alo = (__nv_bfloat16*)p_alo;
    __nv_bfloat16* whi = (__nv_bfloat16*)p_whi;
    __nv_bfloat16* wlo = (__nv_bfloat16*)p_wlo;

    const int nX4 = MTOT * DMODEL / 4;
    const int nW4 = DMODEL * DMODEL / 4;

    cudaFuncSetAttribute(gemm_mma_kernel,
                         cudaFuncAttributeMaxDynamicSharedMemorySize, GEMM_SMEM);
    cudaFuncSetAttribute(attn_mma_kernel,
                         cudaFuncAttributeMaxDynamicSharedMemorySize, ATTN_SMEM);

    dim3 gg(DMODEL / BN, MTOT / BM);

    // Q projection -> bf16 hi/lo with 1/8 scale fused
    split_kernel<<<nX4 / 256, 256>>>((const float4*)q, (uint32_t*)p_ahi, (uint32_t*)p_alo, nX4);
    split_kernel<<<nW4 / 256, 256>>>((const float4*)Wq, (uint32_t*)p_whi, (uint32_t*)p_wlo, nW4);
    gemm_mma_kernel<<<gg, 256, GEMM_SMEM>>>(ahi, alo, whi, wlo, bq,
        nullptr, (uint32_t*)p_qhi, (uint32_t*)p_qlo, 0.125f);

    // K projection -> bf16 hi/lo
    split_kernel<<<nX4 / 256, 256>>>((const float4*)k, (uint32_t*)p_ahi, (uint32_t*)p_alo, nX4);
    split_kernel<<<nW4 / 256, 256>>>((const float4*)Wk, (uint32_t*)p_whi, (uint32_t*)p_wlo, nW4);
    gemm_mma_kernel<<<gg, 256, GEMM_SMEM>>>(ahi, alo, whi, wlo, bk,
        nullptr, (uint32_t*)p_khi, (uint32_t*)p_klo, 1.0f);

    // V projection -> bf16 hi/lo
    split_kernel<<<nX4 / 256, 256>>>((const float4*)v, (uint32_t*)p_ahi, (uint32_t*)p_alo, nX4);
    split_kernel<<<nW4 / 256, 256>>>((const float4*)Wv, (uint32_t*)p_whi, (uint32_t*)p_wlo, nW4);
    gemm_mma_kernel<<<gg, 256, GEMM_SMEM>>>(ahi, alo, whi, wlo, bv,
        nullptr, (uint32_t*)p_vhi, (uint32_t*)p_vlo, 1.0f);

    // attention -> joint bf16 hi/lo (into ahi/alo, consumed by output proj)
    dim3 ag(SEQ / 128, NHEADS, BATCH);
    attn_mma_kernel<<<ag, 256, ATTN_SMEM>>>(
        (const __nv_bfloat16*)p_qhi, (const __nv_bfloat16*)p_qlo,
        (const __nv_bfloat16*)p_khi, (const __nv_bfloat16*)p_klo,
        (const __nv_bfloat16*)p_vhi, (const __nv_bfloat16*)p_vlo,
        mask, (uint32_t*)p_ahi, (uint32_t*)p_alo);

    // output projection (fp32 out)
    split_kernel<<<nW4 / 256, 256>>>((const float4*)Wo, (uint32_t*)p_whi, (uint32_t*)p_wlo, nW4);
    gemm_mma_kernel<<<gg, 256, GEMM_SMEM>>>(ahi, alo, whi, wlo, bo,
        out, nullptr, nullptr, 1.0f);
}

// round 6
// speedup vs baseline: 1.0892x; 1.0892x over previous
#include <cuda_runtime.h>
#include <cuda_bf16.h>
#include <cstdint>
#include <math.h>

#define BATCH 2
#define SEQ   2048
#define DMODEL 1024
#define NHEADS 16
#define HDIM  64
#define MTOT  (BATCH*SEQ)   // 4096

// ---------------- scratch (allocation-free rule: device globals) -----------
__device__ __nv_bfloat16 g_ahi[MTOT*DMODEL];
__device__ __nv_bfloat16 g_alo[MTOT*DMODEL];
__device__ __nv_bfloat16 g_whi[DMODEL*DMODEL];
__device__ __nv_bfloat16 g_wlo[DMODEL*DMODEL];
__device__ __nv_bfloat16 g_qhi[MTOT*DMODEL];
__device__ __nv_bfloat16 g_qlo[MTOT*DMODEL];
__device__ __nv_bfloat16 g_khi[MTOT*DMODEL];
__device__ __nv_bfloat16 g_klo[MTOT*DMODEL];
__device__ __nv_bfloat16 g_vhi[MTOT*DMODEL];
__device__ __nv_bfloat16 g_vlo[MTOT*DMODEL];

// ---------------- helpers ---------------------------------------------------
__device__ __forceinline__ uint32_t smem_u32(const void* p) {
    uint32_t a;
    asm("{ .reg .u64 t; cvta.to.shared.u64 t, %1; cvt.u32.u64 %0, t; }"
        : "=r"(a) : "l"(p));
    return a;
}
__device__ __forceinline__ void cp16(uint32_t s, const void* g) {
    asm volatile("cp.async.cg.shared.global [%0], [%1], 16;" :: "r"(s), "l"(g));
}
#define CP_COMMIT()  asm volatile("cp.async.commit_group;" ::: "memory")
#define CP_WAIT(n)   asm volatile("cp.async.wait_group %0;" :: "n"(n) : "memory")

__device__ __forceinline__ void ldsm_x4(uint32_t* r, uint32_t addr) {
    asm volatile("ldmatrix.sync.aligned.m8n8.x4.shared.b16 {%0,%1,%2,%3}, [%4];"
                 : "=r"(r[0]), "=r"(r[1]), "=r"(r[2]), "=r"(r[3]) : "r"(addr));
}
__device__ __forceinline__ void ldsm_x4_t(uint32_t* r, uint32_t addr) {
    asm volatile("ldmatrix.sync.aligned.m8n8.x4.trans.shared.b16 {%0,%1,%2,%3}, [%4];"
                 : "=r"(r[0]), "=r"(r[1]), "=r"(r[2]), "=r"(r[3]) : "r"(addr));
}
__device__ __forceinline__ void mma16816(float* d, const uint32_t* a,
                                         const uint32_t* b) {
    asm volatile(
        "mma.sync.aligned.m16n8k16.row.col.f32.bf16.bf16.f32 "
        "{%0,%1,%2,%3}, {%4,%5,%6,%7}, {%8,%9}, {%0,%1,%2,%3};"
        : "+f"(d[0]), "+f"(d[1]), "+f"(d[2]), "+f"(d[3])
        : "r"(a[0]), "r"(a[1]), "r"(a[2]), "r"(a[3]), "r"(b[0]), "r"(b[1]));
}
// pack (x,y) to bf16x2 hi plus residual lo
__device__ __forceinline__ void pack_split(float x, float y,
                                           uint32_t& hi, uint32_t& lo) {
    uint32_t h;
    asm("cvt.rn.bf16x2.f32 %0, %1, %2;" : "=r"(h) : "f"(y), "f"(x));
    float hx = __uint_as_float(h << 16);
    float hy = __uint_as_float(h & 0xffff0000u);
    float lx = x - hx, ly = y - hy;
    uint32_t l;
    asm("cvt.rn.bf16x2.f32 %0, %1, %2;" : "=r"(l) : "f"(ly), "f"(lx));
    hi = h; lo = l;
}

// ---------------------------------------------------------------------------
// split fp32 -> (bf16 hi, bf16 lo)   (raw inputs + weights)
// ---------------------------------------------------------------------------
__global__ __launch_bounds__(256)
void split_kernel(const float4* __restrict__ x, uint32_t* __restrict__ hi,
                  uint32_t* __restrict__ lo, int n4)
{
    int i = blockIdx.x * 256 + threadIdx.x;
    if (i >= n4) return;
    float4 v = x[i];
    uint32_t h0, l0, h1, l1;
    pack_split(v.x, v.y, h0, l0);
    pack_split(v.z, v.w, h1, l1);
    hi[2*i] = h0; hi[2*i+1] = h1;
    lo[2*i] = l0; lo[2*i+1] = l1;
}

// ---------------------------------------------------------------------------
// mma.sync bf16 GEMM: out = A*W^T + bias, split-bf16 3-MMA, 2-stage cp.async.
// CTA tile 128 x 256 -> grid 4x32 = 128 CTAs = 1 wave on 148 SMs.
// 8 warps as 4(m) x 2(n); warp tile 32 x 128.
// ---------------------------------------------------------------------------
#define BM 128
#define BN 256
#define BK 32
#define NCHUNK (DMODEL / BK)        // 32
#define ROWB 80
#define A_MAT_B (128 * ROWB)        // 10240
#define B_MAT_B (256 * ROWB)        // 20480
#define OFF_AH 0
#define OFF_AL A_MAT_B
#define OFF_BH (2 * A_MAT_B)
#define OFF_BL (2 * A_MAT_B + B_MAT_B)
#define STAGE_B (2 * A_MAT_B + 2 * B_MAT_B)   // 61440
#define GEMM_SMEM (2 * STAGE_B)               // 122880

__global__ __launch_bounds__(256)
void gemm_mma_kernel(const __nv_bfloat16* __restrict__ Ahi,
                     const __nv_bfloat16* __restrict__ Alo,
                     const __nv_bfloat16* __restrict__ Bhi,
                     const __nv_bfloat16* __restrict__ Blo,
                     const float* __restrict__ bias,
                     float* __restrict__ outf,
                     uint32_t* __restrict__ outhi,
                     uint32_t* __restrict__ outlo,
                     float scale)
{
    extern __shared__ char smraw[];
    const uint32_t sbase = smem_u32(smraw);
    const int tid  = threadIdx.x;
    const int lane = tid & 31;
    const int wid  = tid >> 5;
    const int wm   = (wid & 3) * 32;     // 4 m-warps
    const int wn   = (wid >> 2) * 128;   // 2 n-warps
    const int n0   = blockIdx.x * BN;
    const int m0   = blockIdx.y * BM;

    float c[2][16][4];
    #pragma unroll
    for (int mt = 0; mt < 2; mt++)
        #pragma unroll
        for (int nt = 0; nt < 16; nt++)
            #pragma unroll
            for (int j = 0; j < 4; j++) c[mt][nt][j] = 0.0f;

    auto load_chunk = [&](int ck, int s) {
        uint32_t st = sbase + s * STAGE_B;
        int k0 = ck * BK;
        #pragma unroll
        for (int u = tid; u < 512; u += 256) {       // A: 128 x 32
            int r = u >> 2, c16 = u & 3;
            uint32_t d = st + r * ROWB + c16 * 16;
            size_t g = (size_t)(m0 + r) * DMODEL + k0 + c16 * 8;
            cp16(d + OFF_AH, Ahi + g);
            cp16(d + OFF_AL, Alo + g);
        }
        #pragma unroll
        for (int u = tid; u < 1024; u += 256) {      // B: 256 x 32
            int r = u >> 2, c16 = u & 3;
            uint32_t d = st + r * ROWB + c16 * 16;
            size_t g = (size_t)(n0 + r) * DMODEL + k0 + c16 * 8;
            cp16(d + OFF_BH, Bhi + g);
            cp16(d + OFF_BL, Blo + g);
        }
    };

    load_chunk(0, 0); CP_COMMIT();

    const int a_row  = lane & 15;
    const int a_kb   = ((lane >> 4) & 1) * 16;
    const int b_row  = (lane & 7) + ((lane >> 4) & 1) * 8;
    const int b_kb   = ((lane >> 3) & 1) * 16;

    for (int ck = 0; ck < NCHUNK; ck++) {
        int s = ck & 1;
        if (ck + 1 < NCHUNK) {
            load_chunk(ck + 1, s ^ 1); CP_COMMIT();
            CP_WAIT(1);
        } else {
            CP_WAIT(0);
        }
        __syncthreads();

        uint32_t st = sbase + s * STAGE_B;
        #pragma unroll
        for (int ks = 0; ks < 2; ks++) {
            int kb = ks * 32;
            uint32_t ah[2][4], al[2][4];
            #pragma unroll
            for (int mt = 0; mt < 2; mt++) {
                uint32_t addr = st + (wm + mt * 16 + a_row) * ROWB + kb + a_kb;
                ldsm_x4(ah[mt], addr + OFF_AH);
                ldsm_x4(al[mt], addr + OFF_AL);
            }
            #pragma unroll
            for (int np = 0; np < 8; np++) {
                uint32_t bh4[4], bl4[4];
                uint32_t addr = st + (wn + np * 16 + b_row) * ROWB + kb + b_kb;
                ldsm_x4(bh4, addr + OFF_BH);
                ldsm_x4(bl4, addr + OFF_BL);
                #pragma unroll
                for (int mt = 0; mt < 2; mt++) {
                    mma16816(c[mt][np*2],   ah[mt], bh4);
                    mma16816(c[mt][np*2],   ah[mt], bl4);
                    mma16816(c[mt][np*2],   al[mt], bh4);
                    mma16816(c[mt][np*2+1], ah[mt], bh4 + 2);
                    mma16816(c[mt][np*2+1], ah[mt], bl4 + 2);
                    mma16816(c[mt][np*2+1], al[mt], bh4 + 2);
                }
            }
        }
        __syncthreads();
    }

    const int g  = lane >> 2;
    const int cq = (lane & 3) * 2;
    #pragma unroll
    for (int mt = 0; mt < 2; mt++) {
        #pragma unroll
        for (int nt = 0; nt < 16; nt++) {
            int col = n0 + wn + nt * 8 + cq;
            float2 bv = *(const float2*)(bias + col);
            int r0 = m0 + wm + mt * 16 + g;
            float x0 = c[mt][nt][0] + bv.x, y0 = c[mt][nt][1] + bv.y;
            float x1 = c[mt][nt][2] + bv.x, y1 = c[mt][nt][3] + bv.y;
            if (outf) {
                *(float2*)(outf + (size_t)r0 * DMODEL + col) = make_float2(x0, y0);
                *(float2*)(outf + (size_t)(r0 + 8) * DMODEL + col) = make_float2(x1, y1);
            } else {
                uint32_t h, l;
                pack_split(x0 * scale, y0 * scale, h, l);
                size_t idx0 = ((size_t)r0 * DMODEL + col) >> 1;
                outhi[idx0] = h; outlo[idx0] = l;
                pack_split(x1 * scale, y1 * scale, h, l);
                size_t idx1 = ((size_t)(r0 + 8) * DMODEL + col) >> 1;
                outhi[idx1] = h; outlo[idx1] = l;
            }
        }
    }
}

// ---------------------------------------------------------------------------
// FA2-style mma.sync attention, split-bf16, 2-stage KV pipeline (R4 layout),
// bf16 hi/lo epilogue.
// ---------------------------------------------------------------------------
#define AROWB 144
#define AQ_B   (128 * AROWB)
#define AKV_B  (64 * AROWB)
#define A_OFF_QH 0
#define A_OFF_QL AQ_B
#define A_STAGE0 (2 * AQ_B)
#define A_STAGE_B (4 * AKV_B)
#define A_OFF_KH 0
#define A_OFF_KL AKV_B
#define A_OFF_VH (2 * AKV_B)
#define A_OFF_VL (3 * AKV_B)
#define ATTN_SMEM (A_STAGE0 + 2 * A_STAGE_B)   // 110592
#define NKT (SEQ / 64)

__global__ __launch_bounds__(256, 1)
void attn_mma_kernel(const __nv_bfloat16* __restrict__ qhi,
                     const __nv_bfloat16* __restrict__ qlo,
                     const __nv_bfloat16* __restrict__ khi,
                     const __nv_bfloat16* __restrict__ klo,
                     const __nv_bfloat16* __restrict__ vhi,
                     const __nv_bfloat16* __restrict__ vlo,
                     const int* __restrict__ mask,
                     uint32_t* __restrict__ jhi,
                     uint32_t* __restrict__ jlo)
{
    extern __shared__ char smraw[];
    const uint32_t sbase = smem_u32(smraw);
    const int tid  = threadIdx.x;
    const int lane = tid & 31;
    const int wid  = tid >> 5;
    const int wm   = wid * 16;
    const int b    = blockIdx.z;
    const int h    = blockIdx.y;
    const int q0   = blockIdx.x * 128;

    // ---- load Q tile (hi/lo) ----
    #pragma unroll
    for (int u = tid; u < 1024; u += 256) {
        int r = u >> 3, c16 = u & 7;
        uint32_t d = sbase + r * AROWB + c16 * 16;
        size_t g = ((size_t)(b * SEQ + q0 + r)) * DMODEL + h * HDIM + c16 * 8;
        cp16(d + A_OFF_QH, qhi + g);
        cp16(d + A_OFF_QL, qlo + g);
    }
    CP_COMMIT(); CP_WAIT(0);
    __syncthreads();

    // ---- preload Q fragments ----
    uint32_t aqh[4][4], aql[4][4];
    {
        const int a_row = lane & 15;
        const int a_kb  = ((lane >> 4) & 1) * 16;
        #pragma unroll
        for (int kc = 0; kc < 4; kc++) {
            uint32_t addr = sbase + (wm + a_row) * AROWB + kc * 32 + a_kb;
            ldsm_x4(aqh[kc], addr + A_OFF_QH);
            ldsm_x4(aql[kc], addr + A_OFF_QL);
        }
    }

    const int g_   = lane >> 2;
    const int cq   = (lane & 3) * 2;
    const int b_row = (lane & 7) + ((lane >> 4) & 1) * 8;
    const int b_kb  = ((lane >> 3) & 1) * 16;
    const int v_row = lane & 15;
    const int v_col = (lane >> 4) * 8;

    const size_t mrow0 = ((size_t)b * SEQ + q0 + wm + g_) * SEQ;
    const size_t mrow1 = mrow0 + (size_t)8 * SEQ;

    float o[8][4];
    #pragma unroll
    for (int i = 0; i < 8; i++)
        #pragma unroll
        for (int j = 0; j < 4; j++) o[i][j] = 0.0f;
    float m0r = -INFINITY, m1r = -INFINITY, l0r = 0.0f, l1r = 0.0f;

    auto load_kv = [&](int kt, int s) {
        uint32_t st = sbase + A_STAGE0 + s * A_STAGE_B;
        int k0 = kt * 64;
        #pragma unroll
        for (int u = tid; u < 512; u += 256) {
            int r = u >> 3, c16 = u & 7;
            uint32_t d = st + r * AROWB + c16 * 16;
            size_t g = ((size_t)(b * SEQ + k0 + r)) * DMODEL + h * HDIM + c16 * 8;
            cp16(d + A_OFF_KH, khi + g);
            cp16(d + A_OFF_KL, klo + g);
            cp16(d + A_OFF_VH, vhi + g);
            cp16(d + A_OFF_VL, vlo + g);
        }
    };

    load_kv(0, 0); CP_COMMIT();

    for (int kt = 0; kt < NKT; kt++) {
        int s = kt & 1;
        __syncthreads();
        if (kt + 1 < NKT) {
            load_kv(kt + 1, s ^ 1); CP_COMMIT();
            CP_WAIT(1);
        } else {
            CP_WAIT(0);
        }
        __syncthreads();

        uint32_t st = sbase + A_STAGE0 + s * A_STAGE_B;
        int k0 = kt * 64;

        // ---- S = Q K^T ----
        float sc[8][4];
        #pragma unroll
        for (int i = 0; i < 8; i++)
            #pragma unroll
            for (int j = 0; j < 4; j++) sc[i][j] = 0.0f;

        #pragma unroll
        for (int kc = 0; kc < 4; kc++) {
            #pragma unroll
            for (int np = 0; np < 4; np++) {
                uint32_t bh4[4], bl4[4];
                uint32_t addr = st + (np * 16 + b_row) * AROWB + kc * 32 + b_kb;
                ldsm_x4(bh4, addr + A_OFF_KH);
                ldsm_x4(bl4, addr + A_OFF_KL);
                mma16816(sc[np*2],   aqh[kc], bh4);
                mma16816(sc[np*2],   aqh[kc], bl4);
                mma16816(sc[np*2],   aql[kc], bh4);
                mma16816(sc[np*2+1], aqh[kc], bh4 + 2);
                mma16816(sc[np*2+1], aqh[kc], bl4 + 2);
                mma16816(sc[np*2+1], aql[kc], bh4 + 2);
            }
        }

        // ---- mask ----
        #pragma unroll
        for (int nt = 0; nt < 8; nt++) {
            int2 mm0 = *(const int2*)(mask + mrow0 + k0 + nt * 8 + cq);
            int2 mm1 = *(const int2*)(mask + mrow1 + k0 + nt * 8 + cq);
            if (mm0.x == 0) sc[nt][0] = -1000000000.0f;
            if (mm0.y == 0) sc[nt][1] = -1000000000.0f;
            if (mm1.x == 0) sc[nt][2] = -1000000000.0f;
            if (mm1.y == 0) sc[nt][3] = -1000000000.0f;
        }

        // ---- online softmax ----
        float mx0 = sc[0][0], mx1 = sc[0][2];
        #pragma unroll
        for (int nt = 0; nt < 8; nt++) {
            mx0 = fmaxf(mx0, fmaxf(sc[nt][0], sc[nt][1]));
            mx1 = fmaxf(mx1, fmaxf(sc[nt][2], sc[nt][3]));
        }
        mx0 = fmaxf(mx0, __shfl_xor_sync(0xffffffff, mx0, 1));
        mx0 = fmaxf(mx0, __shfl_xor_sync(0xffffffff, mx0, 2));
        mx1 = fmaxf(mx1, __shfl_xor_sync(0xffffffff, mx1, 1));
        mx1 = fmaxf(mx1, __shfl_xor_sync(0xffffffff, mx1, 2));

        float mn0 = fmaxf(m0r, mx0), mn1 = fmaxf(m1r, mx1);
        float al0 = __expf(m0r - mn0), al1 = __expf(m1r - mn1);
        m0r = mn0; m1r = mn1;

        float rs0 = 0.0f, rs1 = 0.0f;
        #pragma unroll
        for (int nt = 0; nt < 8; nt++) {
            sc[nt][0] = __expf(sc[nt][0] - mn0); rs0 += sc[nt][0];
            sc[nt][1] = __expf(sc[nt][1] - mn0); rs0 += sc[nt][1];
            sc[nt][2] = __expf(sc[nt][2] - mn1); rs1 += sc[nt][2];
            sc[nt][3] = __expf(sc[nt][3] - mn1); rs1 += sc[nt][3];
        }
        rs0 += __shfl_xor_sync(0xffffffff, rs0, 1);
        rs0 += __shfl_xor_sync(0xffffffff, rs0, 2);
        rs1 += __shfl_xor_sync(0xffffffff, rs1, 1);
        rs1 += __shfl_xor_sync(0xffffffff, rs1, 2);
        l0r = l0r * al0 + rs0;
        l1r = l1r * al1 + rs1;

        #pragma unroll
        for (int nt = 0; nt < 8; nt++) {
            o[nt][0] *= al0; o[nt][1] *= al0;
            o[nt][2] *= al1; o[nt][3] *= al1;
        }

        // ---- pack P into A-fragments ----
        uint32_t ph[4][4], pl[4][4];
        #pragma unroll
        for (int tp = 0; tp < 4; tp++) {
            pack_split(sc[2*tp][0],   sc[2*tp][1],   ph[tp][0], pl[tp][0]);
            pack_split(sc[2*tp][2],   sc[2*tp][3],   ph[tp][1], pl[tp][1]);
            pack_split(sc[2*tp+1][0], sc[2*tp+1][1], ph[tp][2], pl[tp][2]);
            pack_split(sc[2*tp+1][2], sc[2*tp+1][3], ph[tp][3], pl[tp][3]);
        }

        // ---- O += P V ----
        #pragma unroll
        for (int nt2 = 0; nt2 < 4; nt2++) {
            #pragma unroll
            for (int tp = 0; tp < 4; tp++) {
                uint32_t vh4[4], vl4[4];
                uint32_t addr = st + A_OFF_VH + (tp * 16 + v_row) * AROWB
                              + (nt2 * 16 + v_col) * 2;
                ldsm_x4_t(vh4, addr);
                ldsm_x4_t(vl4, addr + (A_OFF_VL - A_OFF_VH));
                mma16816(o[nt2*2],   ph[tp], vh4);
                mma16816(o[nt2*2],   ph[tp], vl4);
                mma16816(o[nt2*2],   pl[tp], vh4);
                mma16816(o[nt2*2+1], ph[tp], vh4 + 2);
                mma16816(o[nt2*2+1], ph[tp], vl4 + 2);
                mma16816(o[nt2*2+1], pl[tp], vh4 + 2);
            }
        }
    }

    // ---- epilogue: joint as bf16 hi/lo ----
    float inv0 = 1.0f / l0r, inv1 = 1.0f / l1r;
    size_t row0 = ((size_t)(b * SEQ + q0 + wm + g_)) * DMODEL + h * HDIM;
    #pragma unroll
    for (int nt = 0; nt < 8; nt++) {
        int col = nt * 8 + cq;
        uint32_t hh, ll;
        pack_split(o[nt][0] * inv0, o[nt][1] * inv0, hh, ll);
        size_t i0 = (row0 + col) >> 1;
        jhi[i0] = hh; jlo[i0] = ll;
        pack_split(o[nt][2] * inv1, o[nt][3] * inv1, hh, ll);
        size_t i1 = (row0 + (size_t)8 * DMODEL + col) >> 1;
        jhi[i1] = hh; jlo[i1] = ll;
    }
}

// ---------------------------------------------------------------------------
extern "C" void kernel_launch(void* const* d_in, const int* in_sizes, int n_in,
                              void* d_out, int out_size)
{
    const float* q    = (const float*)d_in[0];
    const float* k    = (const float*)d_in[1];
    const float* v    = (const float*)d_in[2];
    const int*   mask = (const int*)  d_in[3];
    const float* Wq   = (const float*)d_in[4];
    const float* bq   = (const float*)d_in[5];
    const float* Wk   = (const float*)d_in[6];
    const float* bk   = (const float*)d_in[7];
    const float* Wv   = (const float*)d_in[8];
    const float* bv   = (const float*)d_in[9];
    const float* Wo   = (const float*)d_in[10];
    const float* bo   = (const float*)d_in[11];
    float* out = (float*)d_out;

    void *p_ahi, *p_alo, *p_whi, *p_wlo;
    void *p_qhi, *p_qlo, *p_khi, *p_klo, *p_vhi, *p_vlo;
    cudaGetSymbolAddress(&p_ahi, g_ahi);
    cudaGetSymbolAddress(&p_alo, g_alo);
    cudaGetSymbolAddress(&p_whi, g_whi);
    cudaGetSymbolAddress(&p_wlo, g_wlo);
    cudaGetSymbolAddress(&p_qhi, g_qhi);
    cudaGetSymbolAddress(&p_qlo, g_qlo);
    cudaGetSymbolAddress(&p_khi, g_khi);
    cudaGetSymbolAddress(&p_klo, g_klo);
    cudaGetSymbolAddress(&p_vhi, g_vhi);
    cudaGetSymbolAddress(&p_vlo, g_vlo);

    __nv_bfloat16* ahi = (__nv_bfloat16*)p_ahi;
    __nv_bfloat16* alo = (__nv_bfloat16*)p_alo;
    __nv_bfloat16* whi = (__nv_bfloat16*)p_whi;
    __nv_bfloat16* wlo = (__nv_bfloat16*)p_wlo;

    const int nX4 = MTOT * DMODEL / 4;
    const int nW4 = DMODEL * DMODEL / 4;

    cudaFuncSetAttribute(gemm_mma_kernel,
                         cudaFuncAttributeMaxDynamicSharedMemorySize, GEMM_SMEM);
    cudaFuncSetAttribute(attn_mma_kernel,
                         cudaFuncAttributeMaxDynamicSharedMemorySize, ATTN_SMEM);

    dim3 gg(DMODEL / BN, MTOT / BM);     // 4 x 32 = 128 CTAs

    // Q projection -> bf16 hi/lo with 1/8 scale fused
    split_kernel<<<nX4 / 256, 256>>>((const float4*)q, (uint32_t*)p_ahi, (uint32_t*)p_alo, nX4);
    split_kernel<<<nW4 / 256, 256>>>((const float4*)Wq, (uint32_t*)p_whi, (uint32_t*)p_wlo, nW4);
    gemm_mma_kernel<<<gg, 256, GEMM_SMEM>>>(ahi, alo, whi, wlo, bq,
        nullptr, (uint32_t*)p_qhi, (uint32_t*)p_qlo, 0.125f);

    // K projection -> bf16 hi/lo
    split_kernel<<<nX4 / 256, 256>>>((const float4*)k, (uint32_t*)p_ahi, (uint32_t*)p_alo, nX4);
    split_kernel<<<nW4 / 256, 256>>>((const float4*)Wk, (uint32_t*)p_whi, (uint32_t*)p_wlo, nW4);
    gemm_mma_kernel<<<gg, 256, GEMM_SMEM>>>(ahi, alo, whi, wlo, bk,
        nullptr, (uint32_t*)p_khi, (uint32_t*)p_klo, 1.0f);

    // V projection -> bf16 hi/lo
    split_kernel<<<nX4 / 256, 256>>>((const float4*)v, (uint32_t*)p_ahi, (uint32_t*)p_alo, nX4);
    split_kernel<<<nW4 / 256, 256>>>((const float4*)Wv, (uint32_t*)p_whi, (uint32_t*)p_wlo, nW4);
    gemm_mma_kernel<<<gg, 256, GEMM_SMEM>>>(ahi, alo, whi, wlo, bv,
        nullptr, (uint32_t*)p_vhi, (uint32_t*)p_vlo, 1.0f);

    // attention -> joint bf16 hi/lo (into ahi/alo, consumed by output proj)
    dim3 ag(SEQ / 128, NHEADS, BATCH);
    attn_mma_kernel<<<ag, 256, ATTN_SMEM>>>(
        (const __nv_bfloat16*)p_qhi, (const __nv_bfloat16*)p_qlo,
        (const __nv_bfloat16*)p_khi, (const __nv_bfloat16*)p_klo,
        (const __nv_bfloat16*)p_vhi, (const __nv_bfloat16*)p_vlo,
        mask, (uint32_t*)p_ahi, (uint32_t*)p_alo);

    // output projection (fp32 out)
    split_kernel<<<nW4 / 256, 256>>>((const float4*)Wo, (uint32_t*)p_whi, (uint32_t*)p_wlo, nW4);
    gemm_mma_kernel<<<gg, 256, GEMM_SMEM>>>(ahi, alo, whi, wlo, bo,
        out, nullptr, nullptr, 1.0f);
}

// round 7
// speedup vs baseline: 1.1363x; 1.0432x over previous
#include <cuda_runtime.h>
#include <cuda_bf16.h>
#include <cstdint>
#include <math.h>

#define BATCH 2
#define SEQ   2048
#define DMODEL 1024
#define NHEADS 16
#define HDIM  64
#define MTOT  (BATCH*SEQ)   // 4096
#define LOG2E 1.44269504088896f

// ---------------- scratch (allocation-free rule: device globals) -----------
__device__ __nv_bfloat16 g_xhi[3*MTOT*DMODEL];     // split q,k,v inputs
__device__ __nv_bfloat16 g_xlo[3*MTOT*DMODEL];
__device__ __nv_bfloat16 g_whi4[4*DMODEL*DMODEL];  // split Wq,Wk,Wv,Wo
__device__ __nv_bfloat16 g_wlo4[4*DMODEL*DMODEL];
__device__ __nv_bfloat16 g_qhi[MTOT*DMODEL];
__device__ __nv_bfloat16 g_qlo[MTOT*DMODEL];
__device__ __nv_bfloat16 g_khi[MTOT*DMODEL];
__device__ __nv_bfloat16 g_klo[MTOT*DMODEL];
__device__ __nv_bfloat16 g_vhi[MTOT*DMODEL];
__device__ __nv_bfloat16 g_vlo[MTOT*DMODEL];
__device__ __nv_bfloat16 g_jhi[MTOT*DMODEL];
__device__ __nv_bfloat16 g_jlo[MTOT*DMODEL];
__device__ unsigned long long g_maskbits[(size_t)BATCH*SEQ*SEQ/64];

// ---------------- helpers ---------------------------------------------------
__device__ __forceinline__ uint32_t smem_u32(const void* p) {
    uint32_t a;
    asm("{ .reg .u64 t; cvta.to.shared.u64 t, %1; cvt.u32.u64 %0, t; }"
        : "=r"(a) : "l"(p));
    return a;
}
__device__ __forceinline__ void cp16(uint32_t s, const void* g) {
    asm volatile("cp.async.cg.shared.global [%0], [%1], 16;" :: "r"(s), "l"(g));
}
#define CP_COMMIT()  asm volatile("cp.async.commit_group;" ::: "memory")
#define CP_WAIT(n)   asm volatile("cp.async.wait_group %0;" :: "n"(n) : "memory")

__device__ __forceinline__ void ldsm_x4(uint32_t* r, uint32_t addr) {
    asm volatile("ldmatrix.sync.aligned.m8n8.x4.shared.b16 {%0,%1,%2,%3}, [%4];"
                 : "=r"(r[0]), "=r"(r[1]), "=r"(r[2]), "=r"(r[3]) : "r"(addr));
}
__device__ __forceinline__ void ldsm_x4_t(uint32_t* r, uint32_t addr) {
    asm volatile("ldmatrix.sync.aligned.m8n8.x4.trans.shared.b16 {%0,%1,%2,%3}, [%4];"
                 : "=r"(r[0]), "=r"(r[1]), "=r"(r[2]), "=r"(r[3]) : "r"(addr));
}
__device__ __forceinline__ void mma16816(float* d, const uint32_t* a,
                                         const uint32_t* b) {
    asm volatile(
        "mma.sync.aligned.m16n8k16.row.col.f32.bf16.bf16.f32 "
        "{%0,%1,%2,%3}, {%4,%5,%6,%7}, {%8,%9}, {%0,%1,%2,%3};"
        : "+f"(d[0]), "+f"(d[1]), "+f"(d[2]), "+f"(d[3])
        : "r"(a[0]), "r"(a[1]), "r"(a[2]), "r"(a[3]), "r"(b[0]), "r"(b[1]));
}
__device__ __forceinline__ void pack_split(float x, float y,
                                           uint32_t& hi, uint32_t& lo) {
    uint32_t h;
    asm("cvt.rn.bf16x2.f32 %0, %1, %2;" : "=r"(h) : "f"(y), "f"(x));
    float hx = __uint_as_float(h << 16);
    float hy = __uint_as_float(h & 0xffff0000u);
    float lx = x - hx, ly = y - hy;
    uint32_t l;
    asm("cvt.rn.bf16x2.f32 %0, %1, %2;" : "=r"(l) : "f"(ly), "f"(lx));
    hi = h; lo = l;
}

// ---------------------------------------------------------------------------
// split_all: one launch splits q,k,v (4096 blocks each) + 4 weights (1024 each)
// ---------------------------------------------------------------------------
struct SplitAll {
    const float4* src[7];
    uint32_t* hi[7];
    uint32_t* lo[7];
};
#define NX_BLK 4096
#define NW_BLK 1024
#define SPLIT_BLOCKS (3*NX_BLK + 4*NW_BLK)   // 16384

__global__ __launch_bounds__(256)
void split_all_kernel(SplitAll a)
{
    int bid = blockIdx.x;
    int seg, idx;
    if (bid < 3 * NX_BLK) { seg = bid / NX_BLK; idx = (bid % NX_BLK) * 256 + threadIdx.x; }
    else { int r = bid - 3 * NX_BLK; seg = 3 + r / NW_BLK; idx = (r % NW_BLK) * 256 + threadIdx.x; }
    float4 v = a.src[seg][idx];
    uint32_t h0, l0, h1, l1;
    pack_split(v.x, v.y, h0, l0);
    pack_split(v.z, v.w, h1, l1);
    uint32_t* hi = a.hi[seg];
    uint32_t* lo = a.lo[seg];
    hi[2*idx] = h0; hi[2*idx+1] = h1;
    lo[2*idx] = l0; lo[2*idx+1] = l1;
}

// ---------------------------------------------------------------------------
// mask pack: 64 int -> 1 uint64 (bit=1 means keep)
// ---------------------------------------------------------------------------
__global__ __launch_bounds__(256)
void mask_pack_kernel(const int4* __restrict__ mask, unsigned long long* __restrict__ bm)
{
    int i = blockIdx.x * 256 + threadIdx.x;   // word index
    const int4* p = mask + (size_t)i * 16;
    unsigned long long w = 0;
    #pragma unroll
    for (int j = 0; j < 16; j++) {
        int4 v = p[j];
        w |= ((unsigned long long)(v.x != 0)) << (j*4);
        w |= ((unsigned long long)(v.y != 0)) << (j*4+1);
        w |= ((unsigned long long)(v.z != 0)) << (j*4+2);
        w |= ((unsigned long long)(v.w != 0)) << (j*4+3);
    }
    bm[i] = w;
}

// ---------------------------------------------------------------------------
// shared GEMM body: out = A*W^T + bias (split-bf16 3-MMA, 2-stage cp.async)
// CTA tile 128 x 256; 8 warps as 4(m) x 2(n).
// ---------------------------------------------------------------------------
#define BM 128
#define BN 256
#define BK 32
#define NCHUNK (DMODEL / BK)
#define ROWB 80
#define A_MAT_B (128 * ROWB)
#define B_MAT_B (256 * ROWB)
#define OFF_AH 0
#define OFF_AL A_MAT_B
#define OFF_BH (2 * A_MAT_B)
#define OFF_BL (2 * A_MAT_B + B_MAT_B)
#define STAGE_B (2 * A_MAT_B + 2 * B_MAT_B)   // 61440
#define GEMM_SMEM (2 * STAGE_B)               // 122880

__device__ __forceinline__ void gemm_body(
    const __nv_bfloat16* __restrict__ Ahi, const __nv_bfloat16* __restrict__ Alo,
    const __nv_bfloat16* __restrict__ Bhi, const __nv_bfloat16* __restrict__ Blo,
    const float* __restrict__ bias,
    float* __restrict__ outf, uint32_t* __restrict__ outhi,
    uint32_t* __restrict__ outlo, float scale, uint32_t sbase)
{
    const int tid  = threadIdx.x;
    const int lane = tid & 31;
    const int wid  = tid >> 5;
    const int wm   = (wid & 3) * 32;
    const int wn   = (wid >> 2) * 128;
    const int n0   = blockIdx.x * BN;
    const int m0   = blockIdx.y * BM;

    float c[2][16][4];
    #pragma unroll
    for (int mt = 0; mt < 2; mt++)
        #pragma unroll
        for (int nt = 0; nt < 16; nt++)
            #pragma unroll
            for (int j = 0; j < 4; j++) c[mt][nt][j] = 0.0f;

    auto load_chunk = [&](int ck, int s) {
        uint32_t st = sbase + s * STAGE_B;
        int k0 = ck * BK;
        #pragma unroll
        for (int u = tid; u < 512; u += 256) {
            int r = u >> 2, c16 = u & 3;
            uint32_t d = st + r * ROWB + c16 * 16;
            size_t g = (size_t)(m0 + r) * DMODEL + k0 + c16 * 8;
            cp16(d + OFF_AH, Ahi + g);
            cp16(d + OFF_AL, Alo + g);
        }
        #pragma unroll
        for (int u = tid; u < 1024; u += 256) {
            int r = u >> 2, c16 = u & 3;
            uint32_t d = st + r * ROWB + c16 * 16;
            size_t g = (size_t)(n0 + r) * DMODEL + k0 + c16 * 8;
            cp16(d + OFF_BH, Bhi + g);
            cp16(d + OFF_BL, Blo + g);
        }
    };

    load_chunk(0, 0); CP_COMMIT();

    const int a_row  = lane & 15;
    const int a_kb   = ((lane >> 4) & 1) * 16;
    const int b_row  = (lane & 7) + ((lane >> 4) & 1) * 8;
    const int b_kb   = ((lane >> 3) & 1) * 16;

    for (int ck = 0; ck < NCHUNK; ck++) {
        int s = ck & 1;
        if (ck + 1 < NCHUNK) {
            load_chunk(ck + 1, s ^ 1); CP_COMMIT();
            CP_WAIT(1);
        } else {
            CP_WAIT(0);
        }
        __syncthreads();

        uint32_t st = sbase + s * STAGE_B;
        #pragma unroll
        for (int ks = 0; ks < 2; ks++) {
            int kb = ks * 32;
            uint32_t ah[2][4], al[2][4];
            #pragma unroll
            for (int mt = 0; mt < 2; mt++) {
                uint32_t addr = st + (wm + mt * 16 + a_row) * ROWB + kb + a_kb;
                ldsm_x4(ah[mt], addr + OFF_AH);
                ldsm_x4(al[mt], addr + OFF_AL);
            }
            #pragma unroll
            for (int np = 0; np < 8; np++) {
                uint32_t bh4[4], bl4[4];
                uint32_t addr = st + (wn + np * 16 + b_row) * ROWB + kb + b_kb;
                ldsm_x4(bh4, addr + OFF_BH);
                ldsm_x4(bl4, addr + OFF_BL);
                #pragma unroll
                for (int mt = 0; mt < 2; mt++) {
                    mma16816(c[mt][np*2],   ah[mt], bh4);
                    mma16816(c[mt][np*2],   ah[mt], bl4);
                    mma16816(c[mt][np*2],   al[mt], bh4);
                    mma16816(c[mt][np*2+1], ah[mt], bh4 + 2);
                    mma16816(c[mt][np*2+1], ah[mt], bl4 + 2);
                    mma16816(c[mt][np*2+1], al[mt], bh4 + 2);
                }
            }
        }
        __syncthreads();
    }

    const int g  = lane >> 2;
    const int cq = (lane & 3) * 2;
    #pragma unroll
    for (int mt = 0; mt < 2; mt++) {
        #pragma unroll
        for (int nt = 0; nt < 16; nt++) {
            int col = n0 + wn + nt * 8 + cq;
            float2 bv = *(const float2*)(bias + col);
            int r0 = m0 + wm + mt * 16 + g;
            float x0 = c[mt][nt][0] + bv.x, y0 = c[mt][nt][1] + bv.y;
            float x1 = c[mt][nt][2] + bv.x, y1 = c[mt][nt][3] + bv.y;
            if (outf) {
                *(float2*)(outf + (size_t)r0 * DMODEL + col) = make_float2(x0, y0);
                *(float2*)(outf + (size_t)(r0 + 8) * DMODEL + col) = make_float2(x1, y1);
            } else {
                uint32_t h, l;
                pack_split(x0 * scale, y0 * scale, h, l);
                size_t idx0 = ((size_t)r0 * DMODEL + col) >> 1;
                outhi[idx0] = h; outlo[idx0] = l;
                pack_split(x1 * scale, y1 * scale, h, l);
                size_t idx1 = ((size_t)(r0 + 8) * DMODEL + col) >> 1;
                outhi[idx1] = h; outlo[idx1] = l;
            }
        }
    }
}

struct QkvArgs {
    const __nv_bfloat16* ahi[3];
    const __nv_bfloat16* alo[3];
    const __nv_bfloat16* whi[3];
    const __nv_bfloat16* wlo[3];
    const float* bias[3];
    uint32_t* ohi[3];
    uint32_t* olo[3];
    float scale[3];
};

__global__ __launch_bounds__(256)
void gemm_qkv_kernel(QkvArgs a)
{
    extern __shared__ char smraw[];
    int z = blockIdx.z;
    gemm_body(a.ahi[z], a.alo[z], a.whi[z], a.wlo[z], a.bias[z],
              nullptr, a.ohi[z], a.olo[z], a.scale[z], smem_u32(smraw));
}

__global__ __launch_bounds__(256)
void gemm_out_kernel(const __nv_bfloat16* __restrict__ Ahi,
                     const __nv_bfloat16* __restrict__ Alo,
                     const __nv_bfloat16* __restrict__ Bhi,
                     const __nv_bfloat16* __restrict__ Blo,
                     const float* __restrict__ bias, float* __restrict__ outf)
{
    extern __shared__ char smraw[];
    gemm_body(Ahi, Alo, Bhi, Blo, bias, outf, nullptr, nullptr, 1.0f,
              smem_u32(smraw));
}

// ---------------------------------------------------------------------------
// FA2-style mma.sync attention, split-bf16, 2-stage KV pipeline,
// bitmask masking, base-2 softmax, bf16 hi/lo epilogue.
// ---------------------------------------------------------------------------
#define AROWB 144
#define AQ_B   (128 * AROWB)
#define AKV_B  (64 * AROWB)
#define A_OFF_QH 0
#define A_OFF_QL AQ_B
#define A_STAGE0 (2 * AQ_B)
#define A_STAGE_B (4 * AKV_B)
#define A_OFF_KH 0
#define A_OFF_KL AKV_B
#define A_OFF_VH (2 * AKV_B)
#define A_OFF_VL (3 * AKV_B)
#define ATTN_SMEM (A_STAGE0 + 2 * A_STAGE_B)   // 110592
#define NKT (SEQ / 64)
#define MWORDS (SEQ / 64)

__global__ __launch_bounds__(256, 1)
void attn_mma_kernel(const __nv_bfloat16* __restrict__ qhi,
                     const __nv_bfloat16* __restrict__ qlo,
                     const __nv_bfloat16* __restrict__ khi,
                     const __nv_bfloat16* __restrict__ klo,
                     const __nv_bfloat16* __restrict__ vhi,
                     const __nv_bfloat16* __restrict__ vlo,
                     const unsigned long long* __restrict__ bm,
                     uint32_t* __restrict__ jhi,
                     uint32_t* __restrict__ jlo)
{
    extern __shared__ char smraw[];
    const uint32_t sbase = smem_u32(smraw);
    const int tid  = threadIdx.x;
    const int lane = tid & 31;
    const int wid  = tid >> 5;
    const int wm   = wid * 16;
    const int b    = blockIdx.z;
    const int h    = blockIdx.y;
    const int q0   = blockIdx.x * 128;

    // ---- load Q tile (hi/lo) ----
    #pragma unroll
    for (int u = tid; u < 1024; u += 256) {
        int r = u >> 3, c16 = u & 7;
        uint32_t d = sbase + r * AROWB + c16 * 16;
        size_t g = ((size_t)(b * SEQ + q0 + r)) * DMODEL + h * HDIM + c16 * 8;
        cp16(d + A_OFF_QH, qhi + g);
        cp16(d + A_OFF_QL, qlo + g);
    }
    CP_COMMIT(); CP_WAIT(0);
    __syncthreads();

    // ---- preload Q fragments ----
    uint32_t aqh[4][4], aql[4][4];
    {
        const int a_row = lane & 15;
        const int a_kb  = ((lane >> 4) & 1) * 16;
        #pragma unroll
        for (int kc = 0; kc < 4; kc++) {
            uint32_t addr = sbase + (wm + a_row) * AROWB + kc * 32 + a_kb;
            ldsm_x4(aqh[kc], addr + A_OFF_QH);
            ldsm_x4(aql[kc], addr + A_OFF_QL);
        }
    }

    const int g_   = lane >> 2;
    const int cq   = (lane & 3) * 2;
    const int b_row = (lane & 7) + ((lane >> 4) & 1) * 8;
    const int b_kb  = ((lane >> 3) & 1) * 16;
    const int v_row = lane & 15;
    const int v_col = (lane >> 4) * 8;

    const size_t bmrow0 = ((size_t)b * SEQ + q0 + wm + g_) * MWORDS;
    const size_t bmrow1 = bmrow0 + (size_t)8 * MWORDS;

    float o[8][4];
    #pragma unroll
    for (int i = 0; i < 8; i++)
        #pragma unroll
        for (int j = 0; j < 4; j++) o[i][j] = 0.0f;
    float m0r = -INFINITY, m1r = -INFINITY, l0r = 0.0f, l1r = 0.0f;

    auto load_kv = [&](int kt, int s) {
        uint32_t st = sbase + A_STAGE0 + s * A_STAGE_B;
        int k0 = kt * 64;
        #pragma unroll
        for (int u = tid; u < 512; u += 256) {
            int r = u >> 3, c16 = u & 7;
            uint32_t d = st + r * AROWB + c16 * 16;
            size_t g = ((size_t)(b * SEQ + k0 + r)) * DMODEL + h * HDIM + c16 * 8;
            cp16(d + A_OFF_KH, khi + g);
            cp16(d + A_OFF_KL, klo + g);
            cp16(d + A_OFF_VH, vhi + g);
            cp16(d + A_OFF_VL, vlo + g);
        }
    };

    load_kv(0, 0); CP_COMMIT();

    for (int kt = 0; kt < NKT; kt++) {
        int s = kt & 1;
        __syncthreads();
        if (kt + 1 < NKT) {
            load_kv(kt + 1, s ^ 1); CP_COMMIT();
            CP_WAIT(1);
        } else {
            CP_WAIT(0);
        }
        __syncthreads();

        uint32_t st = sbase + A_STAGE0 + s * A_STAGE_B;

        // issue mask loads early (hidden behind QK MMAs)
        unsigned long long mw0 = __ldg(bm + bmrow0 + kt);
        unsigned long long mw1 = __ldg(bm + bmrow1 + kt);

        // ---- S = Q K^T ----
        float sc[8][4];
        #pragma unroll
        for (int i = 0; i < 8; i++)
            #pragma unroll
            for (int j = 0; j < 4; j++) sc[i][j] = 0.0f;

        #pragma unroll
        for (int kc = 0; kc < 4; kc++) {
            #pragma unroll
            for (int np = 0; np < 4; np++) {
                uint32_t bh4[4], bl4[4];
                uint32_t addr = st + (np * 16 + b_row) * AROWB + kc * 32 + b_kb;
                ldsm_x4(bh4, addr + A_OFF_KH);
                ldsm_x4(bl4, addr + A_OFF_KL);
                mma16816(sc[np*2],   aqh[kc], bh4);
                mma16816(sc[np*2],   aqh[kc], bl4);
                mma16816(sc[np*2],   aql[kc], bh4);
                mma16816(sc[np*2+1], aqh[kc], bh4 + 2);
                mma16816(sc[np*2+1], aqh[kc], bl4 + 2);
                mma16816(sc[np*2+1], aql[kc], bh4 + 2);
            }
        }

        // ---- mask via bit tests ----
        #pragma unroll
        for (int nt = 0; nt < 8; nt++) {
            int c0 = nt * 8 + cq;
            if (!((mw0 >> c0) & 1))       sc[nt][0] = -1000000000.0f;
            if (!((mw0 >> (c0 + 1)) & 1)) sc[nt][1] = -1000000000.0f;
            if (!((mw1 >> c0) & 1))       sc[nt][2] = -1000000000.0f;
            if (!((mw1 >> (c0 + 1)) & 1)) sc[nt][3] = -1000000000.0f;
        }

        // ---- online softmax (base 2; log2e folded into Q scale) ----
        float mx0 = sc[0][0], mx1 = sc[0][2];
        #pragma unroll
        for (int nt = 0; nt < 8; nt++) {
            mx0 = fmaxf(mx0, fmaxf(sc[nt][0], sc[nt][1]));
            mx1 = fmaxf(mx1, fmaxf(sc[nt][2], sc[nt][3]));
        }
        mx0 = fmaxf(mx0, __shfl_xor_sync(0xffffffff, mx0, 1));
        mx0 = fmaxf(mx0, __shfl_xor_sync(0xffffffff, mx0, 2));
        mx1 = fmaxf(mx1, __shfl_xor_sync(0xffffffff, mx1, 1));
        mx1 = fmaxf(mx1, __shfl_xor_sync(0xffffffff, mx1, 2));

        float mn0 = fmaxf(m0r, mx0), mn1 = fmaxf(m1r, mx1);
        float al0 = exp2f(m0r - mn0), al1 = exp2f(m1r - mn1);
        m0r = mn0; m1r = mn1;

        float rs0 = 0.0f, rs1 = 0.0f;
        #pragma unroll
        for (int nt = 0; nt < 8; nt++) {
            sc[nt][0] = exp2f(sc[nt][0] - mn0); rs0 += sc[nt][0];
            sc[nt][1] = exp2f(sc[nt][1] - mn0); rs0 += sc[nt][1];
            sc[nt][2] = exp2f(sc[nt][2] - mn1); rs1 += sc[nt][2];
            sc[nt][3] = exp2f(sc[nt][3] - mn1); rs1 += sc[nt][3];
        }
        rs0 += __shfl_xor_sync(0xffffffff, rs0, 1);
        rs0 += __shfl_xor_sync(0xffffffff, rs0, 2);
        rs1 += __shfl_xor_sync(0xffffffff, rs1, 1);
        rs1 += __shfl_xor_sync(0xffffffff, rs1, 2);
        l0r = l0r * al0 + rs0;
        l1r = l1r * al1 + rs1;

        #pragma unroll
        for (int nt = 0; nt < 8; nt++) {
            o[nt][0] *= al0; o[nt][1] *= al0;
            o[nt][2] *= al1; o[nt][3] *= al1;
        }

        // ---- pack P into A-fragments ----
        uint32_t ph[4][4], pl[4][4];
        #pragma unroll
        for (int tp = 0; tp < 4; tp++) {
            pack_split(sc[2*tp][0],   sc[2*tp][1],   ph[tp][0], pl[tp][0]);
            pack_split(sc[2*tp][2],   sc[2*tp][3],   ph[tp][1], pl[tp][1]);
            pack_split(sc[2*tp+1][0], sc[2*tp+1][1], ph[tp][2], pl[tp][2]);
            pack_split(sc[2*tp+1][2], sc[2*tp+1][3], ph[tp][3], pl[tp][3]);
        }

        // ---- O += P V ----
        #pragma unroll
        for (int nt2 = 0; nt2 < 4; nt2++) {
            #pragma unroll
            for (int tp = 0; tp < 4; tp++) {
                uint32_t vh4[4], vl4[4];
                uint32_t addr = st + A_OFF_VH + (tp * 16 + v_row) * AROWB
                              + (nt2 * 16 + v_col) * 2;
                ldsm_x4_t(vh4, addr);
                ldsm_x4_t(vl4, addr + (A_OFF_VL - A_OFF_VH));
                mma16816(o[nt2*2],   ph[tp], vh4);
                mma16816(o[nt2*2],   ph[tp], vl4);
                mma16816(o[nt2*2],   pl[tp], vh4);
                mma16816(o[nt2*2+1], ph[tp], vh4 + 2);
                mma16816(o[nt2*2+1], ph[tp], vl4 + 2);
                mma16816(o[nt2*2+1], pl[tp], vh4 + 2);
            }
        }
    }

    // ---- epilogue: joint as bf16 hi/lo ----
    float inv0 = 1.0f / l0r, inv1 = 1.0f / l1r;
    size_t row0 = ((size_t)(b * SEQ + q0 + wm + g_)) * DMODEL + h * HDIM;
    #pragma unroll
    for (int nt = 0; nt < 8; nt++) {
        int col = nt * 8 + cq;
        uint32_t hh, ll;
        pack_split(o[nt][0] * inv0, o[nt][1] * inv0, hh, ll);
        size_t i0 = (row0 + col) >> 1;
        jhi[i0] = hh; jlo[i0] = ll;
        pack_split(o[nt][2] * inv1, o[nt][3] * inv1, hh, ll);
        size_t i1 = (row0 + (size_t)8 * DMODEL + col) >> 1;
        jhi[i1] = hh; jlo[i1] = ll;
    }
}

// ---------------------------------------------------------------------------
extern "C" void kernel_launch(void* const* d_in, const int* in_sizes, int n_in,
                              void* d_out, int out_size)
{
    const float* q    = (const float*)d_in[0];
    const float* k    = (const float*)d_in[1];
    const float* v    = (const float*)d_in[2];
    const int*   mask = (const int*)  d_in[3];
    const float* Wq   = (const float*)d_in[4];
    const float* bq   = (const float*)d_in[5];
    const float* Wk   = (const float*)d_in[6];
    const float* bk   = (const float*)d_in[7];
    const float* Wv   = (const float*)d_in[8];
    const float* bv   = (const float*)d_in[9];
    const float* Wo   = (const float*)d_in[10];
    const float* bo   = (const float*)d_in[11];
    float* out = (float*)d_out;

    void *p_xhi, *p_xlo, *p_whi4, *p_wlo4;
    void *p_qhi, *p_qlo, *p_khi, *p_klo, *p_vhi, *p_vlo, *p_jhi, *p_jlo, *p_bm;
    cudaGetSymbolAddress(&p_xhi, g_xhi);
    cudaGetSymbolAddress(&p_xlo, g_xlo);
    cudaGetSymbolAddress(&p_whi4, g_whi4);
    cudaGetSymbolAddress(&p_wlo4, g_wlo4);
    cudaGetSymbolAddress(&p_qhi, g_qhi);
    cudaGetSymbolAddress(&p_qlo, g_qlo);
    cudaGetSymbolAddress(&p_khi, g_khi);
    cudaGetSymbolAddress(&p_klo, g_klo);
    cudaGetSymbolAddress(&p_vhi, g_vhi);
    cudaGetSymbolAddress(&p_vlo, g_vlo);
    cudaGetSymbolAddress(&p_jhi, g_jhi);
    cudaGetSymbolAddress(&p_jlo, g_jlo);
    cudaGetSymbolAddress(&p_bm, g_maskbits);

    __nv_bfloat16* xhi = (__nv_bfloat16*)p_xhi;
    __nv_bfloat16* xlo = (__nv_bfloat16*)p_xlo;
    __nv_bfloat16* whi = (__nv_bfloat16*)p_whi4;
    __nv_bfloat16* wlo = (__nv_bfloat16*)p_wlo4;

    const size_t XN = (size_t)MTOT * DMODEL;
    const size_t WN = (size_t)DMODEL * DMODEL;

    cudaFuncSetAttribute(gemm_qkv_kernel,
                         cudaFuncAttributeMaxDynamicSharedMemorySize, GEMM_SMEM);
    cudaFuncSetAttribute(gemm_out_kernel,
                         cudaFuncAttributeMaxDynamicSharedMemorySize, GEMM_SMEM);
    cudaFuncSetAttribute(attn_mma_kernel,
                         cudaFuncAttributeMaxDynamicSharedMemorySize, ATTN_SMEM);

    // 1. pack mask
    mask_pack_kernel<<<(BATCH*SEQ*SEQ/64)/256, 256>>>((const int4*)mask,
        (unsigned long long*)p_bm);

    // 2. split everything (q,k,v + 4 weights) in one launch
    SplitAll sa;
    sa.src[0] = (const float4*)q;  sa.src[1] = (const float4*)k;
    sa.src[2] = (const float4*)v;
    sa.src[3] = (const float4*)Wq; sa.src[4] = (const float4*)Wk;
    sa.src[5] = (const float4*)Wv; sa.src[6] = (const float4*)Wo;
    for (int i = 0; i < 3; i++) {
        sa.hi[i] = (uint32_t*)(xhi + i * XN);
        sa.lo[i] = (uint32_t*)(xlo + i * XN);
    }
    for (int i = 0; i < 4; i++) {
        sa.hi[3+i] = (uint32_t*)(whi + i * WN);
        sa.lo[3+i] = (uint32_t*)(wlo + i * WN);
    }
    split_all_kernel<<<SPLIT_BLOCKS, 256>>>(sa);

    // 3. fused QKV projections (scale log2e/8 folded into Q output)
    QkvArgs qa;
    qa.ahi[0] = xhi;          qa.alo[0] = xlo;
    qa.ahi[1] = xhi + XN;     qa.alo[1] = xlo + XN;
    qa.ahi[2] = xhi + 2*XN;   qa.alo[2] = xlo + 2*XN;
    qa.whi[0] = whi;          qa.wlo[0] = wlo;
    qa.whi[1] = whi + WN;     qa.wlo[1] = wlo + WN;
    qa.whi[2] = whi + 2*WN;   qa.wlo[2] = wlo + 2*WN;
    qa.bias[0] = bq; qa.bias[1] = bk; qa.bias[2] = bv;
    qa.ohi[0] = (uint32_t*)p_qhi; qa.olo[0] = (uint32_t*)p_qlo;
    qa.ohi[1] = (uint32_t*)p_khi; qa.olo[1] = (uint32_t*)p_klo;
    qa.ohi[2] = (uint32_t*)p_vhi; qa.olo[2] = (uint32_t*)p_vlo;
    qa.scale[0] = 0.125f * LOG2E; qa.scale[1] = 1.0f; qa.scale[2] = 1.0f;
    dim3 gq(DMODEL / BN, MTOT / BM, 3);   // 4 x 32 x 3
    gemm_qkv_kernel<<<gq, 256, GEMM_SMEM>>>(qa);

    // 4. attention
    dim3 ag(SEQ / 128, NHEADS, BATCH);
    attn_mma_kernel<<<ag, 256, ATTN_SMEM>>>(
        (const __nv_bfloat16*)p_qhi, (const __nv_bfloat16*)p_qlo,
        (const __nv_bfloat16*)p_khi, (const __nv_bfloat16*)p_klo,
        (const __nv_bfloat16*)p_vhi, (const __nv_bfloat16*)p_vlo,
        (const unsigned long long*)p_bm,
        (uint32_t*)p_jhi, (uint32_t*)p_jlo);

    // 5. output projection
    dim3 gg(DMODEL / BN, MTOT / BM);
    gemm_out_kernel<<<gg, 256, GEMM_SMEM>>>(
        (const __nv_bfloat16*)p_jhi, (const __nv_bfloat16*)p_jlo,
        whi + 3*WN, wlo + 3*WN, bo, out);
}

// round 8
// speedup vs baseline: 1.1963x; 1.0528x over previous
#include <cuda_runtime.h>
#include <cuda_bf16.h>
#include <cuda_fp16.h>
#include <cstdint>
#include <math.h>

#define BATCH 2
#define SEQ   2048
#define DMODEL 1024
#define NHEADS 16
#define HDIM  64
#define MTOT  (BATCH*SEQ)   // 4096
#define LOG2E 1.44269504088896f

// ---------------- scratch (allocation-free rule: device globals) -----------
__device__ __nv_bfloat16 g_xhi[3*MTOT*DMODEL];     // split q,k,v inputs
__device__ __nv_bfloat16 g_xlo[3*MTOT*DMODEL];
__device__ __nv_bfloat16 g_whi4[4*DMODEL*DMODEL];  // split Wq,Wk,Wv,Wo
__device__ __nv_bfloat16 g_wlo4[4*DMODEL*DMODEL];
__device__ __nv_bfloat16 g_qhi[MTOT*DMODEL];
__device__ __nv_bfloat16 g_qlo[MTOT*DMODEL];
__device__ __nv_bfloat16 g_khi[MTOT*DMODEL];
__device__ __nv_bfloat16 g_klo[MTOT*DMODEL];
__device__ __nv_bfloat16 g_vhi[MTOT*DMODEL];       // fp16 bits for V
__device__ __nv_bfloat16 g_vlo[MTOT*DMODEL];       // fp16 bits for V
__device__ __nv_bfloat16 g_jhi[MTOT*DMODEL];
__device__ __nv_bfloat16 g_jlo[MTOT*DMODEL];
__device__ unsigned long long g_maskbits[(size_t)BATCH*SEQ*SEQ/64];

// ---------------- helpers ---------------------------------------------------
__device__ __forceinline__ uint32_t smem_u32(const void* p) {
    uint32_t a;
    asm("{ .reg .u64 t; cvta.to.shared.u64 t, %1; cvt.u32.u64 %0, t; }"
        : "=r"(a) : "l"(p));
    return a;
}
__device__ __forceinline__ void cp16(uint32_t s, const void* g) {
    asm volatile("cp.async.cg.shared.global [%0], [%1], 16;" :: "r"(s), "l"(g));
}
#define CP_COMMIT()  asm volatile("cp.async.commit_group;" ::: "memory")
#define CP_WAIT(n)   asm volatile("cp.async.wait_group %0;" :: "n"(n) : "memory")

__device__ __forceinline__ void ldsm_x4(uint32_t* r, uint32_t addr) {
    asm volatile("ldmatrix.sync.aligned.m8n8.x4.shared.b16 {%0,%1,%2,%3}, [%4];"
                 : "=r"(r[0]), "=r"(r[1]), "=r"(r[2]), "=r"(r[3]) : "r"(addr));
}
__device__ __forceinline__ void ldsm_x4_t(uint32_t* r, uint32_t addr) {
    asm volatile("ldmatrix.sync.aligned.m8n8.x4.trans.shared.b16 {%0,%1,%2,%3}, [%4];"
                 : "=r"(r[0]), "=r"(r[1]), "=r"(r[2]), "=r"(r[3]) : "r"(addr));
}
__device__ __forceinline__ void mma16816(float* d, const uint32_t* a,
                                         const uint32_t* b) {
    asm volatile(
        "mma.sync.aligned.m16n8k16.row.col.f32.bf16.bf16.f32 "
        "{%0,%1,%2,%3}, {%4,%5,%6,%7}, {%8,%9}, {%0,%1,%2,%3};"
        : "+f"(d[0]), "+f"(d[1]), "+f"(d[2]), "+f"(d[3])
        : "r"(a[0]), "r"(a[1]), "r"(a[2]), "r"(a[3]), "r"(b[0]), "r"(b[1]));
}
__device__ __forceinline__ void mma16816h(float* d, const uint32_t* a,
                                          const uint32_t* b) {
    asm volatile(
        "mma.sync.aligned.m16n8k16.row.col.f32.f16.f16.f32 "
        "{%0,%1,%2,%3}, {%4,%5,%6,%7}, {%8,%9}, {%0,%1,%2,%3};"
        : "+f"(d[0]), "+f"(d[1]), "+f"(d[2]), "+f"(d[3])
        : "r"(a[0]), "r"(a[1]), "r"(a[2]), "r"(a[3]), "r"(b[0]), "r"(b[1]));
}
// bf16 hi + residual-lo pack
__device__ __forceinline__ void pack_split(float x, float y,
                                           uint32_t& hi, uint32_t& lo) {
    uint32_t h;
    asm("cvt.rn.bf16x2.f32 %0, %1, %2;" : "=r"(h) : "f"(y), "f"(x));
    float hx = __uint_as_float(h << 16);
    float hy = __uint_as_float(h & 0xffff0000u);
    float lx = x - hx, ly = y - hy;
    uint32_t l;
    asm("cvt.rn.bf16x2.f32 %0, %1, %2;" : "=r"(l) : "f"(ly), "f"(lx));
    hi = h; lo = l;
}
// fp16 hi + residual-lo pack
__device__ __forceinline__ void pack_split_f16(float x, float y,
                                               uint32_t& hi, uint32_t& lo) {
    __half2 h = __floats2half2_rn(x, y);
    float hx = __low2float(h), hy = __high2float(h);
    __half2 l = __floats2half2_rn(x - hx, y - hy);
    hi = *reinterpret_cast<uint32_t*>(&h);
    lo = *reinterpret_cast<uint32_t*>(&l);
}
// fp16 pack (no residual)
__device__ __forceinline__ uint32_t pack_f16(float x, float y) {
    __half2 h = __floats2half2_rn(x, y);
    return *reinterpret_cast<uint32_t*>(&h);
}

// ---------------------------------------------------------------------------
// split_all: one launch splits q,k,v + 4 weights (all bf16 hi/lo)
// ---------------------------------------------------------------------------
struct SplitAll {
    const float4* src[7];
    uint32_t* hi[7];
    uint32_t* lo[7];
};
#define NX_BLK 4096
#define NW_BLK 1024
#define SPLIT_BLOCKS (3*NX_BLK + 4*NW_BLK)

__global__ __launch_bounds__(256)
void split_all_kernel(SplitAll a)
{
    int bid = blockIdx.x;
    int seg, idx;
    if (bid < 3 * NX_BLK) { seg = bid / NX_BLK; idx = (bid % NX_BLK) * 256 + threadIdx.x; }
    else { int r = bid - 3 * NX_BLK; seg = 3 + r / NW_BLK; idx = (r % NW_BLK) * 256 + threadIdx.x; }
    float4 v = a.src[seg][idx];
    uint32_t h0, l0, h1, l1;
    pack_split(v.x, v.y, h0, l0);
    pack_split(v.z, v.w, h1, l1);
    uint32_t* hi = a.hi[seg];
    uint32_t* lo = a.lo[seg];
    hi[2*idx] = h0; hi[2*idx+1] = h1;
    lo[2*idx] = l0; lo[2*idx+1] = l1;
}

// ---------------------------------------------------------------------------
// mask pack: 64 int -> 1 uint64
// ---------------------------------------------------------------------------
__global__ __launch_bounds__(256)
void mask_pack_kernel(const int4* __restrict__ mask, unsigned long long* __restrict__ bm)
{
    int i = blockIdx.x * 256 + threadIdx.x;
    const int4* p = mask + (size_t)i * 16;
    unsigned long long w = 0;
    #pragma unroll
    for (int j = 0; j < 16; j++) {
        int4 v = p[j];
        w |= ((unsigned long long)(v.x != 0)) << (j*4);
        w |= ((unsigned long long)(v.y != 0)) << (j*4+1);
        w |= ((unsigned long long)(v.z != 0)) << (j*4+2);
        w |= ((unsigned long long)(v.w != 0)) << (j*4+3);
    }
    bm[i] = w;
}

// ---------------------------------------------------------------------------
// shared GEMM body (split-bf16 3-MMA, 2-stage cp.async), CTA 128x256.
// f16mode=1 -> pack output as fp16 hi/lo (for V).
// ---------------------------------------------------------------------------
#define BM 128
#define BN 256
#define BK 32
#define NCHUNK (DMODEL / BK)
#define ROWB 80
#define A_MAT_B (128 * ROWB)
#define B_MAT_B (256 * ROWB)
#define OFF_AH 0
#define OFF_AL A_MAT_B
#define OFF_BH (2 * A_MAT_B)
#define OFF_BL (2 * A_MAT_B + B_MAT_B)
#define STAGE_B (2 * A_MAT_B + 2 * B_MAT_B)
#define GEMM_SMEM (2 * STAGE_B)

__device__ __forceinline__ void gemm_body(
    const __nv_bfloat16* __restrict__ Ahi, const __nv_bfloat16* __restrict__ Alo,
    const __nv_bfloat16* __restrict__ Bhi, const __nv_bfloat16* __restrict__ Blo,
    const float* __restrict__ bias,
    float* __restrict__ outf, uint32_t* __restrict__ outhi,
    uint32_t* __restrict__ outlo, float scale, int f16mode, uint32_t sbase)
{
    const int tid  = threadIdx.x;
    const int lane = tid & 31;
    const int wid  = tid >> 5;
    const int wm   = (wid & 3) * 32;
    const int wn   = (wid >> 2) * 128;
    const int n0   = blockIdx.x * BN;
    const int m0   = blockIdx.y * BM;

    float c[2][16][4];
    #pragma unroll
    for (int mt = 0; mt < 2; mt++)
        #pragma unroll
        for (int nt = 0; nt < 16; nt++)
            #pragma unroll
            for (int j = 0; j < 4; j++) c[mt][nt][j] = 0.0f;

    auto load_chunk = [&](int ck, int s) {
        uint32_t st = sbase + s * STAGE_B;
        int k0 = ck * BK;
        #pragma unroll
        for (int u = tid; u < 512; u += 256) {
            int r = u >> 2, c16 = u & 3;
            uint32_t d = st + r * ROWB + c16 * 16;
            size_t g = (size_t)(m0 + r) * DMODEL + k0 + c16 * 8;
            cp16(d + OFF_AH, Ahi + g);
            cp16(d + OFF_AL, Alo + g);
        }
        #pragma unroll
        for (int u = tid; u < 1024; u += 256) {
            int r = u >> 2, c16 = u & 3;
            uint32_t d = st + r * ROWB + c16 * 16;
            size_t g = (size_t)(n0 + r) * DMODEL + k0 + c16 * 8;
            cp16(d + OFF_BH, Bhi + g);
            cp16(d + OFF_BL, Blo + g);
        }
    };

    load_chunk(0, 0); CP_COMMIT();

    const int a_row  = lane & 15;
    const int a_kb   = ((lane >> 4) & 1) * 16;
    const int b_row  = (lane & 7) + ((lane >> 4) & 1) * 8;
    const int b_kb   = ((lane >> 3) & 1) * 16;

    for (int ck = 0; ck < NCHUNK; ck++) {
        int s = ck & 1;
        if (ck + 1 < NCHUNK) {
            load_chunk(ck + 1, s ^ 1); CP_COMMIT();
            CP_WAIT(1);
        } else {
            CP_WAIT(0);
        }
        __syncthreads();

        uint32_t st = sbase + s * STAGE_B;
        #pragma unroll
        for (int ks = 0; ks < 2; ks++) {
            int kb = ks * 32;
            uint32_t ah[2][4], al[2][4];
            #pragma unroll
            for (int mt = 0; mt < 2; mt++) {
                uint32_t addr = st + (wm + mt * 16 + a_row) * ROWB + kb + a_kb;
                ldsm_x4(ah[mt], addr + OFF_AH);
                ldsm_x4(al[mt], addr + OFF_AL);
            }
            #pragma unroll
            for (int np = 0; np < 8; np++) {
                uint32_t bh4[4], bl4[4];
                uint32_t addr = st + (wn + np * 16 + b_row) * ROWB + kb + b_kb;
                ldsm_x4(bh4, addr + OFF_BH);
                ldsm_x4(bl4, addr + OFF_BL);
                #pragma unroll
                for (int mt = 0; mt < 2; mt++) {
                    mma16816(c[mt][np*2],   ah[mt], bh4);
                    mma16816(c[mt][np*2],   ah[mt], bl4);
                    mma16816(c[mt][np*2],   al[mt], bh4);
                    mma16816(c[mt][np*2+1], ah[mt], bh4 + 2);
                    mma16816(c[mt][np*2+1], ah[mt], bl4 + 2);
                    mma16816(c[mt][np*2+1], al[mt], bh4 + 2);
                }
            }
        }
        __syncthreads();
    }

    const int g  = lane >> 2;
    const int cq = (lane & 3) * 2;
    #pragma unroll
    for (int mt = 0; mt < 2; mt++) {
        #pragma unroll
        for (int nt = 0; nt < 16; nt++) {
            int col = n0 + wn + nt * 8 + cq;
            float2 bv = *(const float2*)(bias + col);
            int r0 = m0 + wm + mt * 16 + g;
            float x0 = c[mt][nt][0] + bv.x, y0 = c[mt][nt][1] + bv.y;
            float x1 = c[mt][nt][2] + bv.x, y1 = c[mt][nt][3] + bv.y;
            if (outf) {
                *(float2*)(outf + (size_t)r0 * DMODEL + col) = make_float2(x0, y0);
                *(float2*)(outf + (size_t)(r0 + 8) * DMODEL + col) = make_float2(x1, y1);
            } else {
                uint32_t h, l;
                size_t idx0 = ((size_t)r0 * DMODEL + col) >> 1;
                size_t idx1 = ((size_t)(r0 + 8) * DMODEL + col) >> 1;
                if (f16mode) {
                    pack_split_f16(x0, y0, h, l);
                    outhi[idx0] = h; outlo[idx0] = l;
                    pack_split_f16(x1, y1, h, l);
                    outhi[idx1] = h; outlo[idx1] = l;
                } else {
                    pack_split(x0 * scale, y0 * scale, h, l);
                    outhi[idx0] = h; outlo[idx0] = l;
                    pack_split(x1 * scale, y1 * scale, h, l);
                    outhi[idx1] = h; outlo[idx1] = l;
                }
            }
        }
    }
}

struct QkvArgs {
    const __nv_bfloat16* ahi[3];
    const __nv_bfloat16* alo[3];
    const __nv_bfloat16* whi[3];
    const __nv_bfloat16* wlo[3];
    const float* bias[3];
    uint32_t* ohi[3];
    uint32_t* olo[3];
    float scale[3];
    int f16mode[3];
};

__global__ __launch_bounds__(256)
void gemm_qkv_kernel(QkvArgs a)
{
    extern __shared__ char smraw[];
    int z = blockIdx.z;
    gemm_body(a.ahi[z], a.alo[z], a.whi[z], a.wlo[z], a.bias[z],
              nullptr, a.ohi[z], a.olo[z], a.scale[z], a.f16mode[z],
              smem_u32(smraw));
}

__global__ __launch_bounds__(256)
void gemm_out_kernel(const __nv_bfloat16* __restrict__ Ahi,
                     const __nv_bfloat16* __restrict__ Alo,
                     const __nv_bfloat16* __restrict__ Bhi,
                     const __nv_bfloat16* __restrict__ Blo,
                     const float* __restrict__ bias, float* __restrict__ outf)
{
    extern __shared__ char smraw[];
    gemm_body(Ahi, Alo, Bhi, Blo, bias, outf, nullptr, nullptr, 1.0f, 0,
              smem_u32(smraw));
}

// ---------------------------------------------------------------------------
// FA2-style attention: QK^T split-bf16 (3 MMAs), PV fp16 P x fp16 V hi/lo
// (2 MMAs). Bitmask mask, base-2 softmax, bf16 hi/lo epilogue.
// ---------------------------------------------------------------------------
#define AROWB 144
#define AQ_B   (128 * AROWB)
#define AKV_B  (64 * AROWB)
#define A_OFF_QH 0
#define A_OFF_QL AQ_B
#define A_STAGE0 (2 * AQ_B)
#define A_STAGE_B (4 * AKV_B)
#define A_OFF_KH 0
#define A_OFF_KL AKV_B
#define A_OFF_VH (2 * AKV_B)
#define A_OFF_VL (3 * AKV_B)
#define ATTN_SMEM (A_STAGE0 + 2 * A_STAGE_B)
#define NKT (SEQ / 64)
#define MWORDS (SEQ / 64)

__global__ __launch_bounds__(256, 1)
void attn_mma_kernel(const __nv_bfloat16* __restrict__ qhi,
                     const __nv_bfloat16* __restrict__ qlo,
                     const __nv_bfloat16* __restrict__ khi,
                     const __nv_bfloat16* __restrict__ klo,
                     const __nv_bfloat16* __restrict__ vhi,
                     const __nv_bfloat16* __restrict__ vlo,
                     const unsigned long long* __restrict__ bm,
                     uint32_t* __restrict__ jhi,
                     uint32_t* __restrict__ jlo)
{
    extern __shared__ char smraw[];
    const uint32_t sbase = smem_u32(smraw);
    const int tid  = threadIdx.x;
    const int lane = tid & 31;
    const int wid  = tid >> 5;
    const int wm   = wid * 16;
    const int b    = blockIdx.z;
    const int h    = blockIdx.y;
    const int q0   = blockIdx.x * 128;

    #pragma unroll
    for (int u = tid; u < 1024; u += 256) {
        int r = u >> 3, c16 = u & 7;
        uint32_t d = sbase + r * AROWB + c16 * 16;
        size_t g = ((size_t)(b * SEQ + q0 + r)) * DMODEL + h * HDIM + c16 * 8;
        cp16(d + A_OFF_QH, qhi + g);
        cp16(d + A_OFF_QL, qlo + g);
    }
    CP_COMMIT(); CP_WAIT(0);
    __syncthreads();

    uint32_t aqh[4][4], aql[4][4];
    {
        const int a_row = lane & 15;
        const int a_kb  = ((lane >> 4) & 1) * 16;
        #pragma unroll
        for (int kc = 0; kc < 4; kc++) {
            uint32_t addr = sbase + (wm + a_row) * AROWB + kc * 32 + a_kb;
            ldsm_x4(aqh[kc], addr + A_OFF_QH);
            ldsm_x4(aql[kc], addr + A_OFF_QL);
        }
    }

    const int g_   = lane >> 2;
    const int cq   = (lane & 3) * 2;
    const int b_row = (lane & 7) + ((lane >> 4) & 1) * 8;
    const int b_kb  = ((lane >> 3) & 1) * 16;
    const int v_row = lane & 15;
    const int v_col = (lane >> 4) * 8;

    const size_t bmrow0 = ((size_t)b * SEQ + q0 + wm + g_) * MWORDS;
    const size_t bmrow1 = bmrow0 + (size_t)8 * MWORDS;

    float o[8][4];
    #pragma unroll
    for (int i = 0; i < 8; i++)
        #pragma unroll
        for (int j = 0; j < 4; j++) o[i][j] = 0.0f;
    float m0r = -INFINITY, m1r = -INFINITY, l0r = 0.0f, l1r = 0.0f;

    auto load_kv = [&](int kt, int s) {
        uint32_t st = sbase + A_STAGE0 + s * A_STAGE_B;
        int k0 = kt * 64;
        #pragma unroll
        for (int u = tid; u < 512; u += 256) {
            int r = u >> 3, c16 = u & 7;
            uint32_t d = st + r * AROWB + c16 * 16;
            size_t g = ((size_t)(b * SEQ + k0 + r)) * DMODEL + h * HDIM + c16 * 8;
            cp16(d + A_OFF_KH, khi + g);
            cp16(d + A_OFF_KL, klo + g);
            cp16(d + A_OFF_VH, vhi + g);
            cp16(d + A_OFF_VL, vlo + g);
        }
    };

    load_kv(0, 0); CP_COMMIT();

    for (int kt = 0; kt < NKT; kt++) {
        int s = kt & 1;
        __syncthreads();
        if (kt + 1 < NKT) {
            load_kv(kt + 1, s ^ 1); CP_COMMIT();
            CP_WAIT(1);
        } else {
            CP_WAIT(0);
        }
        __syncthreads();

        uint32_t st = sbase + A_STAGE0 + s * A_STAGE_B;

        unsigned long long mw0 = __ldg(bm + bmrow0 + kt);
        unsigned long long mw1 = __ldg(bm + bmrow1 + kt);

        // ---- S = Q K^T (split-bf16) ----
        float sc[8][4];
        #pragma unroll
        for (int i = 0; i < 8; i++)
            #pragma unroll
            for (int j = 0; j < 4; j++) sc[i][j] = 0.0f;

        #pragma unroll
        for (int kc = 0; kc < 4; kc++) {
            #pragma unroll
            for (int np = 0; np < 4; np++) {
                uint32_t bh4[4], bl4[4];
                uint32_t addr = st + (np * 16 + b_row) * AROWB + kc * 32 + b_kb;
                ldsm_x4(bh4, addr + A_OFF_KH);
                ldsm_x4(bl4, addr + A_OFF_KL);
                mma16816(sc[np*2],   aqh[kc], bh4);
                mma16816(sc[np*2],   aqh[kc], bl4);
                mma16816(sc[np*2],   aql[kc], bh4);
                mma16816(sc[np*2+1], aqh[kc], bh4 + 2);
                mma16816(sc[np*2+1], aqh[kc], bl4 + 2);
                mma16816(sc[np*2+1], aql[kc], bh4 + 2);
            }
        }

        // ---- mask ----
        #pragma unroll
        for (int nt = 0; nt < 8; nt++) {
            int c0 = nt * 8 + cq;
            if (!((mw0 >> c0) & 1))       sc[nt][0] = -1000000000.0f;
            if (!((mw0 >> (c0 + 1)) & 1)) sc[nt][1] = -1000000000.0f;
            if (!((mw1 >> c0) & 1))       sc[nt][2] = -1000000000.0f;
            if (!((mw1 >> (c0 + 1)) & 1)) sc[nt][3] = -1000000000.0f;
        }

        // ---- online softmax (base 2) ----
        float mx0 = sc[0][0], mx1 = sc[0][2];
        #pragma unroll
        for (int nt = 0; nt < 8; nt++) {
            mx0 = fmaxf(mx0, fmaxf(sc[nt][0], sc[nt][1]));
            mx1 = fmaxf(mx1, fmaxf(sc[nt][2], sc[nt][3]));
        }
        mx0 = fmaxf(mx0, __shfl_xor_sync(0xffffffff, mx0, 1));
        mx0 = fmaxf(mx0, __shfl_xor_sync(0xffffffff, mx0, 2));
        mx1 = fmaxf(mx1, __shfl_xor_sync(0xffffffff, mx1, 1));
        mx1 = fmaxf(mx1, __shfl_xor_sync(0xffffffff, mx1, 2));

        float mn0 = fmaxf(m0r, mx0), mn1 = fmaxf(m1r, mx1);
        float al0 = exp2f(m0r - mn0), al1 = exp2f(m1r - mn1);
        m0r = mn0; m1r = mn1;

        float rs0 = 0.0f, rs1 = 0.0f;
        #pragma unroll
        for (int nt = 0; nt < 8; nt++) {
            sc[nt][0] = exp2f(sc[nt][0] - mn0); rs0 += sc[nt][0];
            sc[nt][1] = exp2f(sc[nt][1] - mn0); rs0 += sc[nt][1];
            sc[nt][2] = exp2f(sc[nt][2] - mn1); rs1 += sc[nt][2];
            sc[nt][3] = exp2f(sc[nt][3] - mn1); rs1 += sc[nt][3];
        }
        rs0 += __shfl_xor_sync(0xffffffff, rs0, 1);
        rs0 += __shfl_xor_sync(0xffffffff, rs0, 2);
        rs1 += __shfl_xor_sync(0xffffffff, rs1, 1);
        rs1 += __shfl_xor_sync(0xffffffff, rs1, 2);
        l0r = l0r * al0 + rs0;
        l1r = l1r * al1 + rs1;

        #pragma unroll
        for (int nt = 0; nt < 8; nt++) {
            o[nt][0] *= al0; o[nt][1] *= al0;
            o[nt][2] *= al1; o[nt][3] *= al1;
        }

        // ---- pack P into fp16 A-fragments (no residual) ----
        uint32_t ph[4][4];
        #pragma unroll
        for (int tp = 0; tp < 4; tp++) {
            ph[tp][0] = pack_f16(sc[2*tp][0],   sc[2*tp][1]);
            ph[tp][1] = pack_f16(sc[2*tp][2],   sc[2*tp][3]);
            ph[tp][2] = pack_f16(sc[2*tp+1][0], sc[2*tp+1][1]);
            ph[tp][3] = pack_f16(sc[2*tp+1][2], sc[2*tp+1][3]);
        }

        // ---- O += P V (fp16 x fp16 hi/lo, 2 MMAs) ----
        #pragma unroll
        for (int nt2 = 0; nt2 < 4; nt2++) {
            #pragma unroll
            for (int tp = 0; tp < 4; tp++) {
                uint32_t vh4[4], vl4[4];
                uint32_t addr = st + A_OFF_VH + (tp * 16 + v_row) * AROWB
                              + (nt2 * 16 + v_col) * 2;
                ldsm_x4_t(vh4, addr);
                ldsm_x4_t(vl4, addr + (A_OFF_VL - A_OFF_VH));
                mma16816h(o[nt2*2],   ph[tp], vh4);
                mma16816h(o[nt2*2],   ph[tp], vl4);
                mma16816h(o[nt2*2+1], ph[tp], vh4 + 2);
                mma16816h(o[nt2*2+1], ph[tp], vl4 + 2);
            }
        }
    }

    // ---- epilogue: joint as bf16 hi/lo ----
    float inv0 = 1.0f / l0r, inv1 = 1.0f / l1r;
    size_t row0 = ((size_t)(b * SEQ + q0 + wm + g_)) * DMODEL + h * HDIM;
    #pragma unroll
    for (int nt = 0; nt < 8; nt++) {
        int col = nt * 8 + cq;
        uint32_t hh, ll;
        pack_split(o[nt][0] * inv0, o[nt][1] * inv0, hh, ll);
        size_t i0 = (row0 + col) >> 1;
        jhi[i0] = hh; jlo[i0] = ll;
        pack_split(o[nt][2] * inv1, o[nt][3] * inv1, hh, ll);
        size_t i1 = (row0 + (size_t)8 * DMODEL + col) >> 1;
        jhi[i1] = hh; jlo[i1] = ll;
    }
}

// ---------------------------------------------------------------------------
extern "C" void kernel_launch(void* const* d_in, const int* in_sizes, int n_in,
                              void* d_out, int out_size)
{
    const float* q    = (const float*)d_in[0];
    const float* k    = (const float*)d_in[1];
    const float* v    = (const float*)d_in[2];
    const int*   mask = (const int*)  d_in[3];
    const float* Wq   = (const float*)d_in[4];
    const float* bq   = (const float*)d_in[5];
    const float* Wk   = (const float*)d_in[6];
    const float* bk   = (const float*)d_in[7];
    const float* Wv   = (const float*)d_in[8];
    const float* bv   = (const float*)d_in[9];
    const float* Wo   = (const float*)d_in[10];
    const float* bo   = (const float*)d_in[11];
    float* out = (float*)d_out;

    void *p_xhi, *p_xlo, *p_whi4, *p_wlo4;
    void *p_qhi, *p_qlo, *p_khi, *p_klo, *p_vhi, *p_vlo, *p_jhi, *p_jlo, *p_bm;
    cudaGetSymbolAddress(&p_xhi, g_xhi);
    cudaGetSymbolAddress(&p_xlo, g_xlo);
    cudaGetSymbolAddress(&p_whi4, g_whi4);
    cudaGetSymbolAddress(&p_wlo4, g_wlo4);
    cudaGetSymbolAddress(&p_qhi, g_qhi);
    cudaGetSymbolAddress(&p_qlo, g_qlo);
    cudaGetSymbolAddress(&p_khi, g_khi);
    cudaGetSymbolAddress(&p_klo, g_klo);
    cudaGetSymbolAddress(&p_vhi, g_vhi);
    cudaGetSymbolAddress(&p_vlo, g_vlo);
    cudaGetSymbolAddress(&p_jhi, g_jhi);
    cudaGetSymbolAddress(&p_jlo, g_jlo);
    cudaGetSymbolAddress(&p_bm, g_maskbits);

    __nv_bfloat16* xhi = (__nv_bfloat16*)p_xhi;
    __nv_bfloat16* xlo = (__nv_bfloat16*)p_xlo;
    __nv_bfloat16* whi = (__nv_bfloat16*)p_whi4;
    __nv_bfloat16* wlo = (__nv_bfloat16*)p_wlo4;

    const size_t XN = (size_t)MTOT * DMODEL;
    const size_t WN = (size_t)DMODEL * DMODEL;

    cudaFuncSetAttribute(gemm_qkv_kernel,
                         cudaFuncAttributeMaxDynamicSharedMemorySize, GEMM_SMEM);
    cudaFuncSetAttribute(gemm_out_kernel,
                         cudaFuncAttributeMaxDynamicSharedMemorySize, GEMM_SMEM);
    cudaFuncSetAttribute(attn_mma_kernel,
                         cudaFuncAttributeMaxDynamicSharedMemorySize, ATTN_SMEM);

    // 1. pack mask
    mask_pack_kernel<<<(BATCH*SEQ*SEQ/64)/256, 256>>>((const int4*)mask,
        (unsigned long long*)p_bm);

    // 2. split all inputs/weights
    SplitAll sa;
    sa.src[0] = (const float4*)q;  sa.src[1] = (const float4*)k;
    sa.src[2] = (const float4*)v;
    sa.src[3] = (const float4*)Wq; sa.src[4] = (const float4*)Wk;
    sa.src[5] = (const float4*)Wv; sa.src[6] = (const float4*)Wo;
    for (int i = 0; i < 3; i++) {
        sa.hi[i] = (uint32_t*)(xhi + i * XN);
        sa.lo[i] = (uint32_t*)(xlo + i * XN);
    }
    for (int i = 0; i < 4; i++) {
        sa.hi[3+i] = (uint32_t*)(whi + i * WN);
        sa.lo[3+i] = (uint32_t*)(wlo + i * WN);
    }
    split_all_kernel<<<SPLIT_BLOCKS, 256>>>(sa);

    // 3. fused QKV projections (Q scaled by log2e/8; V packed as fp16 hi/lo)
    QkvArgs qa;
    qa.ahi[0] = xhi;          qa.alo[0] = xlo;
    qa.ahi[1] = xhi + XN;     qa.alo[1] = xlo + XN;
    qa.ahi[2] = xhi + 2*XN;   qa.alo[2] = xlo + 2*XN;
    qa.whi[0] = whi;          qa.wlo[0] = wlo;
    qa.whi[1] = whi + WN;     qa.wlo[1] = wlo + WN;
    qa.whi[2] = whi + 2*WN;   qa.wlo[2] = wlo + 2*WN;
    qa.bias[0] = bq; qa.bias[1] = bk; qa.bias[2] = bv;
    qa.ohi[0] = (uint32_t*)p_qhi; qa.olo[0] = (uint32_t*)p_qlo;
    qa.ohi[1] = (uint32_t*)p_khi; qa.olo[1] = (uint32_t*)p_klo;
    qa.ohi[2] = (uint32_t*)p_vhi; qa.olo[2] = (uint32_t*)p_vlo;
    qa.scale[0] = 0.125f * LOG2E; qa.scale[1] = 1.0f; qa.scale[2] = 1.0f;
    qa.f16mode[0] = 0; qa.f16mode[1] = 0; qa.f16mode[2] = 1;
    dim3 gq(DMODEL / BN, MTOT / BM, 3);
    gemm_qkv_kernel<<<gq, 256, GEMM_SMEM>>>(qa);

    // 4. attention
    dim3 ag(SEQ / 128, NHEADS, BATCH);
    attn_mma_kernel<<<ag, 256, ATTN_SMEM>>>(
        (const __nv_bfloat16*)p_qhi, (const __nv_bfloat16*)p_qlo,
        (const __nv_bfloat16*)p_khi, (const __nv_bfloat16*)p_klo,
        (const __nv_bfloat16*)p_vhi, (const __nv_bfloat16*)p_vlo,
        (const unsigned long long*)p_bm,
        (uint32_t*)p_jhi, (uint32_t*)p_jlo);

    // 5. output projection
    dim3 gg(DMODEL / BN, MTOT / BM);
    gemm_out_kernel<<<gg, 256, GEMM_SMEM>>>(
        (const __nv_bfloat16*)p_jhi, (const __nv_bfloat16*)p_jlo,
        whi + 3*WN, wlo + 3*WN, bo, out);
}

// round 9
// speedup vs baseline: 1.2333x; 1.0310x over previous
#include <cuda_runtime.h>
#include <cuda_bf16.h>
#include <cuda_fp16.h>
#include <cstdint>
#include <math.h>

#define BATCH 2
#define SEQ   2048
#define DMODEL 1024
#define NHEADS 16
#define HDIM  64
#define MTOT  (BATCH*SEQ)   // 4096
#define LOG2E 1.44269504088896f

// ---------------- scratch (allocation-free rule: device globals) -----------
__device__ __nv_bfloat16 g_xhi[3*MTOT*DMODEL];
__device__ __nv_bfloat16 g_xlo[3*MTOT*DMODEL];
__device__ __nv_bfloat16 g_whi4[4*DMODEL*DMODEL];
__device__ __nv_bfloat16 g_wlo4[4*DMODEL*DMODEL];
__device__ __nv_bfloat16 g_qhi[MTOT*DMODEL];
__device__ __nv_bfloat16 g_qlo[MTOT*DMODEL];
__device__ __nv_bfloat16 g_khi[MTOT*DMODEL];
__device__ __nv_bfloat16 g_klo[MTOT*DMODEL];
__device__ __nv_bfloat16 g_vhi[MTOT*DMODEL];       // fp16 bits
__device__ __nv_bfloat16 g_vlo[MTOT*DMODEL];       // fp16 bits
__device__ __nv_bfloat16 g_jhi[MTOT*DMODEL];
__device__ __nv_bfloat16 g_jlo[MTOT*DMODEL];
__device__ unsigned long long g_maskbits[(size_t)BATCH*SEQ*SEQ/64];

// ---------------- helpers ---------------------------------------------------
__device__ __forceinline__ uint32_t smem_u32(const void* p) {
    uint32_t a;
    asm("{ .reg .u64 t; cvta.to.shared.u64 t, %1; cvt.u32.u64 %0, t; }"
        : "=r"(a) : "l"(p));
    return a;
}
__device__ __forceinline__ void cp16(uint32_t s, const void* g) {
    asm volatile("cp.async.cg.shared.global [%0], [%1], 16;" :: "r"(s), "l"(g));
}
#define CP_COMMIT()  asm volatile("cp.async.commit_group;" ::: "memory")
#define CP_WAIT(n)   asm volatile("cp.async.wait_group %0;" :: "n"(n) : "memory")

__device__ __forceinline__ void ldsm_x4(uint32_t* r, uint32_t addr) {
    asm volatile("ldmatrix.sync.aligned.m8n8.x4.shared.b16 {%0,%1,%2,%3}, [%4];"
                 : "=r"(r[0]), "=r"(r[1]), "=r"(r[2]), "=r"(r[3]) : "r"(addr));
}
__device__ __forceinline__ void ldsm_x4_t(uint32_t* r, uint32_t addr) {
    asm volatile("ldmatrix.sync.aligned.m8n8.x4.trans.shared.b16 {%0,%1,%2,%3}, [%4];"
                 : "=r"(r[0]), "=r"(r[1]), "=r"(r[2]), "=r"(r[3]) : "r"(addr));
}
__device__ __forceinline__ void mma16816(float* d, const uint32_t* a,
                                         const uint32_t* b) {
    asm volatile(
        "mma.sync.aligned.m16n8k16.row.col.f32.bf16.bf16.f32 "
        "{%0,%1,%2,%3}, {%4,%5,%6,%7}, {%8,%9}, {%0,%1,%2,%3};"
        : "+f"(d[0]), "+f"(d[1]), "+f"(d[2]), "+f"(d[3])
        : "r"(a[0]), "r"(a[1]), "r"(a[2]), "r"(a[3]), "r"(b[0]), "r"(b[1]));
}
__device__ __forceinline__ void mma16816h(float* d, const uint32_t* a,
                                          const uint32_t* b) {
    asm volatile(
        "mma.sync.aligned.m16n8k16.row.col.f32.f16.f16.f32 "
        "{%0,%1,%2,%3}, {%4,%5,%6,%7}, {%8,%9}, {%0,%1,%2,%3};"
        : "+f"(d[0]), "+f"(d[1]), "+f"(d[2]), "+f"(d[3])
        : "r"(a[0]), "r"(a[1]), "r"(a[2]), "r"(a[3]), "r"(b[0]), "r"(b[1]));
}
__device__ __forceinline__ void pack_split(float x, float y,
                                           uint32_t& hi, uint32_t& lo) {
    uint32_t h;
    asm("cvt.rn.bf16x2.f32 %0, %1, %2;" : "=r"(h) : "f"(y), "f"(x));
    float hx = __uint_as_float(h << 16);
    float hy = __uint_as_float(h & 0xffff0000u);
    float lx = x - hx, ly = y - hy;
    uint32_t l;
    asm("cvt.rn.bf16x2.f32 %0, %1, %2;" : "=r"(l) : "f"(ly), "f"(lx));
    hi = h; lo = l;
}
__device__ __forceinline__ void pack_split_f16(float x, float y,
                                               uint32_t& hi, uint32_t& lo) {
    __half2 h = __floats2half2_rn(x, y);
    float hx = __low2float(h), hy = __high2float(h);
    __half2 l = __floats2half2_rn(x - hx, y - hy);
    hi = *reinterpret_cast<uint32_t*>(&h);
    lo = *reinterpret_cast<uint32_t*>(&l);
}
__device__ __forceinline__ uint32_t pack_f16(float x, float y) {
    __half2 h = __floats2half2_rn(x, y);
    return *reinterpret_cast<uint32_t*>(&h);
}

// ---------------------------------------------------------------------------
// split_all
// ---------------------------------------------------------------------------
struct SplitAll {
    const float4* src[7];
    uint32_t* hi[7];
    uint32_t* lo[7];
};
#define NX_BLK 4096
#define NW_BLK 1024
#define SPLIT_BLOCKS (3*NX_BLK + 4*NW_BLK)

__global__ __launch_bounds__(256)
void split_all_kernel(SplitAll a)
{
    int bid = blockIdx.x;
    int seg, idx;
    if (bid < 3 * NX_BLK) { seg = bid / NX_BLK; idx = (bid % NX_BLK) * 256 + threadIdx.x; }
    else { int r = bid - 3 * NX_BLK; seg = 3 + r / NW_BLK; idx = (r % NW_BLK) * 256 + threadIdx.x; }
    float4 v = a.src[seg][idx];
    uint32_t h0, l0, h1, l1;
    pack_split(v.x, v.y, h0, l0);
    pack_split(v.z, v.w, h1, l1);
    uint32_t* hi = a.hi[seg];
    uint32_t* lo = a.lo[seg];
    hi[2*idx] = h0; hi[2*idx+1] = h1;
    lo[2*idx] = l0; lo[2*idx+1] = l1;
}

// ---------------------------------------------------------------------------
// mask pack
// ---------------------------------------------------------------------------
__global__ __launch_bounds__(256)
void mask_pack_kernel(const int4* __restrict__ mask, unsigned long long* __restrict__ bm)
{
    int i = blockIdx.x * 256 + threadIdx.x;
    const int4* p = mask + (size_t)i * 16;
    unsigned long long w = 0;
    #pragma unroll
    for (int j = 0; j < 16; j++) {
        int4 v = p[j];
        w |= ((unsigned long long)(v.x != 0)) << (j*4);
        w |= ((unsigned long long)(v.y != 0)) << (j*4+1);
        w |= ((unsigned long long)(v.z != 0)) << (j*4+2);
        w |= ((unsigned long long)(v.w != 0)) << (j*4+3);
    }
    bm[i] = w;
}

// ---------------------------------------------------------------------------
// GEMM body (split-bf16 3-MMA, 2-stage cp.async), CTA 128x256.
// ---------------------------------------------------------------------------
#define BM 128
#define BN 256
#define BK 32
#define NCHUNK (DMODEL / BK)
#define ROWB 80
#define A_MAT_B (128 * ROWB)
#define B_MAT_B (256 * ROWB)
#define OFF_AH 0
#define OFF_AL A_MAT_B
#define OFF_BH (2 * A_MAT_B)
#define OFF_BL (2 * A_MAT_B + B_MAT_B)
#define STAGE_B (2 * A_MAT_B + 2 * B_MAT_B)
#define GEMM_SMEM (2 * STAGE_B)

__device__ __forceinline__ void gemm_body(
    const __nv_bfloat16* __restrict__ Ahi, const __nv_bfloat16* __restrict__ Alo,
    const __nv_bfloat16* __restrict__ Bhi, const __nv_bfloat16* __restrict__ Blo,
    const float* __restrict__ bias,
    float* __restrict__ outf, uint32_t* __restrict__ outhi,
    uint32_t* __restrict__ outlo, float scale, int f16mode, uint32_t sbase)
{
    const int tid  = threadIdx.x;
    const int lane = tid & 31;
    const int wid  = tid >> 5;
    const int wm   = (wid & 3) * 32;
    const int wn   = (wid >> 2) * 128;
    const int n0   = blockIdx.x * BN;
    const int m0   = blockIdx.y * BM;

    float c[2][16][4];
    #pragma unroll
    for (int mt = 0; mt < 2; mt++)
        #pragma unroll
        for (int nt = 0; nt < 16; nt++)
            #pragma unroll
            for (int j = 0; j < 4; j++) c[mt][nt][j] = 0.0f;

    auto load_chunk = [&](int ck, int s) {
        uint32_t st = sbase + s * STAGE_B;
        int k0 = ck * BK;
        #pragma unroll
        for (int u = tid; u < 512; u += 256) {
            int r = u >> 2, c16 = u & 3;
            uint32_t d = st + r * ROWB + c16 * 16;
            size_t g = (size_t)(m0 + r) * DMODEL + k0 + c16 * 8;
            cp16(d + OFF_AH, Ahi + g);
            cp16(d + OFF_AL, Alo + g);
        }
        #pragma unroll
        for (int u = tid; u < 1024; u += 256) {
            int r = u >> 2, c16 = u & 3;
            uint32_t d = st + r * ROWB + c16 * 16;
            size_t g = (size_t)(n0 + r) * DMODEL + k0 + c16 * 8;
            cp16(d + OFF_BH, Bhi + g);
            cp16(d + OFF_BL, Blo + g);
        }
    };

    load_chunk(0, 0); CP_COMMIT();

    const int a_row  = lane & 15;
    const int a_kb   = ((lane >> 4) & 1) * 16;
    const int b_row  = (lane & 7) + ((lane >> 4) & 1) * 8;
    const int b_kb   = ((lane >> 3) & 1) * 16;

    for (int ck = 0; ck < NCHUNK; ck++) {
        int s = ck & 1;
        if (ck + 1 < NCHUNK) {
            load_chunk(ck + 1, s ^ 1); CP_COMMIT();
            CP_WAIT(1);
        } else {
            CP_WAIT(0);
        }
        __syncthreads();

        uint32_t st = sbase + s * STAGE_B;
        #pragma unroll
        for (int ks = 0; ks < 2; ks++) {
            int kb = ks * 32;
            uint32_t ah[2][4], al[2][4];
            #pragma unroll
            for (int mt = 0; mt < 2; mt++) {
                uint32_t addr = st + (wm + mt * 16 + a_row) * ROWB + kb + a_kb;
                ldsm_x4(ah[mt], addr + OFF_AH);
                ldsm_x4(al[mt], addr + OFF_AL);
            }
            #pragma unroll
            for (int np = 0; np < 8; np++) {
                uint32_t bh4[4], bl4[4];
                uint32_t addr = st + (wn + np * 16 + b_row) * ROWB + kb + b_kb;
                ldsm_x4(bh4, addr + OFF_BH);
                ldsm_x4(bl4, addr + OFF_BL);
                #pragma unroll
                for (int mt = 0; mt < 2; mt++) {
                    mma16816(c[mt][np*2],   ah[mt], bh4);
                    mma16816(c[mt][np*2],   ah[mt], bl4);
                    mma16816(c[mt][np*2],   al[mt], bh4);
                    mma16816(c[mt][np*2+1], ah[mt], bh4 + 2);
                    mma16816(c[mt][np*2+1], ah[mt], bl4 + 2);
                    mma16816(c[mt][np*2+1], al[mt], bh4 + 2);
                }
            }
        }
        __syncthreads();
    }

    const int g  = lane >> 2;
    const int cq = (lane & 3) * 2;
    #pragma unroll
    for (int mt = 0; mt < 2; mt++) {
        #pragma unroll
        for (int nt = 0; nt < 16; nt++) {
            int col = n0 + wn + nt * 8 + cq;
            float2 bv = *(const float2*)(bias + col);
            int r0 = m0 + wm + mt * 16 + g;
            float x0 = c[mt][nt][0] + bv.x, y0 = c[mt][nt][1] + bv.y;
            float x1 = c[mt][nt][2] + bv.x, y1 = c[mt][nt][3] + bv.y;
            if (outf) {
                *(float2*)(outf + (size_t)r0 * DMODEL + col) = make_float2(x0, y0);
                *(float2*)(outf + (size_t)(r0 + 8) * DMODEL + col) = make_float2(x1, y1);
            } else {
                uint32_t h, l;
                size_t idx0 = ((size_t)r0 * DMODEL + col) >> 1;
                size_t idx1 = ((size_t)(r0 + 8) * DMODEL + col) >> 1;
                if (f16mode) {
                    pack_split_f16(x0, y0, h, l);
                    outhi[idx0] = h; outlo[idx0] = l;
                    pack_split_f16(x1, y1, h, l);
                    outhi[idx1] = h; outlo[idx1] = l;
                } else {
                    pack_split(x0 * scale, y0 * scale, h, l);
                    outhi[idx0] = h; outlo[idx0] = l;
                    pack_split(x1 * scale, y1 * scale, h, l);
                    outhi[idx1] = h; outlo[idx1] = l;
                }
            }
        }
    }
}

struct QkvArgs {
    const __nv_bfloat16* ahi[3];
    const __nv_bfloat16* alo[3];
    const __nv_bfloat16* whi[3];
    const __nv_bfloat16* wlo[3];
    const float* bias[3];
    uint32_t* ohi[3];
    uint32_t* olo[3];
    float scale[3];
    int f16mode[3];
};

__global__ __launch_bounds__(256)
void gemm_qkv_kernel(QkvArgs a)
{
    extern __shared__ char smraw[];
    int z = blockIdx.z;
    gemm_body(a.ahi[z], a.alo[z], a.whi[z], a.wlo[z], a.bias[z],
              nullptr, a.ohi[z], a.olo[z], a.scale[z], a.f16mode[z],
              smem_u32(smraw));
}

__global__ __launch_bounds__(256)
void gemm_out_kernel(const __nv_bfloat16* __restrict__ Ahi,
                     const __nv_bfloat16* __restrict__ Alo,
                     const __nv_bfloat16* __restrict__ Bhi,
                     const __nv_bfloat16* __restrict__ Blo,
                     const float* __restrict__ bias, float* __restrict__ outf)
{
    extern __shared__ char smraw[];
    gemm_body(Ahi, Alo, Bhi, Blo, bias, outf, nullptr, nullptr, 1.0f, 0,
              smem_u32(smraw));
}

// ---------------------------------------------------------------------------
// FA2 attention, software-pipelined: QK^T(kt+1) issued before softmax(kt)
// so tensor pipe stays busy through the softmax ALU block.
// QK^T split-bf16 (3 MMAs); PV fp16 x fp16-hi/lo (2 MMAs). 3 KV smem stages.
// ---------------------------------------------------------------------------
#define AROWB 144
#define AQ_B   (128 * AROWB)
#define AKV_B  (64 * AROWB)
#define A_OFF_QH 0
#define A_OFF_QL AQ_B
#define A_STAGE0 (2 * AQ_B)
#define A_STAGE_B (4 * AKV_B)
#define A_OFF_KH 0
#define A_OFF_KL AKV_B
#define A_OFF_VH (2 * AKV_B)
#define A_OFF_VL (3 * AKV_B)
#define ATTN_SMEM (A_STAGE0 + 3 * A_STAGE_B)   // 147456
#define NKT (SEQ / 64)
#define MWORDS (SEQ / 64)

__global__ __launch_bounds__(256, 1)
void attn_mma_kernel(const __nv_bfloat16* __restrict__ qhi,
                     const __nv_bfloat16* __restrict__ qlo,
                     const __nv_bfloat16* __restrict__ khi,
                     const __nv_bfloat16* __restrict__ klo,
                     const __nv_bfloat16* __restrict__ vhi,
                     const __nv_bfloat16* __restrict__ vlo,
                     const unsigned long long* __restrict__ bm,
                     uint32_t* __restrict__ jhi,
                     uint32_t* __restrict__ jlo)
{
    extern __shared__ char smraw[];
    const uint32_t sbase = smem_u32(smraw);
    const int tid  = threadIdx.x;
    const int lane = tid & 31;
    const int wid  = tid >> 5;
    const int wm   = wid * 16;
    const int b    = blockIdx.z;
    const int h    = blockIdx.y;
    const int q0   = blockIdx.x * 128;

    // ---- load Q (group 0) ----
    #pragma unroll
    for (int u = tid; u < 1024; u += 256) {
        int r = u >> 3, c16 = u & 7;
        uint32_t d = sbase + r * AROWB + c16 * 16;
        size_t g = ((size_t)(b * SEQ + q0 + r)) * DMODEL + h * HDIM + c16 * 8;
        cp16(d + A_OFF_QH, qhi + g);
        cp16(d + A_OFF_QL, qlo + g);
    }
    CP_COMMIT();

    auto load_kv = [&](int kt, int s) {
        uint32_t st = sbase + A_STAGE0 + s * A_STAGE_B;
        int k0 = kt * 64;
        #pragma unroll
        for (int u = tid; u < 512; u += 256) {
            int r = u >> 3, c16 = u & 7;
            uint32_t d = st + r * AROWB + c16 * 16;
            size_t g = ((size_t)(b * SEQ + k0 + r)) * DMODEL + h * HDIM + c16 * 8;
            cp16(d + A_OFF_KH, khi + g);
            cp16(d + A_OFF_KL, klo + g);
            cp16(d + A_OFF_VH, vhi + g);
            cp16(d + A_OFF_VL, vlo + g);
        }
    };

    load_kv(0, 0); CP_COMMIT();   // group 1
    load_kv(1, 1); CP_COMMIT();   // group 2

    CP_WAIT(2);                   // Q done
    __syncthreads();

    // ---- preload Q fragments ----
    uint32_t aqh[4][4], aql[4][4];
    {
        const int a_row = lane & 15;
        const int a_kb  = ((lane >> 4) & 1) * 16;
        #pragma unroll
        for (int kc = 0; kc < 4; kc++) {
            uint32_t addr = sbase + (wm + a_row) * AROWB + kc * 32 + a_kb;
            ldsm_x4(aqh[kc], addr + A_OFF_QH);
            ldsm_x4(aql[kc], addr + A_OFF_QL);
        }
    }

    const int g_    = lane >> 2;
    const int cq    = (lane & 3) * 2;
    const int b_row = (lane & 7) + ((lane >> 4) & 1) * 8;
    const int b_kb  = ((lane >> 3) & 1) * 16;
    const int v_row = lane & 15;
    const int v_col = (lane >> 4) * 8;

    const size_t bmrow0 = ((size_t)b * SEQ + q0 + wm + g_) * MWORDS;
    const size_t bmrow1 = bmrow0 + (size_t)8 * MWORDS;

    float o[8][4];
    #pragma unroll
    for (int i = 0; i < 8; i++)
        #pragma unroll
        for (int j = 0; j < 4; j++) o[i][j] = 0.0f;
    float m0r = -INFINITY, m1r = -INFINITY, l0r = 0.0f, l1r = 0.0f;

    // QK^T of tile kt into s[8][4]
    auto qk_tile = [&](int kt, float (*s)[4]) {
        uint32_t st = sbase + A_STAGE0 + (kt % 3) * A_STAGE_B;
        #pragma unroll
        for (int i = 0; i < 8; i++)
            #pragma unroll
            for (int j = 0; j < 4; j++) s[i][j] = 0.0f;
        #pragma unroll
        for (int kc = 0; kc < 4; kc++) {
            #pragma unroll
            for (int np = 0; np < 4; np++) {
                uint32_t bh4[4], bl4[4];
                uint32_t addr = st + (np * 16 + b_row) * AROWB + kc * 32 + b_kb;
                ldsm_x4(bh4, addr + A_OFF_KH);
                ldsm_x4(bl4, addr + A_OFF_KL);
                mma16816(s[np*2],   aqh[kc], bh4);
                mma16816(s[np*2],   aqh[kc], bl4);
                mma16816(s[np*2],   aql[kc], bh4);
                mma16816(s[np*2+1], aqh[kc], bh4 + 2);
                mma16816(s[np*2+1], aqh[kc], bl4 + 2);
                mma16816(s[np*2+1], aql[kc], bh4 + 2);
            }
        }
    };

    float sc[2][8][4];

    CP_WAIT(1);        // kv0 done
    __syncthreads();
    qk_tile(0, sc[0]); // prologue

    #pragma unroll 2
    for (int kt = 0; kt < NKT; kt++) {
        const int cur = kt & 1, nxt = cur ^ 1;

        // guard stage (kt+2)%3 reuse: all warps finished PV(kt-1) reads
        __syncthreads();
        if (kt + 2 < NKT) { load_kv(kt + 2, (kt + 2) % 3); CP_COMMIT(); }
        if (kt + 1 < NKT) {
            if (kt + 2 < NKT) { CP_WAIT(1); } else { CP_WAIT(0); }
            __syncthreads();              // kv(kt+1) visible CTA-wide
            qk_tile(kt + 1, sc[nxt]);     // tensor pipe filled ahead of softmax
        }

        unsigned long long mw0 = __ldg(bm + bmrow0 + kt);
        unsigned long long mw1 = __ldg(bm + bmrow1 + kt);
        float (*s)[4] = sc[cur];

        // ---- mask ----
        #pragma unroll
        for (int nt = 0; nt < 8; nt++) {
            int c0 = nt * 8 + cq;
            if (!((mw0 >> c0) & 1))       s[nt][0] = -1000000000.0f;
            if (!((mw0 >> (c0 + 1)) & 1)) s[nt][1] = -1000000000.0f;
            if (!((mw1 >> c0) & 1))       s[nt][2] = -1000000000.0f;
            if (!((mw1 >> (c0 + 1)) & 1)) s[nt][3] = -1000000000.0f;
        }

        // ---- online softmax (base 2) ----
        float mx0 = s[0][0], mx1 = s[0][2];
        #pragma unroll
        for (int nt = 0; nt < 8; nt++) {
            mx0 = fmaxf(mx0, fmaxf(s[nt][0], s[nt][1]));
            mx1 = fmaxf(mx1, fmaxf(s[nt][2], s[nt][3]));
        }
        mx0 = fmaxf(mx0, __shfl_xor_sync(0xffffffff, mx0, 1));
        mx0 = fmaxf(mx0, __shfl_xor_sync(0xffffffff, mx0, 2));
        mx1 = fmaxf(mx1, __shfl_xor_sync(0xffffffff, mx1, 1));
        mx1 = fmaxf(mx1, __shfl_xor_sync(0xffffffff, mx1, 2));

        float mn0 = fmaxf(m0r, mx0), mn1 = fmaxf(m1r, mx1);
        float al0 = exp2f(m0r - mn0), al1 = exp2f(m1r - mn1);
        m0r = mn0; m1r = mn1;

        float rs0 = 0.0f, rs1 = 0.0f;
        #pragma unroll
        for (int nt = 0; nt < 8; nt++) {
            s[nt][0] = exp2f(s[nt][0] - mn0); rs0 += s[nt][0];
            s[nt][1] = exp2f(s[nt][1] - mn0); rs0 += s[nt][1];
            s[nt][2] = exp2f(s[nt][2] - mn1); rs1 += s[nt][2];
            s[nt][3] = exp2f(s[nt][3] - mn1); rs1 += s[nt][3];
        }
        rs0 += __shfl_xor_sync(0xffffffff, rs0, 1);
        rs0 += __shfl_xor_sync(0xffffffff, rs0, 2);
        rs1 += __shfl_xor_sync(0xffffffff, rs1, 1);
        rs1 += __shfl_xor_sync(0xffffffff, rs1, 2);
        l0r = l0r * al0 + rs0;
        l1r = l1r * al1 + rs1;

        #pragma unroll
        for (int nt = 0; nt < 8; nt++) {
            o[nt][0] *= al0; o[nt][1] *= al0;
            o[nt][2] *= al1; o[nt][3] *= al1;
        }

        // ---- pack P (fp16, no residual) ----
        uint32_t ph[4][4];
        #pragma unroll
        for (int tp = 0; tp < 4; tp++) {
            ph[tp][0] = pack_f16(s[2*tp][0],   s[2*tp][1]);
            ph[tp][1] = pack_f16(s[2*tp][2],   s[2*tp][3]);
            ph[tp][2] = pack_f16(s[2*tp+1][0], s[2*tp+1][1]);
            ph[tp][3] = pack_f16(s[2*tp+1][2], s[2*tp+1][3]);
        }

        // ---- O += P V (stage kt%3) ----
        uint32_t stv = sbase + A_STAGE0 + (kt % 3) * A_STAGE_B;
        #pragma unroll
        for (int nt2 = 0; nt2 < 4; nt2++) {
            #pragma unroll
            for (int tp = 0; tp < 4; tp++) {
                uint32_t vh4[4], vl4[4];
                uint32_t addr = stv + A_OFF_VH + (tp * 16 + v_row) * AROWB
                              + (nt2 * 16 + v_col) * 2;
                ldsm_x4_t(vh4, addr);
                ldsm_x4_t(vl4, addr + (A_OFF_VL - A_OFF_VH));
                mma16816h(o[nt2*2],   ph[tp], vh4);
                mma16816h(o[nt2*2],   ph[tp], vl4);
                mma16816h(o[nt2*2+1], ph[tp], vh4 + 2);
                mma16816h(o[nt2*2+1], ph[tp], vl4 + 2);
            }
        }
    }

    // ---- epilogue ----
    float inv0 = 1.0f / l0r, inv1 = 1.0f / l1r;
    size_t row0 = ((size_t)(b * SEQ + q0 + wm + g_)) * DMODEL + h * HDIM;
    #pragma unroll
    for (int nt = 0; nt < 8; nt++) {
        int col = nt * 8 + cq;
        uint32_t hh, ll;
        pack_split(o[nt][0] * inv0, o[nt][1] * inv0, hh, ll);
        size_t i0 = (row0 + col) >> 1;
        jhi[i0] = hh; jlo[i0] = ll;
        pack_split(o[nt][2] * inv1, o[nt][3] * inv1, hh, ll);
        size_t i1 = (row0 + (size_t)8 * DMODEL + col) >> 1;
        jhi[i1] = hh; jlo[i1] = ll;
    }
}

// ---------------------------------------------------------------------------
extern "C" void kernel_launch(void* const* d_in, const int* in_sizes, int n_in,
                              void* d_out, int out_size)
{
    const float* q    = (const float*)d_in[0];
    const float* k    = (const float*)d_in[1];
    const float* v    = (const float*)d_in[2];
    const int*   mask = (const int*)  d_in[3];
    const float* Wq   = (const float*)d_in[4];
    const float* bq   = (const float*)d_in[5];
    const float* Wk   = (const float*)d_in[6];
    const float* bk   = (const float*)d_in[7];
    const float* Wv   = (const float*)d_in[8];
    const float* bv   = (const float*)d_in[9];
    const float* Wo   = (const float*)d_in[10];
    const float* bo   = (const float*)d_in[11];
    float* out = (float*)d_out;

    void *p_xhi, *p_xlo, *p_whi4, *p_wlo4;
    void *p_qhi, *p_qlo, *p_khi, *p_klo, *p_vhi, *p_vlo, *p_jhi, *p_jlo, *p_bm;
    cudaGetSymbolAddress(&p_xhi, g_xhi);
    cudaGetSymbolAddress(&p_xlo, g_xlo);
    cudaGetSymbolAddress(&p_whi4, g_whi4);
    cudaGetSymbolAddress(&p_wlo4, g_wlo4);
    cudaGetSymbolAddress(&p_qhi, g_qhi);
    cudaGetSymbolAddress(&p_qlo, g_qlo);
    cudaGetSymbolAddress(&p_khi, g_khi);
    cudaGetSymbolAddress(&p_klo, g_klo);
    cudaGetSymbolAddress(&p_vhi, g_vhi);
    cudaGetSymbolAddress(&p_vlo, g_vlo);
    cudaGetSymbolAddress(&p_jhi, g_jhi);
    cudaGetSymbolAddress(&p_jlo, g_jlo);
    cudaGetSymbolAddress(&p_bm, g_maskbits);

    __nv_bfloat16* xhi = (__nv_bfloat16*)p_xhi;
    __nv_bfloat16* xlo = (__nv_bfloat16*)p_xlo;
    __nv_bfloat16* whi = (__nv_bfloat16*)p_whi4;
    __nv_bfloat16* wlo = (__nv_bfloat16*)p_wlo4;

    const size_t XN = (size_t)MTOT * DMODEL;
    const size_t WN = (size_t)DMODEL * DMODEL;

    cudaFuncSetAttribute(gemm_qkv_kernel,
                         cudaFuncAttributeMaxDynamicSharedMemorySize, GEMM_SMEM);
    cudaFuncSetAttribute(gemm_out_kernel,
                         cudaFuncAttributeMaxDynamicSharedMemorySize, GEMM_SMEM);
    cudaFuncSetAttribute(attn_mma_kernel,
                         cudaFuncAttributeMaxDynamicSharedMemorySize, ATTN_SMEM);

    // 1. pack mask
    mask_pack_kernel<<<(BATCH*SEQ*SEQ/64)/256, 256>>>((const int4*)mask,
        (unsigned long long*)p_bm);

    // 2. split all inputs/weights
    SplitAll sa;
    sa.src[0] = (const float4*)q;  sa.src[1] = (const float4*)k;
    sa.src[2] = (const float4*)v;
    sa.src[3] = (const float4*)Wq; sa.src[4] = (const float4*)Wk;
    sa.src[5] = (const float4*)Wv; sa.src[6] = (const float4*)Wo;
    for (int i = 0; i < 3; i++) {
        sa.hi[i] = (uint32_t*)(xhi + i * XN);
        sa.lo[i] = (uint32_t*)(xlo + i * XN);
    }
    for (int i = 0; i < 4; i++) {
        sa.hi[3+i] = (uint32_t*)(whi + i * WN);
        sa.lo[3+i] = (uint32_t*)(wlo + i * WN);
    }
    split_all_kernel<<<SPLIT_BLOCKS, 256>>>(sa);

    // 3. fused QKV projections
    QkvArgs qa;
    qa.ahi[0] = xhi;          qa.alo[0] = xlo;
    qa.ahi[1] = xhi + XN;     qa.alo[1] = xlo + XN;
    qa.ahi[2] = xhi + 2*XN;   qa.alo[2] = xlo + 2*XN;
    qa.whi[0] = whi;          qa.wlo[0] = wlo;
    qa.whi[1] = whi + WN;     qa.wlo[1] = wlo + WN;
    qa.whi[2] = whi + 2*WN;   qa.wlo[2] = wlo + 2*WN;
    qa.bias[0] = bq; qa.bias[1] = bk; qa.bias[2] = bv;
    qa.ohi[0] = (uint32_t*)p_qhi; qa.olo[0] = (uint32_t*)p_qlo;
    qa.ohi[1] = (uint32_t*)p_khi; qa.olo[1] = (uint32_t*)p_klo;
    qa.ohi[2] = (uint32_t*)p_vhi; qa.olo[2] = (uint32_t*)p_vlo;
    qa.scale[0] = 0.125f * LOG2E; qa.scale[1] = 1.0f; qa.scale[2] = 1.0f;
    qa.f16mode[0] = 0; qa.f16mode[1] = 0; qa.f16mode[2] = 1;
    dim3 gq(DMODEL / BN, MTOT / BM, 3);
    gemm_qkv_kernel<<<gq, 256, GEMM_SMEM>>>(qa);

    // 4. attention
    dim3 ag(SEQ / 128, NHEADS, BATCH);
    attn_mma_kernel<<<ag, 256, ATTN_SMEM>>>(
        (const __nv_bfloat16*)p_qhi, (const __nv_bfloat16*)p_qlo,
        (const __nv_bfloat16*)p_khi, (const __nv_bfloat16*)p_klo,
        (const __nv_bfloat16*)p_vhi, (const __nv_bfloat16*)p_vlo,
        (const unsigned long long*)p_bm,
        (uint32_t*)p_jhi, (uint32_t*)p_jlo);

    // 5. output projection
    dim3 gg(DMODEL / BN, MTOT / BM);
    gemm_out_kernel<<<gg, 256, GEMM_SMEM>>>(
        (const __nv_bfloat16*)p_jhi, (const __nv_bfloat16*)p_jlo,
        whi + 3*WN, wlo + 3*WN, bo, out);
}

// round 10
// speedup vs baseline: 1.2894x; 1.0455x over previous
#include <cuda_runtime.h>
#include <cuda_bf16.h>
#include <cuda_fp16.h>
#include <cstdint>
#include <math.h>

#define BATCH 2
#define SEQ   2048
#define DMODEL 1024
#define NHEADS 16
#define HDIM  64
#define MTOT  (BATCH*SEQ)   // 4096
#define LOG2E 1.44269504088896f

// ---------------- scratch (allocation-free rule: device globals) -----------
__device__ __nv_bfloat16 g_xhi[3*MTOT*DMODEL];
__device__ __nv_bfloat16 g_xlo[3*MTOT*DMODEL];
__device__ __nv_bfloat16 g_whi4[4*DMODEL*DMODEL];
__device__ __nv_bfloat16 g_wlo4[4*DMODEL*DMODEL];
__device__ __nv_bfloat16 g_qf16[MTOT*DMODEL];      // fp16 bits (scaled Q)
__device__ __nv_bfloat16 g_khi[MTOT*DMODEL];       // fp16 bits
__device__ __nv_bfloat16 g_klo[MTOT*DMODEL];       // fp16 bits
__device__ __nv_bfloat16 g_vhi[MTOT*DMODEL];       // fp16 bits
__device__ __nv_bfloat16 g_vlo[MTOT*DMODEL];       // fp16 bits
__device__ __nv_bfloat16 g_jhi[MTOT*DMODEL];
__device__ __nv_bfloat16 g_jlo[MTOT*DMODEL];
__device__ unsigned long long g_maskbits[(size_t)BATCH*SEQ*SEQ/64];

// ---------------- helpers ---------------------------------------------------
__device__ __forceinline__ uint32_t smem_u32(const void* p) {
    uint32_t a;
    asm("{ .reg .u64 t; cvta.to.shared.u64 t, %1; cvt.u32.u64 %0, t; }"
        : "=r"(a) : "l"(p));
    return a;
}
__device__ __forceinline__ void cp16(uint32_t s, const void* g) {
    asm volatile("cp.async.cg.shared.global [%0], [%1], 16;" :: "r"(s), "l"(g));
}
#define CP_COMMIT()  asm volatile("cp.async.commit_group;" ::: "memory")
#define CP_WAIT(n)   asm volatile("cp.async.wait_group %0;" :: "n"(n) : "memory")

__device__ __forceinline__ void ldsm_x4(uint32_t* r, uint32_t addr) {
    asm volatile("ldmatrix.sync.aligned.m8n8.x4.shared.b16 {%0,%1,%2,%3}, [%4];"
                 : "=r"(r[0]), "=r"(r[1]), "=r"(r[2]), "=r"(r[3]) : "r"(addr));
}
__device__ __forceinline__ void ldsm_x4_t(uint32_t* r, uint32_t addr) {
    asm volatile("ldmatrix.sync.aligned.m8n8.x4.trans.shared.b16 {%0,%1,%2,%3}, [%4];"
                 : "=r"(r[0]), "=r"(r[1]), "=r"(r[2]), "=r"(r[3]) : "r"(addr));
}
__device__ __forceinline__ void mma16816(float* d, const uint32_t* a,
                                         const uint32_t* b) {
    asm volatile(
        "mma.sync.aligned.m16n8k16.row.col.f32.bf16.bf16.f32 "
        "{%0,%1,%2,%3}, {%4,%5,%6,%7}, {%8,%9}, {%0,%1,%2,%3};"
        : "+f"(d[0]), "+f"(d[1]), "+f"(d[2]), "+f"(d[3])
        : "r"(a[0]), "r"(a[1]), "r"(a[2]), "r"(a[3]), "r"(b[0]), "r"(b[1]));
}
__device__ __forceinline__ void mma16816h(float* d, const uint32_t* a,
                                          const uint32_t* b) {
    asm volatile(
        "mma.sync.aligned.m16n8k16.row.col.f32.f16.f16.f32 "
        "{%0,%1,%2,%3}, {%4,%5,%6,%7}, {%8,%9}, {%0,%1,%2,%3};"
        : "+f"(d[0]), "+f"(d[1]), "+f"(d[2]), "+f"(d[3])
        : "r"(a[0]), "r"(a[1]), "r"(a[2]), "r"(a[3]), "r"(b[0]), "r"(b[1]));
}
__device__ __forceinline__ void pack_split(float x, float y,
                                           uint32_t& hi, uint32_t& lo) {
    uint32_t h;
    asm("cvt.rn.bf16x2.f32 %0, %1, %2;" : "=r"(h) : "f"(y), "f"(x));
    float hx = __uint_as_float(h << 16);
    float hy = __uint_as_float(h & 0xffff0000u);
    float lx = x - hx, ly = y - hy;
    uint32_t l;
    asm("cvt.rn.bf16x2.f32 %0, %1, %2;" : "=r"(l) : "f"(ly), "f"(lx));
    hi = h; lo = l;
}
__device__ __forceinline__ void pack_split_f16(float x, float y,
                                               uint32_t& hi, uint32_t& lo) {
    __half2 h = __floats2half2_rn(x, y);
    float hx = __low2float(h), hy = __high2float(h);
    __half2 l = __floats2half2_rn(x - hx, y - hy);
    hi = *reinterpret_cast<uint32_t*>(&h);
    lo = *reinterpret_cast<uint32_t*>(&l);
}
__device__ __forceinline__ uint32_t pack_f16(float x, float y) {
    __half2 h = __floats2half2_rn(x, y);
    return *reinterpret_cast<uint32_t*>(&h);
}

// ---------------------------------------------------------------------------
// split_all (inputs + weights, bf16 hi/lo)
// ---------------------------------------------------------------------------
struct SplitAll {
    const float4* src[7];
    uint32_t* hi[7];
    uint32_t* lo[7];
};
#define NX_BLK 4096
#define NW_BLK 1024
#define SPLIT_BLOCKS (3*NX_BLK + 4*NW_BLK)

__global__ __launch_bounds__(256)
void split_all_kernel(SplitAll a)
{
    int bid = blockIdx.x;
    int seg, idx;
    if (bid < 3 * NX_BLK) { seg = bid / NX_BLK; idx = (bid % NX_BLK) * 256 + threadIdx.x; }
    else { int r = bid - 3 * NX_BLK; seg = 3 + r / NW_BLK; idx = (r % NW_BLK) * 256 + threadIdx.x; }
    float4 v = a.src[seg][idx];
    uint32_t h0, l0, h1, l1;
    pack_split(v.x, v.y, h0, l0);
    pack_split(v.z, v.w, h1, l1);
    uint32_t* hi = a.hi[seg];
    uint32_t* lo = a.lo[seg];
    hi[2*idx] = h0; hi[2*idx+1] = h1;
    lo[2*idx] = l0; lo[2*idx+1] = l1;
}

// ---------------------------------------------------------------------------
// mask pack
// ---------------------------------------------------------------------------
__global__ __launch_bounds__(256)
void mask_pack_kernel(const int4* __restrict__ mask, unsigned long long* __restrict__ bm)
{
    int i = blockIdx.x * 256 + threadIdx.x;
    const int4* p = mask + (size_t)i * 16;
    unsigned long long w = 0;
    #pragma unroll
    for (int j = 0; j < 16; j++) {
        int4 v = p[j];
        w |= ((unsigned long long)(v.x != 0)) << (j*4);
        w |= ((unsigned long long)(v.y != 0)) << (j*4+1);
        w |= ((unsigned long long)(v.z != 0)) << (j*4+2);
        w |= ((unsigned long long)(v.w != 0)) << (j*4+3);
    }
    bm[i] = w;
}

// ---------------------------------------------------------------------------
// GEMM body (split-bf16 3-MMA, 2-stage cp.async), CTA 128x256.
// omode: 0=fp32 out, 1=f16 split hi/lo, 2=f16 single (scaled), 3=bf16 split
// ---------------------------------------------------------------------------
#define BM 128
#define BN 256
#define BK 32
#define NCHUNK (DMODEL / BK)
#define ROWB 80
#define A_MAT_B (128 * ROWB)
#define B_MAT_B (256 * ROWB)
#define OFF_AH 0
#define OFF_AL A_MAT_B
#define OFF_BH (2 * A_MAT_B)
#define OFF_BL (2 * A_MAT_B + B_MAT_B)
#define STAGE_B (2 * A_MAT_B + 2 * B_MAT_B)
#define GEMM_SMEM (2 * STAGE_B)

__device__ __forceinline__ void gemm_body(
    const __nv_bfloat16* __restrict__ Ahi, const __nv_bfloat16* __restrict__ Alo,
    const __nv_bfloat16* __restrict__ Bhi, const __nv_bfloat16* __restrict__ Blo,
    const float* __restrict__ bias,
    float* __restrict__ outf, uint32_t* __restrict__ outhi,
    uint32_t* __restrict__ outlo, float scale, int omode, uint32_t sbase)
{
    const int tid  = threadIdx.x;
    const int lane = tid & 31;
    const int wid  = tid >> 5;
    const int wm   = (wid & 3) * 32;
    const int wn   = (wid >> 2) * 128;
    const int n0   = blockIdx.x * BN;
    const int m0   = blockIdx.y * BM;

    float c[2][16][4];
    #pragma unroll
    for (int mt = 0; mt < 2; mt++)
        #pragma unroll
        for (int nt = 0; nt < 16; nt++)
            #pragma unroll
            for (int j = 0; j < 4; j++) c[mt][nt][j] = 0.0f;

    auto load_chunk = [&](int ck, int s) {
        uint32_t st = sbase + s * STAGE_B;
        int k0 = ck * BK;
        #pragma unroll
        for (int u = tid; u < 512; u += 256) {
            int r = u >> 2, c16 = u & 3;
            uint32_t d = st + r * ROWB + c16 * 16;
            size_t g = (size_t)(m0 + r) * DMODEL + k0 + c16 * 8;
            cp16(d + OFF_AH, Ahi + g);
            cp16(d + OFF_AL, Alo + g);
        }
        #pragma unroll
        for (int u = tid; u < 1024; u += 256) {
            int r = u >> 2, c16 = u & 3;
            uint32_t d = st + r * ROWB + c16 * 16;
            size_t g = (size_t)(n0 + r) * DMODEL + k0 + c16 * 8;
            cp16(d + OFF_BH, Bhi + g);
            cp16(d + OFF_BL, Blo + g);
        }
    };

    load_chunk(0, 0); CP_COMMIT();

    const int a_row  = lane & 15;
    const int a_kb   = ((lane >> 4) & 1) * 16;
    const int b_row  = (lane & 7) + ((lane >> 4) & 1) * 8;
    const int b_kb   = ((lane >> 3) & 1) * 16;

    for (int ck = 0; ck < NCHUNK; ck++) {
        int s = ck & 1;
        if (ck + 1 < NCHUNK) {
            load_chunk(ck + 1, s ^ 1); CP_COMMIT();
            CP_WAIT(1);
        } else {
            CP_WAIT(0);
        }
        __syncthreads();

        uint32_t st = sbase + s * STAGE_B;
        #pragma unroll
        for (int ks = 0; ks < 2; ks++) {
            int kb = ks * 32;
            uint32_t ah[2][4], al[2][4];
            #pragma unroll
            for (int mt = 0; mt < 2; mt++) {
                uint32_t addr = st + (wm + mt * 16 + a_row) * ROWB + kb + a_kb;
                ldsm_x4(ah[mt], addr + OFF_AH);
                ldsm_x4(al[mt], addr + OFF_AL);
            }
            #pragma unroll
            for (int np = 0; np < 8; np++) {
                uint32_t bh4[4], bl4[4];
                uint32_t addr = st + (wn + np * 16 + b_row) * ROWB + kb + b_kb;
                ldsm_x4(bh4, addr + OFF_BH);
                ldsm_x4(bl4, addr + OFF_BL);
                #pragma unroll
                for (int mt = 0; mt < 2; mt++) {
                    mma16816(c[mt][np*2],   ah[mt], bh4);
                    mma16816(c[mt][np*2],   ah[mt], bl4);
                    mma16816(c[mt][np*2],   al[mt], bh4);
                    mma16816(c[mt][np*2+1], ah[mt], bh4 + 2);
                    mma16816(c[mt][np*2+1], ah[mt], bl4 + 2);
                    mma16816(c[mt][np*2+1], al[mt], bh4 + 2);
                }
            }
        }
        __syncthreads();
    }

    const int g  = lane >> 2;
    const int cq = (lane & 3) * 2;
    #pragma unroll
    for (int mt = 0; mt < 2; mt++) {
        #pragma unroll
        for (int nt = 0; nt < 16; nt++) {
            int col = n0 + wn + nt * 8 + cq;
            float2 bv = *(const float2*)(bias + col);
            int r0 = m0 + wm + mt * 16 + g;
            float x0 = c[mt][nt][0] + bv.x, y0 = c[mt][nt][1] + bv.y;
            float x1 = c[mt][nt][2] + bv.x, y1 = c[mt][nt][3] + bv.y;
            size_t idx0 = ((size_t)r0 * DMODEL + col) >> 1;
            size_t idx1 = ((size_t)(r0 + 8) * DMODEL + col) >> 1;
            if (omode == 0) {
                *(float2*)(outf + (size_t)r0 * DMODEL + col) = make_float2(x0, y0);
                *(float2*)(outf + (size_t)(r0 + 8) * DMODEL + col) = make_float2(x1, y1);
            } else if (omode == 1) {
                uint32_t h, l;
                pack_split_f16(x0, y0, h, l);
                outhi[idx0] = h; outlo[idx0] = l;
                pack_split_f16(x1, y1, h, l);
                outhi[idx1] = h; outlo[idx1] = l;
            } else if (omode == 2) {
                outhi[idx0] = pack_f16(x0 * scale, y0 * scale);
                outhi[idx1] = pack_f16(x1 * scale, y1 * scale);
            } else {
                uint32_t h, l;
                pack_split(x0 * scale, y0 * scale, h, l);
                outhi[idx0] = h; outlo[idx0] = l;
                pack_split(x1 * scale, y1 * scale, h, l);
                outhi[idx1] = h; outlo[idx1] = l;
            }
        }
    }
}

struct QkvArgs {
    const __nv_bfloat16* ahi[3];
    const __nv_bfloat16* alo[3];
    const __nv_bfloat16* whi[3];
    const __nv_bfloat16* wlo[3];
    const float* bias[3];
    uint32_t* ohi[3];
    uint32_t* olo[3];
    float scale[3];
    int omode[3];
};

__global__ __launch_bounds__(256)
void gemm_qkv_kernel(QkvArgs a)
{
    extern __shared__ char smraw[];
    int z = blockIdx.z;
    gemm_body(a.ahi[z], a.alo[z], a.whi[z], a.wlo[z], a.bias[z],
              nullptr, a.ohi[z], a.olo[z], a.scale[z], a.omode[z],
              smem_u32(smraw));
}

__global__ __launch_bounds__(256)
void gemm_out_kernel(const __nv_bfloat16* __restrict__ Ahi,
                     const __nv_bfloat16* __restrict__ Alo,
                     const __nv_bfloat16* __restrict__ Bhi,
                     const __nv_bfloat16* __restrict__ Blo,
                     const float* __restrict__ bias, float* __restrict__ outf)
{
    extern __shared__ char smraw[];
    gemm_body(Ahi, Alo, Bhi, Blo, bias, outf, nullptr, nullptr, 1.0f, 0,
              smem_u32(smraw));
}

// ---------------------------------------------------------------------------
// FA2 attention: QK^T = Q_f16 x (K_hi + K_lo)_f16 (2 MMAs);
// PV = P_f16 x (V_hi + V_lo)_f16 (2 MMAs). Pipelined QK(kt+1) before
// softmax(kt). 3 KV smem stages, bitmask mask, base-2 softmax.
// ---------------------------------------------------------------------------
#define AROWB 144
#define AQ_B   (128 * AROWB)
#define A_STAGE0 AQ_B              // only Q f16 (single buffer)
#define AKV_B  (64 * AROWB)
#define A_STAGE_B (4 * AKV_B)
#define A_OFF_KH 0
#define A_OFF_KL AKV_B
#define A_OFF_VH (2 * AKV_B)
#define A_OFF_VL (3 * AKV_B)
#define ATTN_SMEM (A_STAGE0 + 3 * A_STAGE_B)   // 18432 + 110592 = 129024
#define NKT (SEQ / 64)
#define MWORDS (SEQ / 64)

__global__ __launch_bounds__(256, 1)
void attn_mma_kernel(const __nv_bfloat16* __restrict__ qf16,
                     const __nv_bfloat16* __restrict__ khi,
                     const __nv_bfloat16* __restrict__ klo,
                     const __nv_bfloat16* __restrict__ vhi,
                     const __nv_bfloat16* __restrict__ vlo,
                     const unsigned long long* __restrict__ bm,
                     uint32_t* __restrict__ jhi,
                     uint32_t* __restrict__ jlo)
{
    extern __shared__ char smraw[];
    const uint32_t sbase = smem_u32(smraw);
    const int tid  = threadIdx.x;
    const int lane = tid & 31;
    const int wid  = tid >> 5;
    const int wm   = wid * 16;
    const int b    = blockIdx.z;
    const int h    = blockIdx.y;
    const int q0   = blockIdx.x * 128;

    // ---- load Q tile (f16 single) ----
    #pragma unroll
    for (int u = tid; u < 1024; u += 512) {
        int r = u >> 3, c16 = u & 7;
        uint32_t d = sbase + r * AROWB + c16 * 16;
        size_t g = ((size_t)(b * SEQ + q0 + r)) * DMODEL + h * HDIM + c16 * 8;
        cp16(d, qf16 + g);
        int u2 = u + 256;
        int r2 = u2 >> 3, c2 = u2 & 7;
        uint32_t d2 = sbase + r2 * AROWB + c2 * 16;
        size_t g2 = ((size_t)(b * SEQ + q0 + r2)) * DMODEL + h * HDIM + c2 * 8;
        cp16(d2, qf16 + g2);
    }
    CP_COMMIT();

    auto load_kv = [&](int kt, int s) {
        uint32_t st = sbase + A_STAGE0 + s * A_STAGE_B;
        int k0 = kt * 64;
        #pragma unroll
        for (int u = tid; u < 512; u += 256) {
            int r = u >> 3, c16 = u & 7;
            uint32_t d = st + r * AROWB + c16 * 16;
            size_t g = ((size_t)(b * SEQ + k0 + r)) * DMODEL + h * HDIM + c16 * 8;
            cp16(d + A_OFF_KH, khi + g);
            cp16(d + A_OFF_KL, klo + g);
            cp16(d + A_OFF_VH, vhi + g);
            cp16(d + A_OFF_VL, vlo + g);
        }
    };

    load_kv(0, 0); CP_COMMIT();
    load_kv(1, 1); CP_COMMIT();

    CP_WAIT(2);
    __syncthreads();

    // ---- preload Q fragments (f16, 4 k-chunks) ----
    uint32_t aq[4][4];
    {
        const int a_row = lane & 15;
        const int a_kb  = ((lane >> 4) & 1) * 16;
        #pragma unroll
        for (int kc = 0; kc < 4; kc++) {
            uint32_t addr = sbase + (wm + a_row) * AROWB + kc * 32 + a_kb;
            ldsm_x4(aq[kc], addr);
        }
    }

    const int g_    = lane >> 2;
    const int cq    = (lane & 3) * 2;
    const int b_row = (lane & 7) + ((lane >> 4) & 1) * 8;
    const int b_kb  = ((lane >> 3) & 1) * 16;
    const int v_row = lane & 15;
    const int v_col = (lane >> 4) * 8;

    const size_t bmrow0 = ((size_t)b * SEQ + q0 + wm + g_) * MWORDS;
    const size_t bmrow1 = bmrow0 + (size_t)8 * MWORDS;

    float o[8][4];
    #pragma unroll
    for (int i = 0; i < 8; i++)
        #pragma unroll
        for (int j = 0; j < 4; j++) o[i][j] = 0.0f;
    float m0r = -INFINITY, m1r = -INFINITY, l0r = 0.0f, l1r = 0.0f;

    // QK^T of tile kt into s[8][4] (2 f16 MMAs per fragment pair)
    auto qk_tile = [&](int kt, float (*s)[4]) {
        uint32_t st = sbase + A_STAGE0 + (kt % 3) * A_STAGE_B;
        #pragma unroll
        for (int i = 0; i < 8; i++)
            #pragma unroll
            for (int j = 0; j < 4; j++) s[i][j] = 0.0f;
        #pragma unroll
        for (int kc = 0; kc < 4; kc++) {
            #pragma unroll
            for (int np = 0; np < 4; np++) {
                uint32_t kh4[4], kl4[4];
                uint32_t addr = st + (np * 16 + b_row) * AROWB + kc * 32 + b_kb;
                ldsm_x4(kh4, addr + A_OFF_KH);
                ldsm_x4(kl4, addr + A_OFF_KL);
                mma16816h(s[np*2],   aq[kc], kh4);
                mma16816h(s[np*2],   aq[kc], kl4);
                mma16816h(s[np*2+1], aq[kc], kh4 + 2);
                mma16816h(s[np*2+1], aq[kc], kl4 + 2);
            }
        }
    };

    float sc[2][8][4];

    CP_WAIT(1);
    __syncthreads();
    qk_tile(0, sc[0]);

    #pragma unroll 2
    for (int kt = 0; kt < NKT; kt++) {
        const int cur = kt & 1, nxt = cur ^ 1;

        __syncthreads();
        if (kt + 2 < NKT) { load_kv(kt + 2, (kt + 2) % 3); CP_COMMIT(); }
        if (kt + 1 < NKT) {
            if (kt + 2 < NKT) { CP_WAIT(1); } else { CP_WAIT(0); }
            __syncthreads();
            qk_tile(kt + 1, sc[nxt]);
        }

        unsigned long long mw0 = __ldg(bm + bmrow0 + kt);
        unsigned long long mw1 = __ldg(bm + bmrow1 + kt);
        float (*s)[4] = sc[cur];

        // ---- mask ----
        #pragma unroll
        for (int nt = 0; nt < 8; nt++) {
            int c0 = nt * 8 + cq;
            if (!((mw0 >> c0) & 1))       s[nt][0] = -1000000000.0f;
            if (!((mw0 >> (c0 + 1)) & 1)) s[nt][1] = -1000000000.0f;
            if (!((mw1 >> c0) & 1))       s[nt][2] = -1000000000.0f;
            if (!((mw1 >> (c0 + 1)) & 1)) s[nt][3] = -1000000000.0f;
        }

        // ---- online softmax (base 2) ----
        float mx0 = s[0][0], mx1 = s[0][2];
        #pragma unroll
        for (int nt = 0; nt < 8; nt++) {
            mx0 = fmaxf(mx0, fmaxf(s[nt][0], s[nt][1]));
            mx1 = fmaxf(mx1, fmaxf(s[nt][2], s[nt][3]));
        }
        mx0 = fmaxf(mx0, __shfl_xor_sync(0xffffffff, mx0, 1));
        mx0 = fmaxf(mx0, __shfl_xor_sync(0xffffffff, mx0, 2));
        mx1 = fmaxf(mx1, __shfl_xor_sync(0xffffffff, mx1, 1));
        mx1 = fmaxf(mx1, __shfl_xor_sync(0xffffffff, mx1, 2));

        float mn0 = fmaxf(m0r, mx0), mn1 = fmaxf(m1r, mx1);
        float al0 = exp2f(m0r - mn0), al1 = exp2f(m1r - mn1);
        m0r = mn0; m1r = mn1;

        float rs0 = 0.0f, rs1 = 0.0f;
        #pragma unroll
        for (int nt = 0; nt < 8; nt++) {
            s[nt][0] = exp2f(s[nt][0] - mn0); rs0 += s[nt][0];
            s[nt][1] = exp2f(s[nt][1] - mn0); rs0 += s[nt][1];
            s[nt][2] = exp2f(s[nt][2] - mn1); rs1 += s[nt][2];
            s[nt][3] = exp2f(s[nt][3] - mn1); rs1 += s[nt][3];
        }
        rs0 += __shfl_xor_sync(0xffffffff, rs0, 1);
        rs0 += __shfl_xor_sync(0xffffffff, rs0, 2);
        rs1 += __shfl_xor_sync(0xffffffff, rs1, 1);
        rs1 += __shfl_xor_sync(0xffffffff, rs1, 2);
        l0r = l0r * al0 + rs0;
        l1r = l1r * al1 + rs1;

        #pragma unroll
        for (int nt = 0; nt < 8; nt++) {
            o[nt][0] *= al0; o[nt][1] *= al0;
            o[nt][2] *= al1; o[nt][3] *= al1;
        }

        // ---- pack P (fp16) ----
        uint32_t ph[4][4];
        #pragma unroll
        for (int tp = 0; tp < 4; tp++) {
            ph[tp][0] = pack_f16(s[2*tp][0],   s[2*tp][1]);
            ph[tp][1] = pack_f16(s[2*tp][2],   s[2*tp][3]);
            ph[tp][2] = pack_f16(s[2*tp+1][0], s[2*tp+1][1]);
            ph[tp][3] = pack_f16(s[2*tp+1][2], s[2*tp+1][3]);
        }

        // ---- O += P V ----
        uint32_t stv = sbase + A_STAGE0 + (kt % 3) * A_STAGE_B;
        #pragma unroll
        for (int nt2 = 0; nt2 < 4; nt2++) {
            #pragma unroll
            for (int tp = 0; tp < 4; tp++) {
                uint32_t vh4[4], vl4[4];
                uint32_t addr = stv + A_OFF_VH + (tp * 16 + v_row) * AROWB
                              + (nt2 * 16 + v_col) * 2;
                ldsm_x4_t(vh4, addr);
                ldsm_x4_t(vl4, addr + (A_OFF_VL - A_OFF_VH));
                mma16816h(o[nt2*2],   ph[tp], vh4);
                mma16816h(o[nt2*2],   ph[tp], vl4);
                mma16816h(o[nt2*2+1], ph[tp], vh4 + 2);
                mma16816h(o[nt2*2+1], ph[tp], vl4 + 2);
            }
        }
    }

    // ---- epilogue ----
    float inv0 = 1.0f / l0r, inv1 = 1.0f / l1r;
    size_t row0 = ((size_t)(b * SEQ + q0 + wm + g_)) * DMODEL + h * HDIM;
    #pragma unroll
    for (int nt = 0; nt < 8; nt++) {
        int col = nt * 8 + cq;
        uint32_t hh, ll;
        pack_split(o[nt][0] * inv0, o[nt][1] * inv0, hh, ll);
        size_t i0 = (row0 + col) >> 1;
        jhi[i0] = hh; jlo[i0] = ll;
        pack_split(o[nt][2] * inv1, o[nt][3] * inv1, hh, ll);
        size_t i1 = (row0 + (size_t)8 * DMODEL + col) >> 1;
        jhi[i1] = hh; jlo[i1] = ll;
    }
}

// ---------------------------------------------------------------------------
extern "C" void kernel_launch(void* const* d_in, const int* in_sizes, int n_in,
                              void* d_out, int out_size)
{
    const float* q    = (const float*)d_in[0];
    const float* k    = (const float*)d_in[1];
    const float* v    = (const float*)d_in[2];
    const int*   mask = (const int*)  d_in[3];
    const float* Wq   = (const float*)d_in[4];
    const float* bq   = (const float*)d_in[5];
    const float* Wk   = (const float*)d_in[6];
    const float* bk   = (const float*)d_in[7];
    const float* Wv   = (const float*)d_in[8];
    const float* bv   = (const float*)d_in[9];
    const float* Wo   = (const float*)d_in[10];
    const float* bo   = (const float*)d_in[11];
    float* out = (float*)d_out;

    void *p_xhi, *p_xlo, *p_whi4, *p_wlo4;
    void *p_qf16, *p_khi, *p_klo, *p_vhi, *p_vlo, *p_jhi, *p_jlo, *p_bm;
    cudaGetSymbolAddress(&p_xhi, g_xhi);
    cudaGetSymbolAddress(&p_xlo, g_xlo);
    cudaGetSymbolAddress(&p_whi4, g_whi4);
    cudaGetSymbolAddress(&p_wlo4, g_wlo4);
    cudaGetSymbolAddress(&p_qf16, g_qf16);
    cudaGetSymbolAddress(&p_khi, g_khi);
    cudaGetSymbolAddress(&p_klo, g_klo);
    cudaGetSymbolAddress(&p_vhi, g_vhi);
    cudaGetSymbolAddress(&p_vlo, g_vlo);
    cudaGetSymbolAddress(&p_jhi, g_jhi);
    cudaGetSymbolAddress(&p_jlo, g_jlo);
    cudaGetSymbolAddress(&p_bm, g_maskbits);

    __nv_bfloat16* xhi = (__nv_bfloat16*)p_xhi;
    __nv_bfloat16* xlo = (__nv_bfloat16*)p_xlo;
    __nv_bfloat16* whi = (__nv_bfloat16*)p_whi4;
    __nv_bfloat16* wlo = (__nv_bfloat16*)p_wlo4;

    const size_t XN = (size_t)MTOT * DMODEL;
    const size_t WN = (size_t)DMODEL * DMODEL;

    cudaFuncSetAttribute(gemm_qkv_kernel,
                         cudaFuncAttributeMaxDynamicSharedMemorySize, GEMM_SMEM);
    cudaFuncSetAttribute(gemm_out_kernel,
                         cudaFuncAttributeMaxDynamicSharedMemorySize, GEMM_SMEM);
    cudaFuncSetAttribute(attn_mma_kernel,
                         cudaFuncAttributeMaxDynamicSharedMemorySize, ATTN_SMEM);

    // 1. pack mask
    mask_pack_kernel<<<(BATCH*SEQ*SEQ/64)/256, 256>>>((const int4*)mask,
        (unsigned long long*)p_bm);

    // 2. split all inputs/weights
    SplitAll sa;
    sa.src[0] = (const float4*)q;  sa.src[1] = (const float4*)k;
    sa.src[2] = (const float4*)v;
    sa.src[3] = (const float4*)Wq; sa.src[4] = (const float4*)Wk;
    sa.src[5] = (const float4*)Wv; sa.src[6] = (const float4*)Wo;
    for (int i = 0; i < 3; i++) {
        sa.hi[i] = (uint32_t*)(xhi + i * XN);
        sa.lo[i] = (uint32_t*)(xlo + i * XN);
    }
    for (int i = 0; i < 4; i++) {
        sa.hi[3+i] = (uint32_t*)(whi + i * WN);
        sa.lo[3+i] = (uint32_t*)(wlo + i * WN);
    }
    split_all_kernel<<<SPLIT_BLOCKS, 256>>>(sa);

    // 3. fused QKV projections
    //    Q -> f16 single, scaled by log2e/8 (omode 2)
    //    K -> f16 hi/lo (omode 1), V -> f16 hi/lo (omode 1)
    QkvArgs qa;
    qa.ahi[0] = xhi;          qa.alo[0] = xlo;
    qa.ahi[1] = xhi + XN;     qa.alo[1] = xlo + XN;
    qa.ahi[2] = xhi + 2*XN;   qa.alo[2] = xlo + 2*XN;
    qa.whi[0] = whi;          qa.wlo[0] = wlo;
    qa.whi[1] = whi + WN;     qa.wlo[1] = wlo + WN;
    qa.whi[2] = whi + 2*WN;   qa.wlo[2] = wlo + 2*WN;
    qa.bias[0] = bq; qa.bias[1] = bk; qa.bias[2] = bv;
    qa.ohi[0] = (uint32_t*)p_qf16; qa.olo[0] = (uint32_t*)p_qf16; // lo unused
    qa.ohi[1] = (uint32_t*)p_khi;  qa.olo[1] = (uint32_t*)p_klo;
    qa.ohi[2] = (uint32_t*)p_vhi;  qa.olo[2] = (uint32_t*)p_vlo;
    qa.scale[0] = 0.125f * LOG2E; qa.scale[1] = 1.0f; qa.scale[2] = 1.0f;
    qa.omode[0] = 2; qa.omode[1] = 1; qa.omode[2] = 1;
    dim3 gq(DMODEL / BN, MTOT / BM, 3);
    gemm_qkv_kernel<<<gq, 256, GEMM_SMEM>>>(qa);

    // 4. attention
    dim3 ag(SEQ / 128, NHEADS, BATCH);
    attn_mma_kernel<<<ag, 256, ATTN_SMEM>>>(
        (const __nv_bfloat16*)p_qf16,
        (const __nv_bfloat16*)p_khi, (const __nv_bfloat16*)p_klo,
        (const __nv_bfloat16*)p_vhi, (const __nv_bfloat16*)p_vlo,
        (const unsigned long long*)p_bm,
        (uint32_t*)p_jhi, (uint32_t*)p_jlo);

    // 5. output projection
    dim3 gg(DMODEL / BN, MTOT / BM);
    gemm_out_kernel<<<gg, 256, GEMM_SMEM>>>(
        (const __nv_bfloat16*)p_jhi, (const __nv_bfloat16*)p_jlo,
        whi + 3*WN, wlo + 3*WN, bo, out);
}

// round 11
// speedup vs baseline: 1.6081x; 1.2472x over previous
#include <cuda_runtime.h>
#include <cuda_bf16.h>
#include <cuda_fp16.h>
#include <cstdint>
#include <math.h>

#define BATCH 2
#define SEQ   2048
#define DMODEL 1024
#define NHEADS 16
#define HDIM  64
#define MTOT  (BATCH*SEQ)   // 4096
#define LOG2E 1.44269504088896f

// ---------------- scratch (allocation-free rule: device globals) -----------
__device__ __nv_bfloat16 g_xf16[3*MTOT*DMODEL];    // fp16 bits: q,k,v inputs
__device__ __nv_bfloat16 g_whi4[4*DMODEL*DMODEL];  // fp16 hi: Wq,Wk,Wv,Wo
__device__ __nv_bfloat16 g_wlo4[4*DMODEL*DMODEL];  // fp16 lo
__device__ __nv_bfloat16 g_qf16[MTOT*DMODEL];      // fp16 (scaled Q)
__device__ __nv_bfloat16 g_kf16[MTOT*DMODEL];      // fp16 K
__device__ __nv_bfloat16 g_vhi[MTOT*DMODEL];       // fp16 V hi
__device__ __nv_bfloat16 g_vlo[MTOT*DMODEL];       // fp16 V lo
__device__ __nv_bfloat16 g_jf16[MTOT*DMODEL];      // fp16 joint
__device__ unsigned long long g_maskbits[(size_t)BATCH*SEQ*SEQ/64];

// ---------------- helpers ---------------------------------------------------
__device__ __forceinline__ uint32_t smem_u32(const void* p) {
    uint32_t a;
    asm("{ .reg .u64 t; cvta.to.shared.u64 t, %1; cvt.u32.u64 %0, t; }"
        : "=r"(a) : "l"(p));
    return a;
}
__device__ __forceinline__ void cp16(uint32_t s, const void* g) {
    asm volatile("cp.async.cg.shared.global [%0], [%1], 16;" :: "r"(s), "l"(g));
}
#define CP_COMMIT()  asm volatile("cp.async.commit_group;" ::: "memory")
#define CP_WAIT(n)   asm volatile("cp.async.wait_group %0;" :: "n"(n) : "memory")

__device__ __forceinline__ void ldsm_x4(uint32_t* r, uint32_t addr) {
    asm volatile("ldmatrix.sync.aligned.m8n8.x4.shared.b16 {%0,%1,%2,%3}, [%4];"
                 : "=r"(r[0]), "=r"(r[1]), "=r"(r[2]), "=r"(r[3]) : "r"(addr));
}
__device__ __forceinline__ void ldsm_x4_t(uint32_t* r, uint32_t addr) {
    asm volatile("ldmatrix.sync.aligned.m8n8.x4.trans.shared.b16 {%0,%1,%2,%3}, [%4];"
                 : "=r"(r[0]), "=r"(r[1]), "=r"(r[2]), "=r"(r[3]) : "r"(addr));
}
__device__ __forceinline__ void mma16816h(float* d, const uint32_t* a,
                                          const uint32_t* b) {
    asm volatile(
        "mma.sync.aligned.m16n8k16.row.col.f32.f16.f16.f32 "
        "{%0,%1,%2,%3}, {%4,%5,%6,%7}, {%8,%9}, {%0,%1,%2,%3};"
        : "+f"(d[0]), "+f"(d[1]), "+f"(d[2]), "+f"(d[3])
        : "r"(a[0]), "r"(a[1]), "r"(a[2]), "r"(a[3]), "r"(b[0]), "r"(b[1]));
}
__device__ __forceinline__ void pack_split_f16(float x, float y,
                                               uint32_t& hi, uint32_t& lo) {
    __half2 h = __floats2half2_rn(x, y);
    float hx = __low2float(h), hy = __high2float(h);
    __half2 l = __floats2half2_rn(x - hx, y - hy);
    hi = *reinterpret_cast<uint32_t*>(&h);
    lo = *reinterpret_cast<uint32_t*>(&l);
}
__device__ __forceinline__ uint32_t pack_f16(float x, float y) {
    __half2 h = __floats2half2_rn(x, y);
    return *reinterpret_cast<uint32_t*>(&h);
}

// ---------------------------------------------------------------------------
// split_all: q,k,v -> fp16 single; 4 weights -> fp16 hi/lo
// ---------------------------------------------------------------------------
struct SplitAll {
    const float4* src[7];
    uint32_t* hi[7];
    uint32_t* lo[7];
};
#define NX_BLK 4096
#define NW_BLK 1024
#define SPLIT_BLOCKS (3*NX_BLK + 4*NW_BLK)

__global__ __launch_bounds__(256)
void split_all_kernel(SplitAll a)
{
    int bid = blockIdx.x;
    int seg, idx;
    if (bid < 3 * NX_BLK) { seg = bid / NX_BLK; idx = (bid % NX_BLK) * 256 + threadIdx.x; }
    else { int r = bid - 3 * NX_BLK; seg = 3 + r / NW_BLK; idx = (r % NW_BLK) * 256 + threadIdx.x; }
    float4 v = a.src[seg][idx];
    uint32_t* hi = a.hi[seg];
    if (seg < 3) {
        hi[2*idx]   = pack_f16(v.x, v.y);
        hi[2*idx+1] = pack_f16(v.z, v.w);
    } else {
        uint32_t h0, l0, h1, l1;
        pack_split_f16(v.x, v.y, h0, l0);
        pack_split_f16(v.z, v.w, h1, l1);
        uint32_t* lo = a.lo[seg];
        hi[2*idx] = h0; hi[2*idx+1] = h1;
        lo[2*idx] = l0; lo[2*idx+1] = l1;
    }
}

// ---------------------------------------------------------------------------
// mask pack
// ---------------------------------------------------------------------------
__global__ __launch_bounds__(256)
void mask_pack_kernel(const int4* __restrict__ mask, unsigned long long* __restrict__ bm)
{
    int i = blockIdx.x * 256 + threadIdx.x;
    const int4* p = mask + (size_t)i * 16;
    unsigned long long w = 0;
    #pragma unroll
    for (int j = 0; j < 16; j++) {
        int4 v = p[j];
        w |= ((unsigned long long)(v.x != 0)) << (j*4);
        w |= ((unsigned long long)(v.y != 0)) << (j*4+1);
        w |= ((unsigned long long)(v.z != 0)) << (j*4+2);
        w |= ((unsigned long long)(v.w != 0)) << (j*4+3);
    }
    bm[i] = w;
}

// ---------------------------------------------------------------------------
// GEMM body: A fp16 single x W fp16 hi/lo -> 2 MMAs. 2-stage cp.async.
// CTA 128x256; 8 warps (4m x 2n).
// omode: 0=fp32 out, 1=f16 hi/lo out, 2=f16 single out (scaled)
// ---------------------------------------------------------------------------
#define BM 128
#define BN 256
#define BK 32
#define NCHUNK (DMODEL / BK)
#define ROWB 80
#define A_MAT_B (128 * ROWB)        // 10240
#define B_MAT_B (256 * ROWB)        // 20480
#define OFF_A  0
#define OFF_BH A_MAT_B
#define OFF_BL (A_MAT_B + B_MAT_B)
#define STAGE_B (A_MAT_B + 2 * B_MAT_B)   // 51200
#define GEMM_SMEM (2 * STAGE_B)           // 102400

__device__ __forceinline__ void gemm_body(
    const __nv_bfloat16* __restrict__ Af,
    const __nv_bfloat16* __restrict__ Whi, const __nv_bfloat16* __restrict__ Wlo,
    const float* __restrict__ bias,
    float* __restrict__ outf, uint32_t* __restrict__ outhi,
    uint32_t* __restrict__ outlo, float scale, int omode, uint32_t sbase)
{
    const int tid  = threadIdx.x;
    const int lane = tid & 31;
    const int wid  = tid >> 5;
    const int wm   = (wid & 3) * 32;
    const int wn   = (wid >> 2) * 128;
    const int n0   = blockIdx.x * BN;
    const int m0   = blockIdx.y * BM;

    float c[2][16][4];
    #pragma unroll
    for (int mt = 0; mt < 2; mt++)
        #pragma unroll
        for (int nt = 0; nt < 16; nt++)
            #pragma unroll
            for (int j = 0; j < 4; j++) c[mt][nt][j] = 0.0f;

    auto load_chunk = [&](int ck, int s) {
        uint32_t st = sbase + s * STAGE_B;
        int k0 = ck * BK;
        #pragma unroll
        for (int u = tid; u < 512; u += 256) {       // A: 128 x 32 f16
            int r = u >> 2, c16 = u & 3;
            uint32_t d = st + r * ROWB + c16 * 16;
            size_t g = (size_t)(m0 + r) * DMODEL + k0 + c16 * 8;
            cp16(d + OFF_A, Af + g);
        }
        #pragma unroll
        for (int u = tid; u < 1024; u += 256) {      // W: 256 x 32 hi/lo
            int r = u >> 2, c16 = u & 3;
            uint32_t d = st + r * ROWB + c16 * 16;
            size_t g = (size_t)(n0 + r) * DMODEL + k0 + c16 * 8;
            cp16(d + OFF_BH, Whi + g);
            cp16(d + OFF_BL, Wlo + g);
        }
    };

    load_chunk(0, 0); CP_COMMIT();

    const int a_row  = lane & 15;
    const int a_kb   = ((lane >> 4) & 1) * 16;
    const int b_row  = (lane & 7) + ((lane >> 4) & 1) * 8;
    const int b_kb   = ((lane >> 3) & 1) * 16;

    for (int ck = 0; ck < NCHUNK; ck++) {
        int s = ck & 1;
        if (ck + 1 < NCHUNK) {
            load_chunk(ck + 1, s ^ 1); CP_COMMIT();
            CP_WAIT(1);
        } else {
            CP_WAIT(0);
        }
        __syncthreads();

        uint32_t st = sbase + s * STAGE_B;
        #pragma unroll
        for (int ks = 0; ks < 2; ks++) {
            int kb = ks * 32;
            uint32_t ah[2][4];
            #pragma unroll
            for (int mt = 0; mt < 2; mt++) {
                uint32_t addr = st + OFF_A + (wm + mt * 16 + a_row) * ROWB + kb + a_kb;
                ldsm_x4(ah[mt], addr);
            }
            #pragma unroll
            for (int np = 0; np < 8; np++) {
                uint32_t bh4[4], bl4[4];
                uint32_t addr = st + (wn + np * 16 + b_row) * ROWB + kb + b_kb;
                ldsm_x4(bh4, addr + OFF_BH);
                ldsm_x4(bl4, addr + OFF_BL);
                #pragma unroll
                for (int mt = 0; mt < 2; mt++) {
                    mma16816h(c[mt][np*2],   ah[mt], bh4);
                    mma16816h(c[mt][np*2],   ah[mt], bl4);
                    mma16816h(c[mt][np*2+1], ah[mt], bh4 + 2);
                    mma16816h(c[mt][np*2+1], ah[mt], bl4 + 2);
                }
            }
        }
        __syncthreads();
    }

    const int g  = lane >> 2;
    const int cq = (lane & 3) * 2;
    #pragma unroll
    for (int mt = 0; mt < 2; mt++) {
        #pragma unroll
        for (int nt = 0; nt < 16; nt++) {
            int col = n0 + wn + nt * 8 + cq;
            float2 bv = *(const float2*)(bias + col);
            int r0 = m0 + wm + mt * 16 + g;
            float x0 = c[mt][nt][0] + bv.x, y0 = c[mt][nt][1] + bv.y;
            float x1 = c[mt][nt][2] + bv.x, y1 = c[mt][nt][3] + bv.y;
            size_t idx0 = ((size_t)r0 * DMODEL + col) >> 1;
            size_t idx1 = ((size_t)(r0 + 8) * DMODEL + col) >> 1;
            if (omode == 0) {
                *(float2*)(outf + (size_t)r0 * DMODEL + col) = make_float2(x0, y0);
                *(float2*)(outf + (size_t)(r0 + 8) * DMODEL + col) = make_float2(x1, y1);
            } else if (omode == 1) {
                uint32_t h, l;
                pack_split_f16(x0, y0, h, l);
                outhi[idx0] = h; outlo[idx0] = l;
                pack_split_f16(x1, y1, h, l);
                outhi[idx1] = h; outlo[idx1] = l;
            } else {
                outhi[idx0] = pack_f16(x0 * scale, y0 * scale);
                outhi[idx1] = pack_f16(x1 * scale, y1 * scale);
            }
        }
    }
}

struct QkvArgs {
    const __nv_bfloat16* a[3];
    const __nv_bfloat16* whi[3];
    const __nv_bfloat16* wlo[3];
    const float* bias[3];
    uint32_t* ohi[3];
    uint32_t* olo[3];
    float scale[3];
    int omode[3];
};

__global__ __launch_bounds__(256)
void gemm_qkv_kernel(QkvArgs a)
{
    extern __shared__ char smraw[];
    int z = blockIdx.z;
    gemm_body(a.a[z], a.whi[z], a.wlo[z], a.bias[z],
              nullptr, a.ohi[z], a.olo[z], a.scale[z], a.omode[z],
              smem_u32(smraw));
}

__global__ __launch_bounds__(256)
void gemm_out_kernel(const __nv_bfloat16* __restrict__ Af,
                     const __nv_bfloat16* __restrict__ Whi,
                     const __nv_bfloat16* __restrict__ Wlo,
                     const float* __restrict__ bias, float* __restrict__ outf)
{
    extern __shared__ char smraw[];
    gemm_body(Af, Whi, Wlo, bias, outf, nullptr, nullptr, 1.0f, 0,
              smem_u32(smraw));
}

// ---------------------------------------------------------------------------
// FA2 attention: QK^T = Q_f16 x K_f16 (1 MMA); PV = P_f16 x (V_hi+V_lo)
// (2 MMAs). Pipelined QK(kt+1) before softmax(kt). 3 KV stages.
// ---------------------------------------------------------------------------
#define AROWB 144
#define AQ_B   (128 * AROWB)       // 18432
#define AKV_B  (64 * AROWB)        // 9216
#define A_OFF_K  0
#define A_OFF_VH AKV_B
#define A_OFF_VL (2 * AKV_B)
#define A_STAGE_B (3 * AKV_B)      // 27648
#define ATTN_SMEM (AQ_B + 3 * A_STAGE_B)   // 101376
#define NKT (SEQ / 64)
#define MWORDS (SEQ / 64)

__global__ __launch_bounds__(256, 1)
void attn_mma_kernel(const __nv_bfloat16* __restrict__ qf16,
                     const __nv_bfloat16* __restrict__ kf16,
                     const __nv_bfloat16* __restrict__ vhi,
                     const __nv_bfloat16* __restrict__ vlo,
                     const unsigned long long* __restrict__ bm,
                     uint32_t* __restrict__ jf)
{
    extern __shared__ char smraw[];
    const uint32_t sbase = smem_u32(smraw);
    const int tid  = threadIdx.x;
    const int lane = tid & 31;
    const int wid  = tid >> 5;
    const int wm   = wid * 16;
    const int b    = blockIdx.z;
    const int h    = blockIdx.y;
    const int q0   = blockIdx.x * 128;

    // ---- load Q tile (f16 single) ----
    #pragma unroll
    for (int u = tid; u < 1024; u += 256) {
        int r = u >> 3, c16 = u & 7;
        uint32_t d = sbase + r * AROWB + c16 * 16;
        size_t g = ((size_t)(b * SEQ + q0 + r)) * DMODEL + h * HDIM + c16 * 8;
        cp16(d, qf16 + g);
    }
    CP_COMMIT();

    auto load_kv = [&](int kt, int s) {
        uint32_t st = sbase + AQ_B + s * A_STAGE_B;
        int k0 = kt * 64;
        #pragma unroll
        for (int u = tid; u < 512; u += 256) {
            int r = u >> 3, c16 = u & 7;
            uint32_t d = st + r * AROWB + c16 * 16;
            size_t g = ((size_t)(b * SEQ + k0 + r)) * DMODEL + h * HDIM + c16 * 8;
            cp16(d + A_OFF_K,  kf16 + g);
            cp16(d + A_OFF_VH, vhi + g);
            cp16(d + A_OFF_VL, vlo + g);
        }
    };

    load_kv(0, 0); CP_COMMIT();
    load_kv(1, 1); CP_COMMIT();

    CP_WAIT(2);
    __syncthreads();

    // ---- preload Q fragments ----
    uint32_t aq[4][4];
    {
        const int a_row = lane & 15;
        const int a_kb  = ((lane >> 4) & 1) * 16;
        #pragma unroll
        for (int kc = 0; kc < 4; kc++) {
            uint32_t addr = sbase + (wm + a_row) * AROWB + kc * 32 + a_kb;
            ldsm_x4(aq[kc], addr);
        }
    }

    const int g_    = lane >> 2;
    const int cq    = (lane & 3) * 2;
    const int b_row = (lane & 7) + ((lane >> 4) & 1) * 8;
    const int b_kb  = ((lane >> 3) & 1) * 16;
    const int v_row = lane & 15;
    const int v_col = (lane >> 4) * 8;

    const size_t bmrow0 = ((size_t)b * SEQ + q0 + wm + g_) * MWORDS;
    const size_t bmrow1 = bmrow0 + (size_t)8 * MWORDS;

    float o[8][4];
    #pragma unroll
    for (int i = 0; i < 8; i++)
        #pragma unroll
        for (int j = 0; j < 4; j++) o[i][j] = 0.0f;
    float m0r = -INFINITY, m1r = -INFINITY, l0r = 0.0f, l1r = 0.0f;

    auto qk_tile = [&](int kt, float (*s)[4]) {
        uint32_t st = sbase + AQ_B + (kt % 3) * A_STAGE_B;
        #pragma unroll
        for (int i = 0; i < 8; i++)
            #pragma unroll
            for (int j = 0; j < 4; j++) s[i][j] = 0.0f;
        #pragma unroll
        for (int kc = 0; kc < 4; kc++) {
            #pragma unroll
            for (int np = 0; np < 4; np++) {
                uint32_t kh4[4];
                uint32_t addr = st + A_OFF_K + (np * 16 + b_row) * AROWB + kc * 32 + b_kb;
                ldsm_x4(kh4, addr);
                mma16816h(s[np*2],   aq[kc], kh4);
                mma16816h(s[np*2+1], aq[kc], kh4 + 2);
            }
        }
    };

    float sc[2][8][4];

    CP_WAIT(1);
    __syncthreads();
    qk_tile(0, sc[0]);

    #pragma unroll 2
    for (int kt = 0; kt < NKT; kt++) {
        const int cur = kt & 1, nxt = cur ^ 1;

        __syncthreads();
        if (kt + 2 < NKT) { load_kv(kt + 2, (kt + 2) % 3); CP_COMMIT(); }
        if (kt + 1 < NKT) {
            if (kt + 2 < NKT) { CP_WAIT(1); } else { CP_WAIT(0); }
            __syncthreads();
            qk_tile(kt + 1, sc[nxt]);
        }

        unsigned long long mw0 = __ldg(bm + bmrow0 + kt);
        unsigned long long mw1 = __ldg(bm + bmrow1 + kt);
        float (*s)[4] = sc[cur];

        // ---- mask ----
        #pragma unroll
        for (int nt = 0; nt < 8; nt++) {
            int c0 = nt * 8 + cq;
            if (!((mw0 >> c0) & 1))       s[nt][0] = -1000000000.0f;
            if (!((mw0 >> (c0 + 1)) & 1)) s[nt][1] = -1000000000.0f;
            if (!((mw1 >> c0) & 1))       s[nt][2] = -1000000000.0f;
            if (!((mw1 >> (c0 + 1)) & 1)) s[nt][3] = -1000000000.0f;
        }

        // ---- online softmax (base 2) ----
        float mx0 = s[0][0], mx1 = s[0][2];
        #pragma unroll
        for (int nt = 0; nt < 8; nt++) {
            mx0 = fmaxf(mx0, fmaxf(s[nt][0], s[nt][1]));
            mx1 = fmaxf(mx1, fmaxf(s[nt][2], s[nt][3]));
        }
        mx0 = fmaxf(mx0, __shfl_xor_sync(0xffffffff, mx0, 1));
        mx0 = fmaxf(mx0, __shfl_xor_sync(0xffffffff, mx0, 2));
        mx1 = fmaxf(mx1, __shfl_xor_sync(0xffffffff, mx1, 1));
        mx1 = fmaxf(mx1, __shfl_xor_sync(0xffffffff, mx1, 2));

        float mn0 = fmaxf(m0r, mx0), mn1 = fmaxf(m1r, mx1);
        float al0 = exp2f(m0r - mn0), al1 = exp2f(m1r - mn1);
        m0r = mn0; m1r = mn1;

        float rs0 = 0.0f, rs1 = 0.0f;
        #pragma unroll
        for (int nt = 0; nt < 8; nt++) {
            s[nt][0] = exp2f(s[nt][0] - mn0); rs0 += s[nt][0];
            s[nt][1] = exp2f(s[nt][1] - mn0); rs0 += s[nt][1];
            s[nt][2] = exp2f(s[nt][2] - mn1); rs1 += s[nt][2];
            s[nt][3] = exp2f(s[nt][3] - mn1); rs1 += s[nt][3];
        }
        rs0 += __shfl_xor_sync(0xffffffff, rs0, 1);
        rs0 += __shfl_xor_sync(0xffffffff, rs0, 2);
        rs1 += __shfl_xor_sync(0xffffffff, rs1, 1);
        rs1 += __shfl_xor_sync(0xffffffff, rs1, 2);
        l0r = l0r * al0 + rs0;
        l1r = l1r * al1 + rs1;

        #pragma unroll
        for (int nt = 0; nt < 8; nt++) {
            o[nt][0] *= al0; o[nt][1] *= al0;
            o[nt][2] *= al1; o[nt][3] *= al1;
        }

        // ---- pack P (fp16) ----
        uint32_t ph[4][4];
        #pragma unroll
        for (int tp = 0; tp < 4; tp++) {
            ph[tp][0] = pack_f16(s[2*tp][0],   s[2*tp][1]);
            ph[tp][1] = pack_f16(s[2*tp][2],   s[2*tp][3]);
            ph[tp][2] = pack_f16(s[2*tp+1][0], s[2*tp+1][1]);
            ph[tp][3] = pack_f16(s[2*tp+1][2], s[2*tp+1][3]);
        }

        // ---- O += P V ----
        uint32_t stv = sbase + AQ_B + (kt % 3) * A_STAGE_B;
        #pragma unroll
        for (int nt2 = 0; nt2 < 4; nt2++) {
            #pragma unroll
            for (int tp = 0; tp < 4; tp++) {
                uint32_t vh4[4], vl4[4];
                uint32_t addr = stv + A_OFF_VH + (tp * 16 + v_row) * AROWB
                              + (nt2 * 16 + v_col) * 2;
                ldsm_x4_t(vh4, addr);
                ldsm_x4_t(vl4, addr + (A_OFF_VL - A_OFF_VH));
                mma16816h(o[nt2*2],   ph[tp], vh4);
                mma16816h(o[nt2*2],   ph[tp], vl4);
                mma16816h(o[nt2*2+1], ph[tp], vh4 + 2);
                mma16816h(o[nt2*2+1], ph[tp], vl4 + 2);
            }
        }
    }

    // ---- epilogue: joint as fp16 single ----
    float inv0 = 1.0f / l0r, inv1 = 1.0f / l1r;
    size_t row0 = ((size_t)(b * SEQ + q0 + wm + g_)) * DMODEL + h * HDIM;
    #pragma unroll
    for (int nt = 0; nt < 8; nt++) {
        int col = nt * 8 + cq;
        jf[(row0 + col) >> 1] = pack_f16(o[nt][0] * inv0, o[nt][1] * inv0);
        jf[(row0 + (size_t)8 * DMODEL + col) >> 1] =
            pack_f16(o[nt][2] * inv1, o[nt][3] * inv1);
    }
}

// ---------------------------------------------------------------------------
extern "C" void kernel_launch(void* const* d_in, const int* in_sizes, int n_in,
                              void* d_out, int out_size)
{
    const float* q    = (const float*)d_in[0];
    const float* k    = (const float*)d_in[1];
    const float* v    = (const float*)d_in[2];
    const int*   mask = (const int*)  d_in[3];
    const float* Wq   = (const float*)d_in[4];
    const float* bq   = (const float*)d_in[5];
    const float* Wk   = (const float*)d_in[6];
    const float* bk   = (const float*)d_in[7];
    const float* Wv   = (const float*)d_in[8];
    const float* bv   = (const float*)d_in[9];
    const float* Wo   = (const float*)d_in[10];
    const float* bo   = (const float*)d_in[11];
    float* out = (float*)d_out;

    void *p_xf16, *p_whi4, *p_wlo4;
    void *p_qf16, *p_kf16, *p_vhi, *p_vlo, *p_jf16, *p_bm;
    cudaGetSymbolAddress(&p_xf16, g_xf16);
    cudaGetSymbolAddress(&p_whi4, g_whi4);
    cudaGetSymbolAddress(&p_wlo4, g_wlo4);
    cudaGetSymbolAddress(&p_qf16, g_qf16);
    cudaGetSymbolAddress(&p_kf16, g_kf16);
    cudaGetSymbolAddress(&p_vhi, g_vhi);
    cudaGetSymbolAddress(&p_vlo, g_vlo);
    cudaGetSymbolAddress(&p_jf16, g_jf16);
    cudaGetSymbolAddress(&p_bm, g_maskbits);

    __nv_bfloat16* xf = (__nv_bfloat16*)p_xf16;
    __nv_bfloat16* whi = (__nv_bfloat16*)p_whi4;
    __nv_bfloat16* wlo = (__nv_bfloat16*)p_wlo4;

    const size_t XN = (size_t)MTOT * DMODEL;
    const size_t WN = (size_t)DMODEL * DMODEL;

    cudaFuncSetAttribute(gemm_qkv_kernel,
                         cudaFuncAttributeMaxDynamicSharedMemorySize, GEMM_SMEM);
    cudaFuncSetAttribute(gemm_out_kernel,
                         cudaFuncAttributeMaxDynamicSharedMemorySize, GEMM_SMEM);
    cudaFuncSetAttribute(attn_mma_kernel,
                         cudaFuncAttributeMaxDynamicSharedMemorySize, ATTN_SMEM);

    // 1. pack mask
    mask_pack_kernel<<<(BATCH*SEQ*SEQ/64)/256, 256>>>((const int4*)mask,
        (unsigned long long*)p_bm);

    // 2. split inputs (f16 single) + weights (f16 hi/lo)
    SplitAll sa;
    sa.src[0] = (const float4*)q;  sa.src[1] = (const float4*)k;
    sa.src[2] = (const float4*)v;
    sa.src[3] = (const float4*)Wq; sa.src[4] = (const float4*)Wk;
    sa.src[5] = (const float4*)Wv; sa.src[6] = (const float4*)Wo;
    for (int i = 0; i < 3; i++) {
        sa.hi[i] = (uint32_t*)(xf + i * XN);
        sa.lo[i] = nullptr;
    }
    for (int i = 0; i < 4; i++) {
        sa.hi[3+i] = (uint32_t*)(whi + i * WN);
        sa.lo[3+i] = (uint32_t*)(wlo + i * WN);
    }
    split_all_kernel<<<SPLIT_BLOCKS, 256>>>(sa);

    // 3. fused QKV projections:
    //    Q -> f16 single scaled (log2e/8); K -> f16 single; V -> f16 hi/lo
    QkvArgs qa;
    qa.a[0] = xf;          qa.a[1] = xf + XN;     qa.a[2] = xf + 2*XN;
    qa.whi[0] = whi;       qa.wlo[0] = wlo;
    qa.whi[1] = whi + WN;  qa.wlo[1] = wlo + WN;
    qa.whi[2] = whi + 2*WN; qa.wlo[2] = wlo + 2*WN;
    qa.bias[0] = bq; qa.bias[1] = bk; qa.bias[2] = bv;
    qa.ohi[0] = (uint32_t*)p_qf16; qa.olo[0] = nullptr;
    qa.ohi[1] = (uint32_t*)p_kf16; qa.olo[1] = nullptr;
    qa.ohi[2] = (uint32_t*)p_vhi;  qa.olo[2] = (uint32_t*)p_vlo;
    qa.scale[0] = 0.125f * LOG2E; qa.scale[1] = 1.0f; qa.scale[2] = 1.0f;
    qa.omode[0] = 2; qa.omode[1] = 2; qa.omode[2] = 1;
    dim3 gq(DMODEL / BN, MTOT / BM, 3);
    gemm_qkv_kernel<<<gq, 256, GEMM_SMEM>>>(qa);

    // 4. attention
    dim3 ag(SEQ / 128, NHEADS, BATCH);
    attn_mma_kernel<<<ag, 256, ATTN_SMEM>>>(
        (const __nv_bfloat16*)p_qf16, (const __nv_bfloat16*)p_kf16,
        (const __nv_bfloat16*)p_vhi,  (const __nv_bfloat16*)p_vlo,
        (const unsigned long long*)p_bm, (uint32_t*)p_jf16);

    // 5. output projection (joint f16 single x Wo f16 hi/lo)
    dim3 gg(DMODEL / BN, MTOT / BM);
    gemm_out_kernel<<<gg, 256, GEMM_SMEM>>>(
        (const __nv_bfloat16*)p_jf16, whi + 3*WN, wlo + 3*WN, bo, out);
}

// round 12
// speedup vs baseline: 2.0096x; 1.2496x over previous
#include <cuda_runtime.h>
#include <cuda_bf16.h>
#include <cuda_fp16.h>
#include <cstdint>
#include <math.h>

#define BATCH 2
#define SEQ   2048
#define DMODEL 1024
#define NHEADS 16
#define HDIM  64
#define MTOT  (BATCH*SEQ)   // 4096
#define LOG2E 1.44269504088896f

// ---------------- scratch (allocation-free rule: device globals) -----------
__device__ __nv_bfloat16 g_xf16[3*MTOT*DMODEL];    // fp16: q,k,v inputs
__device__ __nv_bfloat16 g_wf16[4*DMODEL*DMODEL];  // fp16: Wq,Wk,Wv,Wo
__device__ __nv_bfloat16 g_qf16[MTOT*DMODEL];      // fp16 (scaled Q)
__device__ __nv_bfloat16 g_kf16[MTOT*DMODEL];      // fp16 K
__device__ __nv_bfloat16 g_vf16[MTOT*DMODEL];      // fp16 V
__device__ __nv_bfloat16 g_jf16[MTOT*DMODEL];      // fp16 joint
__device__ unsigned long long g_maskbits[(size_t)BATCH*SEQ*SEQ/64];

// ---------------- helpers ---------------------------------------------------
__device__ __forceinline__ uint32_t smem_u32(const void* p) {
    uint32_t a;
    asm("{ .reg .u64 t; cvta.to.shared.u64 t, %1; cvt.u32.u64 %0, t; }"
        : "=r"(a) : "l"(p));
    return a;
}
__device__ __forceinline__ void cp16(uint32_t s, const void* g) {
    asm volatile("cp.async.cg.shared.global [%0], [%1], 16;" :: "r"(s), "l"(g));
}
#define CP_COMMIT()  asm volatile("cp.async.commit_group;" ::: "memory")
#define CP_WAIT(n)   asm volatile("cp.async.wait_group %0;" :: "n"(n) : "memory")

__device__ __forceinline__ void ldsm_x4(uint32_t* r, uint32_t addr) {
    asm volatile("ldmatrix.sync.aligned.m8n8.x4.shared.b16 {%0,%1,%2,%3}, [%4];"
                 : "=r"(r[0]), "=r"(r[1]), "=r"(r[2]), "=r"(r[3]) : "r"(addr));
}
__device__ __forceinline__ void ldsm_x4_t(uint32_t* r, uint32_t addr) {
    asm volatile("ldmatrix.sync.aligned.m8n8.x4.trans.shared.b16 {%0,%1,%2,%3}, [%4];"
                 : "=r"(r[0]), "=r"(r[1]), "=r"(r[2]), "=r"(r[3]) : "r"(addr));
}
__device__ __forceinline__ void mma16816h(float* d, const uint32_t* a,
                                          const uint32_t* b) {
    asm volatile(
        "mma.sync.aligned.m16n8k16.row.col.f32.f16.f16.f32 "
        "{%0,%1,%2,%3}, {%4,%5,%6,%7}, {%8,%9}, {%0,%1,%2,%3};"
        : "+f"(d[0]), "+f"(d[1]), "+f"(d[2]), "+f"(d[3])
        : "r"(a[0]), "r"(a[1]), "r"(a[2]), "r"(a[3]), "r"(b[0]), "r"(b[1]));
}
__device__ __forceinline__ uint32_t pack_f16(float x, float y) {
    __half2 h = __floats2half2_rn(x, y);
    return *reinterpret_cast<uint32_t*>(&h);
}

// ---------------------------------------------------------------------------
// split_all: all 7 tensors -> fp16 single
// ---------------------------------------------------------------------------
struct SplitAll {
    const float4* src[7];
    uint32_t* dst[7];
};
#define NX_BLK 4096
#define NW_BLK 1024
#define SPLIT_BLOCKS (3*NX_BLK + 4*NW_BLK)

__global__ __launch_bounds__(256)
void split_all_kernel(SplitAll a)
{
    int bid = blockIdx.x;
    int seg, idx;
    if (bid < 3 * NX_BLK) { seg = bid / NX_BLK; idx = (bid % NX_BLK) * 256 + threadIdx.x; }
    else { int r = bid - 3 * NX_BLK; seg = 3 + r / NW_BLK; idx = (r % NW_BLK) * 256 + threadIdx.x; }
    float4 v = a.src[seg][idx];
    uint32_t* dst = a.dst[seg];
    dst[2*idx]   = pack_f16(v.x, v.y);
    dst[2*idx+1] = pack_f16(v.z, v.w);
}

// ---------------------------------------------------------------------------
// mask pack
// ---------------------------------------------------------------------------
__global__ __launch_bounds__(256)
void mask_pack_kernel(const int4* __restrict__ mask, unsigned long long* __restrict__ bm)
{
    int i = blockIdx.x * 256 + threadIdx.x;
    const int4* p = mask + (size_t)i * 16;
    unsigned long long w = 0;
    #pragma unroll
    for (int j = 0; j < 16; j++) {
        int4 v = p[j];
        w |= ((unsigned long long)(v.x != 0)) << (j*4);
        w |= ((unsigned long long)(v.y != 0)) << (j*4+1);
        w |= ((unsigned long long)(v.z != 0)) << (j*4+2);
        w |= ((unsigned long long)(v.w != 0)) << (j*4+3);
    }
    bm[i] = w;
}

// ---------------------------------------------------------------------------
// GEMM body: A fp16 x W fp16 -> 1 MMA. 2-stage cp.async. CTA 128x256.
// omode: 0=fp32 out, 2=f16 single out (scaled)
// ---------------------------------------------------------------------------
#define BM 128
#define BN 256
#define BK 32
#define NCHUNK (DMODEL / BK)
#define ROWB 80
#define A_MAT_B (128 * ROWB)        // 10240
#define B_MAT_B (256 * ROWB)        // 20480
#define OFF_A  0
#define OFF_B  A_MAT_B
#define STAGE_B (A_MAT_B + B_MAT_B)   // 30720
#define GEMM_SMEM (2 * STAGE_B)       // 61440

__device__ __forceinline__ void gemm_body(
    const __nv_bfloat16* __restrict__ Af,
    const __nv_bfloat16* __restrict__ Wf,
    const float* __restrict__ bias,
    float* __restrict__ outf, uint32_t* __restrict__ outh,
    float scale, int omode, uint32_t sbase)
{
    const int tid  = threadIdx.x;
    const int lane = tid & 31;
    const int wid  = tid >> 5;
    const int wm   = (wid & 3) * 32;
    const int wn   = (wid >> 2) * 128;
    const int n0   = blockIdx.x * BN;
    const int m0   = blockIdx.y * BM;

    float c[2][16][4];
    #pragma unroll
    for (int mt = 0; mt < 2; mt++)
        #pragma unroll
        for (int nt = 0; nt < 16; nt++)
            #pragma unroll
            for (int j = 0; j < 4; j++) c[mt][nt][j] = 0.0f;

    auto load_chunk = [&](int ck, int s) {
        uint32_t st = sbase + s * STAGE_B;
        int k0 = ck * BK;
        #pragma unroll
        for (int u = tid; u < 512; u += 256) {       // A: 128 x 32 f16
            int r = u >> 2, c16 = u & 3;
            uint32_t d = st + r * ROWB + c16 * 16;
            size_t g = (size_t)(m0 + r) * DMODEL + k0 + c16 * 8;
            cp16(d + OFF_A, Af + g);
        }
        #pragma unroll
        for (int u = tid; u < 1024; u += 256) {      // W: 256 x 32 f16
            int r = u >> 2, c16 = u & 3;
            uint32_t d = st + r * ROWB + c16 * 16;
            size_t g = (size_t)(n0 + r) * DMODEL + k0 + c16 * 8;
            cp16(d + OFF_B, Wf + g);
        }
    };

    load_chunk(0, 0); CP_COMMIT();

    const int a_row  = lane & 15;
    const int a_kb   = ((lane >> 4) & 1) * 16;
    const int b_row  = (lane & 7) + ((lane >> 4) & 1) * 8;
    const int b_kb   = ((lane >> 3) & 1) * 16;

    for (int ck = 0; ck < NCHUNK; ck++) {
        int s = ck & 1;
        if (ck + 1 < NCHUNK) {
            load_chunk(ck + 1, s ^ 1); CP_COMMIT();
            CP_WAIT(1);
        } else {
            CP_WAIT(0);
        }
        __syncthreads();

        uint32_t st = sbase + s * STAGE_B;
        #pragma unroll
        for (int ks = 0; ks < 2; ks++) {
            int kb = ks * 32;
            uint32_t ah[2][4];
            #pragma unroll
            for (int mt = 0; mt < 2; mt++) {
                uint32_t addr = st + OFF_A + (wm + mt * 16 + a_row) * ROWB + kb + a_kb;
                ldsm_x4(ah[mt], addr);
            }
            #pragma unroll
            for (int np = 0; np < 8; np++) {
                uint32_t bh4[4];
                uint32_t addr = st + OFF_B + (wn + np * 16 + b_row) * ROWB + kb + b_kb;
                ldsm_x4(bh4, addr);
                #pragma unroll
                for (int mt = 0; mt < 2; mt++) {
                    mma16816h(c[mt][np*2],   ah[mt], bh4);
                    mma16816h(c[mt][np*2+1], ah[mt], bh4 + 2);
                }
            }
        }
        __syncthreads();
    }

    const int g  = lane >> 2;
    const int cq = (lane & 3) * 2;
    #pragma unroll
    for (int mt = 0; mt < 2; mt++) {
        #pragma unroll
        for (int nt = 0; nt < 16; nt++) {
            int col = n0 + wn + nt * 8 + cq;
            float2 bv = *(const float2*)(bias + col);
            int r0 = m0 + wm + mt * 16 + g;
            float x0 = c[mt][nt][0] + bv.x, y0 = c[mt][nt][1] + bv.y;
            float x1 = c[mt][nt][2] + bv.x, y1 = c[mt][nt][3] + bv.y;
            if (omode == 0) {
                *(float2*)(outf + (size_t)r0 * DMODEL + col) = make_float2(x0, y0);
                *(float2*)(outf + (size_t)(r0 + 8) * DMODEL + col) = make_float2(x1, y1);
            } else {
                outh[((size_t)r0 * DMODEL + col) >> 1] = pack_f16(x0 * scale, y0 * scale);
                outh[(((size_t)(r0 + 8)) * DMODEL + col) >> 1] = pack_f16(x1 * scale, y1 * scale);
            }
        }
    }
}

struct QkvArgs {
    const __nv_bfloat16* a[3];
    const __nv_bfloat16* w[3];
    const float* bias[3];
    uint32_t* o[3];
    float scale[3];
};

__global__ __launch_bounds__(256)
void gemm_qkv_kernel(QkvArgs a)
{
    extern __shared__ char smraw[];
    int z = blockIdx.z;
    gemm_body(a.a[z], a.w[z], a.bias[z], nullptr, a.o[z], a.scale[z], 2,
              smem_u32(smraw));
}

__global__ __launch_bounds__(256)
void gemm_out_kernel(const __nv_bfloat16* __restrict__ Af,
                     const __nv_bfloat16* __restrict__ Wf,
                     const float* __restrict__ bias, float* __restrict__ outf)
{
    extern __shared__ char smraw[];
    gemm_body(Af, Wf, bias, outf, nullptr, 1.0f, 0, smem_u32(smraw));
}

// ---------------------------------------------------------------------------
// FA2 attention: all fp16 single. QK^T 1 MMA, PV 1 MMA per fragment.
// Pipelined QK(kt+1) before softmax(kt). 3 KV stages.
// ---------------------------------------------------------------------------
#define AROWB 144
#define AQ_B   (128 * AROWB)       // 18432
#define AKV_B  (64 * AROWB)        // 9216
#define A_OFF_K  0
#define A_OFF_V  AKV_B
#define A_STAGE_B (2 * AKV_B)      // 18432
#define ATTN_SMEM (AQ_B + 3 * A_STAGE_B)   // 73728
#define NKT (SEQ / 64)
#define MWORDS (SEQ / 64)

__global__ __launch_bounds__(256, 1)
void attn_mma_kernel(const __nv_bfloat16* __restrict__ qf16,
                     const __nv_bfloat16* __restrict__ kf16,
                     const __nv_bfloat16* __restrict__ vf16,
                     const unsigned long long* __restrict__ bm,
                     uint32_t* __restrict__ jf)
{
    extern __shared__ char smraw[];
    const uint32_t sbase = smem_u32(smraw);
    const int tid  = threadIdx.x;
    const int lane = tid & 31;
    const int wid  = tid >> 5;
    const int wm   = wid * 16;
    const int b    = blockIdx.z;
    const int h    = blockIdx.y;
    const int q0   = blockIdx.x * 128;

    // ---- load Q tile (f16) ----
    #pragma unroll
    for (int u = tid; u < 1024; u += 256) {
        int r = u >> 3, c16 = u & 7;
        uint32_t d = sbase + r * AROWB + c16 * 16;
        size_t g = ((size_t)(b * SEQ + q0 + r)) * DMODEL + h * HDIM + c16 * 8;
        cp16(d, qf16 + g);
    }
    CP_COMMIT();

    auto load_kv = [&](int kt, int s) {
        uint32_t st = sbase + AQ_B + s * A_STAGE_B;
        int k0 = kt * 64;
        #pragma unroll
        for (int u = tid; u < 512; u += 256) {
            int r = u >> 3, c16 = u & 7;
            uint32_t d = st + r * AROWB + c16 * 16;
            size_t g = ((size_t)(b * SEQ + k0 + r)) * DMODEL + h * HDIM + c16 * 8;
            cp16(d + A_OFF_K, kf16 + g);
            cp16(d + A_OFF_V, vf16 + g);
        }
    };

    load_kv(0, 0); CP_COMMIT();
    load_kv(1, 1); CP_COMMIT();

    CP_WAIT(2);
    __syncthreads();

    // ---- preload Q fragments ----
    uint32_t aq[4][4];
    {
        const int a_row = lane & 15;
        const int a_kb  = ((lane >> 4) & 1) * 16;
        #pragma unroll
        for (int kc = 0; kc < 4; kc++) {
            uint32_t addr = sbase + (wm + a_row) * AROWB + kc * 32 + a_kb;
            ldsm_x4(aq[kc], addr);
        }
    }

    const int g_    = lane >> 2;
    const int cq    = (lane & 3) * 2;
    const int b_row = (lane & 7) + ((lane >> 4) & 1) * 8;
    const int b_kb  = ((lane >> 3) & 1) * 16;
    const int v_row = lane & 15;
    const int v_col = (lane >> 4) * 8;

    const size_t bmrow0 = ((size_t)b * SEQ + q0 + wm + g_) * MWORDS;
    const size_t bmrow1 = bmrow0 + (size_t)8 * MWORDS;

    float o[8][4];
    #pragma unroll
    for (int i = 0; i < 8; i++)
        #pragma unroll
        for (int j = 0; j < 4; j++) o[i][j] = 0.0f;
    float m0r = -INFINITY, m1r = -INFINITY, l0r = 0.0f, l1r = 0.0f;

    auto qk_tile = [&](int kt, float (*s)[4]) {
        uint32_t st = sbase + AQ_B + (kt % 3) * A_STAGE_B;
        #pragma unroll
        for (int i = 0; i < 8; i++)
            #pragma unroll
            for (int j = 0; j < 4; j++) s[i][j] = 0.0f;
        #pragma unroll
        for (int kc = 0; kc < 4; kc++) {
            #pragma unroll
            for (int np = 0; np < 4; np++) {
                uint32_t kh4[4];
                uint32_t addr = st + A_OFF_K + (np * 16 + b_row) * AROWB + kc * 32 + b_kb;
                ldsm_x4(kh4, addr);
                mma16816h(s[np*2],   aq[kc], kh4);
                mma16816h(s[np*2+1], aq[kc], kh4 + 2);
            }
        }
    };

    float sc[2][8][4];

    CP_WAIT(1);
    __syncthreads();
    qk_tile(0, sc[0]);

    #pragma unroll 2
    for (int kt = 0; kt < NKT; kt++) {
        const int cur = kt & 1, nxt = cur ^ 1;

        __syncthreads();
        if (kt + 2 < NKT) { load_kv(kt + 2, (kt + 2) % 3); CP_COMMIT(); }
        if (kt + 1 < NKT) {
            if (kt + 2 < NKT) { CP_WAIT(1); } else { CP_WAIT(0); }
            __syncthreads();
            qk_tile(kt + 1, sc[nxt]);
        }

        unsigned long long mw0 = __ldg(bm + bmrow0 + kt);
        unsigned long long mw1 = __ldg(bm + bmrow1 + kt);
        float (*s)[4] = sc[cur];

        // ---- mask ----
        #pragma unroll
        for (int nt = 0; nt < 8; nt++) {
            int c0 = nt * 8 + cq;
            if (!((mw0 >> c0) & 1))       s[nt][0] = -1000000000.0f;
            if (!((mw0 >> (c0 + 1)) & 1)) s[nt][1] = -1000000000.0f;
            if (!((mw1 >> c0) & 1))       s[nt][2] = -1000000000.0f;
            if (!((mw1 >> (c0 + 1)) & 1)) s[nt][3] = -1000000000.0f;
        }

        // ---- online softmax (base 2) ----
        float mx0 = s[0][0], mx1 = s[0][2];
        #pragma unroll
        for (int nt = 0; nt < 8; nt++) {
            mx0 = fmaxf(mx0, fmaxf(s[nt][0], s[nt][1]));
            mx1 = fmaxf(mx1, fmaxf(s[nt][2], s[nt][3]));
        }
        mx0 = fmaxf(mx0, __shfl_xor_sync(0xffffffff, mx0, 1));
        mx0 = fmaxf(mx0, __shfl_xor_sync(0xffffffff, mx0, 2));
        mx1 = fmaxf(mx1, __shfl_xor_sync(0xffffffff, mx1, 1));
        mx1 = fmaxf(mx1, __shfl_xor_sync(0xffffffff, mx1, 2));

        float mn0 = fmaxf(m0r, mx0), mn1 = fmaxf(m1r, mx1);
        float al0 = exp2f(m0r - mn0), al1 = exp2f(m1r - mn1);
        m0r = mn0; m1r = mn1;

        float rs0 = 0.0f, rs1 = 0.0f;
        #pragma unroll
        for (int nt = 0; nt < 8; nt++) {
            s[nt][0] = exp2f(s[nt][0] - mn0); rs0 += s[nt][0];
            s[nt][1] = exp2f(s[nt][1] - mn0); rs0 += s[nt][1];
            s[nt][2] = exp2f(s[nt][2] - mn1); rs1 += s[nt][2];
            s[nt][3] = exp2f(s[nt][3] - mn1); rs1 += s[nt][3];
        }
        rs0 += __shfl_xor_sync(0xffffffff, rs0, 1);
        rs0 += __shfl_xor_sync(0xffffffff, rs0, 2);
        rs1 += __shfl_xor_sync(0xffffffff, rs1, 1);
        rs1 += __shfl_xor_sync(0xffffffff, rs1, 2);
        l0r = l0r * al0 + rs0;
        l1r = l1r * al1 + rs1;

        #pragma unroll
        for (int nt = 0; nt < 8; nt++) {
            o[nt][0] *= al0; o[nt][1] *= al0;
            o[nt][2] *= al1; o[nt][3] *= al1;
        }

        // ---- pack P (fp16) ----
        uint32_t ph[4][4];
        #pragma unroll
        for (int tp = 0; tp < 4; tp++) {
            ph[tp][0] = pack_f16(s[2*tp][0],   s[2*tp][1]);
            ph[tp][1] = pack_f16(s[2*tp][2],   s[2*tp][3]);
            ph[tp][2] = pack_f16(s[2*tp+1][0], s[2*tp+1][1]);
            ph[tp][3] = pack_f16(s[2*tp+1][2], s[2*tp+1][3]);
        }

        // ---- O += P V ----
        uint32_t stv = sbase + AQ_B + (kt % 3) * A_STAGE_B;
        #pragma unroll
        for (int nt2 = 0; nt2 < 4; nt2++) {
            #pragma unroll
            for (int tp = 0; tp < 4; tp++) {
                uint32_t vh4[4];
                uint32_t addr = stv + A_OFF_V + (tp * 16 + v_row) * AROWB
                              + (nt2 * 16 + v_col) * 2;
                ldsm_x4_t(vh4, addr);
                mma16816h(o[nt2*2],   ph[tp], vh4);
                mma16816h(o[nt2*2+1], ph[tp], vh4 + 2);
            }
        }
    }

    // ---- epilogue: joint as fp16 ----
    float inv0 = 1.0f / l0r, inv1 = 1.0f / l1r;
    size_t row0 = ((size_t)(b * SEQ + q0 + wm + g_)) * DMODEL + h * HDIM;
    #pragma unroll
    for (int nt = 0; nt < 8; nt++) {
        int col = nt * 8 + cq;
        jf[(row0 + col) >> 1] = pack_f16(o[nt][0] * inv0, o[nt][1] * inv0);
        jf[(row0 + (size_t)8 * DMODEL + col) >> 1] =
            pack_f16(o[nt][2] * inv1, o[nt][3] * inv1);
    }
}

// ---------------------------------------------------------------------------
extern "C" void kernel_launch(void* const* d_in, const int* in_sizes, int n_in,
                              void* d_out, int out_size)
{
    const float* q    = (const float*)d_in[0];
    const float* k    = (const float*)d_in[1];
    const float* v    = (const float*)d_in[2];
    const int*   mask = (const int*)  d_in[3];
    const float* Wq   = (const float*)d_in[4];
    const float* bq   = (const float*)d_in[5];
    const float* Wk   = (const float*)d_in[6];
    const float* bk   = (const float*)d_in[7];
    const float* Wv   = (const float*)d_in[8];
    const float* bv   = (const float*)d_in[9];
    const float* Wo   = (const float*)d_in[10];
    const float* bo   = (const float*)d_in[11];
    float* out = (float*)d_out;

    void *p_xf16, *p_wf16, *p_qf16, *p_kf16, *p_vf16, *p_jf16, *p_bm;
    cudaGetSymbolAddress(&p_xf16, g_xf16);
    cudaGetSymbolAddress(&p_wf16, g_wf16);
    cudaGetSymbolAddress(&p_qf16, g_qf16);
    cudaGetSymbolAddress(&p_kf16, g_kf16);
    cudaGetSymbolAddress(&p_vf16, g_vf16);
    cudaGetSymbolAddress(&p_jf16, g_jf16);
    cudaGetSymbolAddress(&p_bm, g_maskbits);

    __nv_bfloat16* xf = (__nv_bfloat16*)p_xf16;
    __nv_bfloat16* wf = (__nv_bfloat16*)p_wf16;

    const size_t XN = (size_t)MTOT * DMODEL;
    const size_t WN = (size_t)DMODEL * DMODEL;

    cudaFuncSetAttribute(gemm_qkv_kernel,
                         cudaFuncAttributeMaxDynamicSharedMemorySize, GEMM_SMEM);
    cudaFuncSetAttribute(gemm_out_kernel,
                         cudaFuncAttributeMaxDynamicSharedMemorySize, GEMM_SMEM);
    cudaFuncSetAttribute(attn_mma_kernel,
                         cudaFuncAttributeMaxDynamicSharedMemorySize, ATTN_SMEM);

    // 1. pack mask
    mask_pack_kernel<<<(BATCH*SEQ*SEQ/64)/256, 256>>>((const int4*)mask,
        (unsigned long long*)p_bm);

    // 2. split all to fp16
    SplitAll sa;
    sa.src[0] = (const float4*)q;  sa.src[1] = (const float4*)k;
    sa.src[2] = (const float4*)v;
    sa.src[3] = (const float4*)Wq; sa.src[4] = (const float4*)Wk;
    sa.src[5] = (const float4*)Wv; sa.src[6] = (const float4*)Wo;
    for (int i = 0; i < 3; i++) sa.dst[i] = (uint32_t*)(xf + i * XN);
    for (int i = 0; i < 4; i++) sa.dst[3+i] = (uint32_t*)(wf + i * WN);
    split_all_kernel<<<SPLIT_BLOCKS, 256>>>(sa);

    // 3. fused QKV projections (Q scaled by log2e/8)
    QkvArgs qa;
    qa.a[0] = xf;          qa.a[1] = xf + XN;     qa.a[2] = xf + 2*XN;
    qa.w[0] = wf;          qa.w[1] = wf + WN;     qa.w[2] = wf + 2*WN;
    qa.bias[0] = bq; qa.bias[1] = bk; qa.bias[2] = bv;
    qa.o[0] = (uint32_t*)p_qf16;
    qa.o[1] = (uint32_t*)p_kf16;
    qa.o[2] = (uint32_t*)p_vf16;
    qa.scale[0] = 0.125f * LOG2E; qa.scale[1] = 1.0f; qa.scale[2] = 1.0f;
    dim3 gq(DMODEL / BN, MTOT / BM, 3);
    gemm_qkv_kernel<<<gq, 256, GEMM_SMEM>>>(qa);

    // 4. attention
    dim3 ag(SEQ / 128, NHEADS, BATCH);
    attn_mma_kernel<<<ag, 256, ATTN_SMEM>>>(
        (const __nv_bfloat16*)p_qf16, (const __nv_bfloat16*)p_kf16,
        (const __nv_bfloat16*)p_vf16,
        (const unsigned long long*)p_bm, (uint32_t*)p_jf16);

    // 5. output projection (fp32 out)
    dim3 gg(DMODEL / BN, MTOT / BM);
    gemm_out_kernel<<<gg, 256, GEMM_SMEM>>>(
        (const __nv_bfloat16*)p_jf16, wf + 3*WN, bo, out);
}

// round 13
// speedup vs baseline: 2.0167x; 1.0035x over previous
#include <cuda_runtime.h>
#include <cuda_bf16.h>
#include <cuda_fp16.h>
#include <cstdint>
#include <math.h>

#define BATCH 2
#define SEQ   2048
#define DMODEL 1024
#define NHEADS 16
#define HDIM  64
#define MTOT  (BATCH*SEQ)   // 4096
#define LOG2E 1.44269504088896f

// ---------------- scratch (allocation-free rule: device globals) -----------
__device__ __nv_bfloat16 g_xf16[3*MTOT*DMODEL];    // fp16: q,k,v inputs
__device__ __nv_bfloat16 g_wf16[4*DMODEL*DMODEL];  // fp16: Wq,Wk,Wv,Wo
__device__ __nv_bfloat16 g_qf16[MTOT*DMODEL];      // fp16 (scaled Q)
__device__ __nv_bfloat16 g_kf16[MTOT*DMODEL];      // fp16 K
__device__ __nv_bfloat16 g_vf16[MTOT*DMODEL];      // fp16 V
__device__ __nv_bfloat16 g_jf16[MTOT*DMODEL];      // fp16 joint
__device__ unsigned long long g_maskbits[(size_t)BATCH*SEQ*SEQ/64];

// ---------------- helpers ---------------------------------------------------
__device__ __forceinline__ uint32_t smem_u32(const void* p) {
    uint32_t a;
    asm("{ .reg .u64 t; cvta.to.shared.u64 t, %1; cvt.u32.u64 %0, t; }"
        : "=r"(a) : "l"(p));
    return a;
}
__device__ __forceinline__ void cp16(uint32_t s, const void* g) {
    asm volatile("cp.async.cg.shared.global [%0], [%1], 16;" :: "r"(s), "l"(g));
}
#define CP_COMMIT()  asm volatile("cp.async.commit_group;" ::: "memory")
#define CP_WAIT(n)   asm volatile("cp.async.wait_group %0;" :: "n"(n) : "memory")

__device__ __forceinline__ void ldsm_x4(uint32_t* r, uint32_t addr) {
    asm volatile("ldmatrix.sync.aligned.m8n8.x4.shared.b16 {%0,%1,%2,%3}, [%4];"
                 : "=r"(r[0]), "=r"(r[1]), "=r"(r[2]), "=r"(r[3]) : "r"(addr));
}
__device__ __forceinline__ void ldsm_x4_t(uint32_t* r, uint32_t addr) {
    asm volatile("ldmatrix.sync.aligned.m8n8.x4.trans.shared.b16 {%0,%1,%2,%3}, [%4];"
                 : "=r"(r[0]), "=r"(r[1]), "=r"(r[2]), "=r"(r[3]) : "r"(addr));
}
__device__ __forceinline__ void mma16816h(float* d, const uint32_t* a,
                                          const uint32_t* b) {
    asm volatile(
        "mma.sync.aligned.m16n8k16.row.col.f32.f16.f16.f32 "
        "{%0,%1,%2,%3}, {%4,%5,%6,%7}, {%8,%9}, {%0,%1,%2,%3};"
        : "+f"(d[0]), "+f"(d[1]), "+f"(d[2]), "+f"(d[3])
        : "r"(a[0]), "r"(a[1]), "r"(a[2]), "r"(a[3]), "r"(b[0]), "r"(b[1]));
}
__device__ __forceinline__ uint32_t pack_f16(float x, float y) {
    __half2 h = __floats2half2_rn(x, y);
    return *reinterpret_cast<uint32_t*>(&h);
}

// ---------------------------------------------------------------------------
// split_all: all 7 tensors -> fp16 single
// ---------------------------------------------------------------------------
struct SplitAll {
    const float4* src[7];
    uint32_t* dst[7];
};
#define NX_BLK 4096
#define NW_BLK 1024
#define SPLIT_BLOCKS (3*NX_BLK + 4*NW_BLK)

__global__ __launch_bounds__(256)
void split_all_kernel(SplitAll a)
{
    int bid = blockIdx.x;
    int seg, idx;
    if (bid < 3 * NX_BLK) { seg = bid / NX_BLK; idx = (bid % NX_BLK) * 256 + threadIdx.x; }
    else { int r = bid - 3 * NX_BLK; seg = 3 + r / NW_BLK; idx = (r % NW_BLK) * 256 + threadIdx.x; }
    float4 v = a.src[seg][idx];
    uint32_t* dst = a.dst[seg];
    dst[2*idx]   = pack_f16(v.x, v.y);
    dst[2*idx+1] = pack_f16(v.z, v.w);
}

// ---------------------------------------------------------------------------
// mask pack
// ---------------------------------------------------------------------------
__global__ __launch_bounds__(256)
void mask_pack_kernel(const int4* __restrict__ mask, unsigned long long* __restrict__ bm)
{
    int i = blockIdx.x * 256 + threadIdx.x;
    const int4* p = mask + (size_t)i * 16;
    unsigned long long w = 0;
    #pragma unroll
    for (int j = 0; j < 16; j++) {
        int4 v = p[j];
        w |= ((unsigned long long)(v.x != 0)) << (j*4);
        w |= ((unsigned long long)(v.y != 0)) << (j*4+1);
        w |= ((unsigned long long)(v.z != 0)) << (j*4+2);
        w |= ((unsigned long long)(v.w != 0)) << (j*4+3);
    }
    bm[i] = w;
}

// ---------------------------------------------------------------------------
// GEMM body: A fp16 x W fp16 -> 1 MMA. Warp tile 64x64 (2m x 4n warps),
// 2-stage cp.async. CTA 128x256.
// omode: 0=fp32 out, 2=f16 single out (scaled)
// ---------------------------------------------------------------------------
#define BM 128
#define BN 256
#define BK 32
#define NCHUNK (DMODEL / BK)
#define ROWB 80
#define A_MAT_B (128 * ROWB)        // 10240
#define B_MAT_B (256 * ROWB)        // 20480
#define OFF_A  0
#define OFF_B  A_MAT_B
#define STAGE_B (A_MAT_B + B_MAT_B)   // 30720
#define GEMM_SMEM (2 * STAGE_B)       // 61440

__device__ __forceinline__ void gemm_body(
    const __nv_bfloat16* __restrict__ Af,
    const __nv_bfloat16* __restrict__ Wf,
    const float* __restrict__ bias,
    float* __restrict__ outf, uint32_t* __restrict__ outh,
    float scale, int omode, uint32_t sbase)
{
    const int tid  = threadIdx.x;
    const int lane = tid & 31;
    const int wid  = tid >> 5;
    const int wm   = (wid & 1) * 64;     // 2 m-warps (64 rows each)
    const int wn   = (wid >> 1) * 64;    // 4 n-warps (64 cols each)
    const int n0   = blockIdx.x * BN;
    const int m0   = blockIdx.y * BM;

    float c[4][8][4];
    #pragma unroll
    for (int mt = 0; mt < 4; mt++)
        #pragma unroll
        for (int nt = 0; nt < 8; nt++)
            #pragma unroll
            for (int j = 0; j < 4; j++) c[mt][nt][j] = 0.0f;

    auto load_chunk = [&](int ck, int s) {
        uint32_t st = sbase + s * STAGE_B;
        int k0 = ck * BK;
        #pragma unroll
        for (int u = tid; u < 512; u += 256) {       // A: 128 x 32 f16
            int r = u >> 2, c16 = u & 3;
            uint32_t d = st + r * ROWB + c16 * 16;
            size_t g = (size_t)(m0 + r) * DMODEL + k0 + c16 * 8;
            cp16(d + OFF_A, Af + g);
        }
        #pragma unroll
        for (int u = tid; u < 1024; u += 256) {      // W: 256 x 32 f16
            int r = u >> 2, c16 = u & 3;
            uint32_t d = st + r * ROWB + c16 * 16;
            size_t g = (size_t)(n0 + r) * DMODEL + k0 + c16 * 8;
            cp16(d + OFF_B, Wf + g);
        }
    };

    load_chunk(0, 0); CP_COMMIT();

    const int a_row  = lane & 15;
    const int a_kb   = ((lane >> 4) & 1) * 16;
    const int b_row  = (lane & 7) + ((lane >> 4) & 1) * 8;
    const int b_kb   = ((lane >> 3) & 1) * 16;

    for (int ck = 0; ck < NCHUNK; ck++) {
        int s = ck & 1;
        if (ck + 1 < NCHUNK) {
            load_chunk(ck + 1, s ^ 1); CP_COMMIT();
            CP_WAIT(1);
        } else {
            CP_WAIT(0);
        }
        __syncthreads();

        uint32_t st = sbase + s * STAGE_B;
        #pragma unroll
        for (int ks = 0; ks < 2; ks++) {
            int kb = ks * 32;
            uint32_t ah[4][4];
            #pragma unroll
            for (int mt = 0; mt < 4; mt++) {
                uint32_t addr = st + OFF_A + (wm + mt * 16 + a_row) * ROWB + kb + a_kb;
                ldsm_x4(ah[mt], addr);
            }
            #pragma unroll
            for (int np = 0; np < 4; np++) {
                uint32_t bh4[4];
                uint32_t addr = st + OFF_B + (wn + np * 16 + b_row) * ROWB + kb + b_kb;
                ldsm_x4(bh4, addr);
                #pragma unroll
                for (int mt = 0; mt < 4; mt++) {
                    mma16816h(c[mt][np*2],   ah[mt], bh4);
                    mma16816h(c[mt][np*2+1], ah[mt], bh4 + 2);
                }
            }
        }
        __syncthreads();
    }

    const int g  = lane >> 2;
    const int cq = (lane & 3) * 2;
    #pragma unroll
    for (int mt = 0; mt < 4; mt++) {
        #pragma unroll
        for (int nt = 0; nt < 8; nt++) {
            int col = n0 + wn + nt * 8 + cq;
            float2 bv = *(const float2*)(bias + col);
            int r0 = m0 + wm + mt * 16 + g;
            float x0 = c[mt][nt][0] + bv.x, y0 = c[mt][nt][1] + bv.y;
            float x1 = c[mt][nt][2] + bv.x, y1 = c[mt][nt][3] + bv.y;
            if (omode == 0) {
                *(float2*)(outf + (size_t)r0 * DMODEL + col) = make_float2(x0, y0);
                *(float2*)(outf + (size_t)(r0 + 8) * DMODEL + col) = make_float2(x1, y1);
            } else {
                outh[((size_t)r0 * DMODEL + col) >> 1] = pack_f16(x0 * scale, y0 * scale);
                outh[(((size_t)(r0 + 8)) * DMODEL + col) >> 1] = pack_f16(x1 * scale, y1 * scale);
            }
        }
    }
}

struct QkvArgs {
    const __nv_bfloat16* a[3];
    const __nv_bfloat16* w[3];
    const float* bias[3];
    uint32_t* o[3];
    float scale[3];
};

__global__ __launch_bounds__(256)
void gemm_qkv_kernel(QkvArgs a)
{
    extern __shared__ char smraw[];
    int z = blockIdx.z;
    gemm_body(a.a[z], a.w[z], a.bias[z], nullptr, a.o[z], a.scale[z], 2,
              smem_u32(smraw));
}

__global__ __launch_bounds__(256)
void gemm_out_kernel(const __nv_bfloat16* __restrict__ Af,
                     const __nv_bfloat16* __restrict__ Wf,
                     const float* __restrict__ bias, float* __restrict__ outf)
{
    extern __shared__ char smraw[];
    gemm_body(Af, Wf, bias, outf, nullptr, 1.0f, 0, smem_u32(smraw));
}

// ---------------------------------------------------------------------------
// FA2 attention: all fp16. KV tile = 128 rows (16 iterations). Single score
// buffer sc[16][4]; softmax bookkeeping amortized over 128 columns.
// 2-stage KV smem pipeline.
// ---------------------------------------------------------------------------
#define AROWB 144
#define AQ_B   (128 * AROWB)       // 18432
#define AKV_B  (128 * AROWB)       // 18432 (128-row tile)
#define A_OFF_K  0
#define A_OFF_V  AKV_B
#define A_STAGE_B (2 * AKV_B)      // 36864
#define ATTN_SMEM (AQ_B + 2 * A_STAGE_B)   // 92160
#define NKT (SEQ / 128)            // 16
#define MWORDS (SEQ / 64)          // 32

__global__ __launch_bounds__(256, 1)
void attn_mma_kernel(const __nv_bfloat16* __restrict__ qf16,
                     const __nv_bfloat16* __restrict__ kf16,
                     const __nv_bfloat16* __restrict__ vf16,
                     const unsigned long long* __restrict__ bm,
                     uint32_t* __restrict__ jf)
{
    extern __shared__ char smraw[];
    const uint32_t sbase = smem_u32(smraw);
    const int tid  = threadIdx.x;
    const int lane = tid & 31;
    const int wid  = tid >> 5;
    const int wm   = wid * 16;
    const int b    = blockIdx.z;
    const int h    = blockIdx.y;
    const int q0   = blockIdx.x * 128;

    // ---- load Q tile (f16) ----
    #pragma unroll
    for (int u = tid; u < 1024; u += 256) {
        int r = u >> 3, c16 = u & 7;
        uint32_t d = sbase + r * AROWB + c16 * 16;
        size_t g = ((size_t)(b * SEQ + q0 + r)) * DMODEL + h * HDIM + c16 * 8;
        cp16(d, qf16 + g);
    }
    CP_COMMIT();

    auto load_kv = [&](int kt, int s) {
        uint32_t st = sbase + AQ_B + s * A_STAGE_B;
        int k0 = kt * 128;
        #pragma unroll
        for (int u = tid; u < 1024; u += 256) {
            int r = u >> 3, c16 = u & 7;
            uint32_t d = st + r * AROWB + c16 * 16;
            size_t g = ((size_t)(b * SEQ + k0 + r)) * DMODEL + h * HDIM + c16 * 8;
            cp16(d + A_OFF_K, kf16 + g);
            cp16(d + A_OFF_V, vf16 + g);
        }
    };

    load_kv(0, 0); CP_COMMIT();
    CP_WAIT(1);   // Q done, kv0 in flight
    __syncthreads();

    // ---- preload Q fragments ----
    uint32_t aq[4][4];
    {
        const int a_row = lane & 15;
        const int a_kb  = ((lane >> 4) & 1) * 16;
        #pragma unroll
        for (int kc = 0; kc < 4; kc++) {
            uint32_t addr = sbase + (wm + a_row) * AROWB + kc * 32 + a_kb;
            ldsm_x4(aq[kc], addr);
        }
    }

    const int g_    = lane >> 2;
    const int cq    = (lane & 3) * 2;
    const int b_row = (lane & 7) + ((lane >> 4) & 1) * 8;
    const int b_kb  = ((lane >> 3) & 1) * 16;
    const int v_row = lane & 15;
    const int v_col = (lane >> 4) * 8;

    const size_t bmrow0 = ((size_t)b * SEQ + q0 + wm + g_) * MWORDS;
    const size_t bmrow1 = bmrow0 + (size_t)8 * MWORDS;

    float o[8][4];
    #pragma unroll
    for (int i = 0; i < 8; i++)
        #pragma unroll
        for (int j = 0; j < 4; j++) o[i][j] = 0.0f;
    float m0r = -INFINITY, m1r = -INFINITY, l0r = 0.0f, l1r = 0.0f;

    for (int kt = 0; kt < NKT; kt++) {
        int s = kt & 1;
        __syncthreads();   // all warps done reading stage s^1 (prev iter)
        if (kt + 1 < NKT) {
            load_kv(kt + 1, s ^ 1); CP_COMMIT();
            CP_WAIT(1);
        } else {
            CP_WAIT(0);
        }
        __syncthreads();

        uint32_t st = sbase + AQ_B + s * A_STAGE_B;

        // mask words for 128 columns (2 u64 per row-half)
        unsigned long long mw0a = __ldg(bm + bmrow0 + 2*kt);
        unsigned long long mw0b = __ldg(bm + bmrow0 + 2*kt + 1);
        unsigned long long mw1a = __ldg(bm + bmrow1 + 2*kt);
        unsigned long long mw1b = __ldg(bm + bmrow1 + 2*kt + 1);

        // ---- S = Q K^T over 128 K rows ----
        float sc[16][4];
        #pragma unroll
        for (int i = 0; i < 16; i++)
            #pragma unroll
            for (int j = 0; j < 4; j++) sc[i][j] = 0.0f;

        #pragma unroll
        for (int kc = 0; kc < 4; kc++) {
            #pragma unroll
            for (int np = 0; np < 8; np++) {
                uint32_t kh4[4];
                uint32_t addr = st + A_OFF_K + (np * 16 + b_row) * AROWB + kc * 32 + b_kb;
                ldsm_x4(kh4, addr);
                mma16816h(sc[np*2],   aq[kc], kh4);
                mma16816h(sc[np*2+1], aq[kc], kh4 + 2);
            }
        }

        // ---- mask ----
        #pragma unroll
        for (int nt = 0; nt < 16; nt++) {
            unsigned long long w0 = (nt < 8) ? mw0a : mw0b;
            unsigned long long w1 = (nt < 8) ? mw1a : mw1b;
            int c0 = (nt & 7) * 8 + cq;
            if (!((w0 >> c0) & 1))       sc[nt][0] = -1000000000.0f;
            if (!((w0 >> (c0 + 1)) & 1)) sc[nt][1] = -1000000000.0f;
            if (!((w1 >> c0) & 1))       sc[nt][2] = -1000000000.0f;
            if (!((w1 >> (c0 + 1)) & 1)) sc[nt][3] = -1000000000.0f;
        }

        // ---- online softmax (base 2), amortized over 128 cols ----
        float mx0 = sc[0][0], mx1 = sc[0][2];
        #pragma unroll
        for (int nt = 0; nt < 16; nt++) {
            mx0 = fmaxf(mx0, fmaxf(sc[nt][0], sc[nt][1]));
            mx1 = fmaxf(mx1, fmaxf(sc[nt][2], sc[nt][3]));
        }
        mx0 = fmaxf(mx0, __shfl_xor_sync(0xffffffff, mx0, 1));
        mx0 = fmaxf(mx0, __shfl_xor_sync(0xffffffff, mx0, 2));
        mx1 = fmaxf(mx1, __shfl_xor_sync(0xffffffff, mx1, 1));
        mx1 = fmaxf(mx1, __shfl_xor_sync(0xffffffff, mx1, 2));

        float mn0 = fmaxf(m0r, mx0), mn1 = fmaxf(m1r, mx1);
        float al0 = exp2f(m0r - mn0), al1 = exp2f(m1r - mn1);
        m0r = mn0; m1r = mn1;

        float rs0 = 0.0f, rs1 = 0.0f;
        #pragma unroll
        for (int nt = 0; nt < 16; nt++) {
            sc[nt][0] = exp2f(sc[nt][0] - mn0); rs0 += sc[nt][0];
            sc[nt][1] = exp2f(sc[nt][1] - mn0); rs0 += sc[nt][1];
            sc[nt][2] = exp2f(sc[nt][2] - mn1); rs1 += sc[nt][2];
            sc[nt][3] = exp2f(sc[nt][3] - mn1); rs1 += sc[nt][3];
        }
        rs0 += __shfl_xor_sync(0xffffffff, rs0, 1);
        rs0 += __shfl_xor_sync(0xffffffff, rs0, 2);
        rs1 += __shfl_xor_sync(0xffffffff, rs1, 1);
        rs1 += __shfl_xor_sync(0xffffffff, rs1, 2);
        l0r = l0r * al0 + rs0;
        l1r = l1r * al1 + rs1;

        #pragma unroll
        for (int nt = 0; nt < 8; nt++) {
            o[nt][0] *= al0; o[nt][1] *= al0;
            o[nt][2] *= al1; o[nt][3] *= al1;
        }

        // ---- pack P (fp16): 8 k16 chunks ----
        uint32_t ph[8][4];
        #pragma unroll
        for (int tp = 0; tp < 8; tp++) {
            ph[tp][0] = pack_f16(sc[2*tp][0],   sc[2*tp][1]);
            ph[tp][1] = pack_f16(sc[2*tp][2],   sc[2*tp][3]);
            ph[tp][2] = pack_f16(sc[2*tp+1][0], sc[2*tp+1][1]);
            ph[tp][3] = pack_f16(sc[2*tp+1][2], sc[2*tp+1][3]);
        }

        // ---- O += P V  (V: 128 k-rows x 64 cols) ----
        #pragma unroll
        for (int nt2 = 0; nt2 < 4; nt2++) {
            #pragma unroll
            for (int tp = 0; tp < 8; tp++) {
                uint32_t vh4[4];
                uint32_t addr = st + A_OFF_V + (tp * 16 + v_row) * AROWB
                              + (nt2 * 16 + v_col) * 2;
                ldsm_x4_t(vh4, addr);
                mma16816h(o[nt2*2],   ph[tp], vh4);
                mma16816h(o[nt2*2+1], ph[tp], vh4 + 2);
            }
        }
    }

    // ---- epilogue: joint as fp16 ----
    float inv0 = 1.0f / l0r, inv1 = 1.0f / l1r;
    size_t row0 = ((size_t)(b * SEQ + q0 + wm + g_)) * DMODEL + h * HDIM;
    #pragma unroll
    for (int nt = 0; nt < 8; nt++) {
        int col = nt * 8 + cq;
        jf[(row0 + col) >> 1] = pack_f16(o[nt][0] * inv0, o[nt][1] * inv0);
        jf[(row0 + (size_t)8 * DMODEL + col) >> 1] =
            pack_f16(o[nt][2] * inv1, o[nt][3] * inv1);
    }
}

// ---------------------------------------------------------------------------
extern "C" void kernel_launch(void* const* d_in, const int* in_sizes, int n_in,
                              void* d_out, int out_size)
{
    const float* q    = (const float*)d_in[0];
    const float* k    = (const float*)d_in[1];
    const float* v    = (const float*)d_in[2];
    const int*   mask = (const int*)  d_in[3];
    const float* Wq   = (const float*)d_in[4];
    const float* bq   = (const float*)d_in[5];
    const float* Wk   = (const float*)d_in[6];
    const float* bk   = (const float*)d_in[7];
    const float* Wv   = (const float*)d_in[8];
    const float* bv   = (const float*)d_in[9];
    const float* Wo   = (const float*)d_in[10];
    const float* bo   = (const float*)d_in[11];
    float* out = (float*)d_out;

    void *p_xf16, *p_wf16, *p_qf16, *p_kf16, *p_vf16, *p_jf16, *p_bm;
    cudaGetSymbolAddress(&p_xf16, g_xf16);
    cudaGetSymbolAddress(&p_wf16, g_wf16);
    cudaGetSymbolAddress(&p_qf16, g_qf16);
    cudaGetSymbolAddress(&p_kf16, g_kf16);
    cudaGetSymbolAddress(&p_vf16, g_vf16);
    cudaGetSymbolAddress(&p_jf16, g_jf16);
    cudaGetSymbolAddress(&p_bm, g_maskbits);

    __nv_bfloat16* xf = (__nv_bfloat16*)p_xf16;
    __nv_bfloat16* wf = (__nv_bfloat16*)p_wf16;

    const size_t XN = (size_t)MTOT * DMODEL;
    const size_t WN = (size_t)DMODEL * DMODEL;

    cudaFuncSetAttribute(gemm_qkv_kernel,
                         cudaFuncAttributeMaxDynamicSharedMemorySize, GEMM_SMEM);
    cudaFuncSetAttribute(gemm_out_kernel,
                         cudaFuncAttributeMaxDynamicSharedMemorySize, GEMM_SMEM);
    cudaFuncSetAttribute(attn_mma_kernel,
                         cudaFuncAttributeMaxDynamicSharedMemorySize, ATTN_SMEM);

    // 1. pack mask
    mask_pack_kernel<<<(BATCH*SEQ*SEQ/64)/256, 256>>>((const int4*)mask,
        (unsigned long long*)p_bm);

    // 2. split all to fp16
    SplitAll sa;
    sa.src[0] = (const float4*)q;  sa.src[1] = (const float4*)k;
    sa.src[2] = (const float4*)v;
    sa.src[3] = (const float4*)Wq; sa.src[4] = (const float4*)Wk;
    sa.src[5] = (const float4*)Wv; sa.src[6] = (const float4*)Wo;
    for (int i = 0; i < 3; i++) sa.dst[i] = (uint32_t*)(xf + i * XN);
    for (int i = 0; i < 4; i++) sa.dst[3+i] = (uint32_t*)(wf + i * WN);
    split_all_kernel<<<SPLIT_BLOCKS, 256>>>(sa);

    // 3. fused QKV projections (Q scaled by log2e/8)
    QkvArgs qa;
    qa.a[0] = xf;          qa.a[1] = xf + XN;     qa.a[2] = xf + 2*XN;
    qa.w[0] = wf;          qa.w[1] = wf + WN;     qa.w[2] = wf + 2*WN;
    qa.bias[0] = bq; qa.bias[1] = bk; qa.bias[2] = bv;
    qa.o[0] = (uint32_t*)p_qf16;
    qa.o[1] = (uint32_t*)p_kf16;
    qa.o[2] = (uint32_t*)p_vf16;
    qa.scale[0] = 0.125f * LOG2E; qa.scale[1] = 1.0f; qa.scale[2] = 1.0f;
    dim3 gq(DMODEL / BN, MTOT / BM, 3);
    gemm_qkv_kernel<<<gq, 256, GEMM_SMEM>>>(qa);

    // 4. attention
    dim3 ag(SEQ / 128, NHEADS, BATCH);
    attn_mma_kernel<<<ag, 256, ATTN_SMEM>>>(
        (const __nv_bfloat16*)p_qf16, (const __nv_bfloat16*)p_kf16,
        (const __nv_bfloat16*)p_vf16,
        (const unsigned long long*)p_bm, (uint32_t*)p_jf16);

    // 5. output projection (fp32 out)
    dim3 gg(DMODEL / BN, MTOT / BM);
    gemm_out_kernel<<<gg, 256, GEMM_SMEM>>>(
        (const __nv_bfloat16*)p_jf16, wf + 3*WN, bo, out);
}

// round 14
// speedup vs baseline: 2.1903x; 1.0861x over previous
#include <cuda_runtime.h>
#include <cuda_bf16.h>
#include <cuda_fp16.h>
#include <cstdint>
#include <math.h>

#define BATCH 2
#define SEQ   2048
#define DMODEL 1024
#define NHEADS 16
#define HDIM  64
#define MTOT  (BATCH*SEQ)   // 4096
#define LOG2E 1.44269504088896f

// ---------------- scratch (allocation-free rule: device globals) -----------
__device__ __nv_bfloat16 g_xf16[3*MTOT*DMODEL];    // fp16: q,k,v inputs
__device__ __nv_bfloat16 g_wf16[4*DMODEL*DMODEL];  // fp16: Wq,Wk,Wv,Wo
__device__ __nv_bfloat16 g_qf16[MTOT*DMODEL];      // fp16 (scaled Q)
__device__ __nv_bfloat16 g_kf16[MTOT*DMODEL];      // fp16 K
__device__ __nv_bfloat16 g_vf16[MTOT*DMODEL];      // fp16 V
__device__ __nv_bfloat16 g_jf16[MTOT*DMODEL];      // fp16 joint
__device__ unsigned long long g_maskbits[(size_t)BATCH*SEQ*SEQ/64];

// ---------------- helpers ---------------------------------------------------
__device__ __forceinline__ uint32_t smem_u32(const void* p) {
    uint32_t a;
    asm("{ .reg .u64 t; cvta.to.shared.u64 t, %1; cvt.u32.u64 %0, t; }"
        : "=r"(a) : "l"(p));
    return a;
}
__device__ __forceinline__ void cp16(uint32_t s, const void* g) {
    asm volatile("cp.async.cg.shared.global [%0], [%1], 16;" :: "r"(s), "l"(g));
}
#define CP_COMMIT()  asm volatile("cp.async.commit_group;" ::: "memory")
#define CP_WAIT(n)   asm volatile("cp.async.wait_group %0;" :: "n"(n) : "memory")

__device__ __forceinline__ void ldsm_x4(uint32_t* r, uint32_t addr) {
    asm volatile("ldmatrix.sync.aligned.m8n8.x4.shared.b16 {%0,%1,%2,%3}, [%4];"
                 : "=r"(r[0]), "=r"(r[1]), "=r"(r[2]), "=r"(r[3]) : "r"(addr));
}
__device__ __forceinline__ void ldsm_x4_t(uint32_t* r, uint32_t addr) {
    asm volatile("ldmatrix.sync.aligned.m8n8.x4.trans.shared.b16 {%0,%1,%2,%3}, [%4];"
                 : "=r"(r[0]), "=r"(r[1]), "=r"(r[2]), "=r"(r[3]) : "r"(addr));
}
__device__ __forceinline__ void mma16816h(float* d, const uint32_t* a,
                                          const uint32_t* b) {
    asm volatile(
        "mma.sync.aligned.m16n8k16.row.col.f32.f16.f16.f32 "
        "{%0,%1,%2,%3}, {%4,%5,%6,%7}, {%8,%9}, {%0,%1,%2,%3};"
        : "+f"(d[0]), "+f"(d[1]), "+f"(d[2]), "+f"(d[3])
        : "r"(a[0]), "r"(a[1]), "r"(a[2]), "r"(a[3]), "r"(b[0]), "r"(b[1]));
}
__device__ __forceinline__ uint32_t pack_f16(float x, float y) {
    __half2 h = __floats2half2_rn(x, y);
    return *reinterpret_cast<uint32_t*>(&h);
}

// ---------------------------------------------------------------------------
// split_all: all 7 tensors -> fp16 single
// ---------------------------------------------------------------------------
struct SplitAll {
    const float4* src[7];
    uint32_t* dst[7];
};
#define NX_BLK 4096
#define NW_BLK 1024
#define SPLIT_BLOCKS (3*NX_BLK + 4*NW_BLK)

__global__ __launch_bounds__(256)
void split_all_kernel(SplitAll a)
{
    int bid = blockIdx.x;
    int seg, idx;
    if (bid < 3 * NX_BLK) { seg = bid / NX_BLK; idx = (bid % NX_BLK) * 256 + threadIdx.x; }
    else { int r = bid - 3 * NX_BLK; seg = 3 + r / NW_BLK; idx = (r % NW_BLK) * 256 + threadIdx.x; }
    float4 v = a.src[seg][idx];
    uint32_t* dst = a.dst[seg];
    dst[2*idx]   = pack_f16(v.x, v.y);
    dst[2*idx+1] = pack_f16(v.z, v.w);
}

// ---------------------------------------------------------------------------
// mask pack
// ---------------------------------------------------------------------------
__global__ __launch_bounds__(256)
void mask_pack_kernel(const int4* __restrict__ mask, unsigned long long* __restrict__ bm)
{
    int i = blockIdx.x * 256 + threadIdx.x;
    const int4* p = mask + (size_t)i * 16;
    unsigned long long w = 0;
    #pragma unroll
    for (int j = 0; j < 16; j++) {
        int4 v = p[j];
        w |= ((unsigned long long)(v.x != 0)) << (j*4);
        w |= ((unsigned long long)(v.y != 0)) << (j*4+1);
        w |= ((unsigned long long)(v.z != 0)) << (j*4+2);
        w |= ((unsigned long long)(v.w != 0)) << (j*4+3);
    }
    bm[i] = w;
}

// ---------------------------------------------------------------------------
// GEMM body: A fp16 x W fp16 -> 1 MMA. CTA 128x128, BK=64.
// 8 warps as 2m x 4n (warp tile 64x32, 64 accum regs) -> 2 CTAs/SM.
// omode: 0=fp32 out, 2=f16 single out (scaled)
// ---------------------------------------------------------------------------
#define BM 128
#define BN 128
#define BK 64
#define NCHUNK (DMODEL / BK)          // 16
#define GROWB 144                     // 64 f16 = 128B + 16B pad
#define G_MAT_B (128 * GROWB)         // 18432
#define OFF_A  0
#define OFF_B  G_MAT_B
#define STAGE_B (2 * G_MAT_B)         // 36864
#define GEMM_SMEM (2 * STAGE_B)       // 73728

__device__ __forceinline__ void gemm_body(
    const __nv_bfloat16* __restrict__ Af,
    const __nv_bfloat16* __restrict__ Wf,
    const float* __restrict__ bias,
    float* __restrict__ outf, uint32_t* __restrict__ outh,
    float scale, int omode, uint32_t sbase)
{
    const int tid  = threadIdx.x;
    const int lane = tid & 31;
    const int wid  = tid >> 5;
    const int wm   = (wid & 1) * 64;     // 2 m-warps (64 rows)
    const int wn   = (wid >> 1) * 32;    // 4 n-warps (32 cols)
    const int n0   = blockIdx.x * BN;
    const int m0   = blockIdx.y * BM;

    float c[4][4][4];
    #pragma unroll
    for (int mt = 0; mt < 4; mt++)
        #pragma unroll
        for (int nt = 0; nt < 4; nt++)
            #pragma unroll
            for (int j = 0; j < 4; j++) c[mt][nt][j] = 0.0f;

    auto load_chunk = [&](int ck, int s) {
        uint32_t st = sbase + s * STAGE_B;
        int k0 = ck * BK;
        #pragma unroll
        for (int u = tid; u < 1024; u += 256) {      // A: 128 x 64 f16
            int r = u >> 3, c16 = u & 7;
            uint32_t d = st + r * GROWB + c16 * 16;
            size_t g = (size_t)(m0 + r) * DMODEL + k0 + c16 * 8;
            cp16(d + OFF_A, Af + g);
        }
        #pragma unroll
        for (int u = tid; u < 1024; u += 256) {      // W: 128 x 64 f16
            int r = u >> 3, c16 = u & 7;
            uint32_t d = st + r * GROWB + c16 * 16;
            size_t g = (size_t)(n0 + r) * DMODEL + k0 + c16 * 8;
            cp16(d + OFF_B, Wf + g);
        }
    };

    load_chunk(0, 0); CP_COMMIT();

    const int a_row  = lane & 15;
    const int a_kb   = ((lane >> 4) & 1) * 16;
    const int b_row  = (lane & 7) + ((lane >> 4) & 1) * 8;
    const int b_kb   = ((lane >> 3) & 1) * 16;

    for (int ck = 0; ck < NCHUNK; ck++) {
        int s = ck & 1;
        if (ck + 1 < NCHUNK) {
            load_chunk(ck + 1, s ^ 1); CP_COMMIT();
            CP_WAIT(1);
        } else {
            CP_WAIT(0);
        }
        __syncthreads();

        uint32_t st = sbase + s * STAGE_B;
        #pragma unroll
        for (int ks = 0; ks < 4; ks++) {          // 4 k16 steps in BK=64
            int kb = ks * 32;
            uint32_t ah[4][4];
            #pragma unroll
            for (int mt = 0; mt < 4; mt++) {
                uint32_t addr = st + OFF_A + (wm + mt * 16 + a_row) * GROWB + kb + a_kb;
                ldsm_x4(ah[mt], addr);
            }
            #pragma unroll
            for (int np = 0; np < 2; np++) {      // n32 = 2 ldsm (k16 x n16)
                uint32_t bh4[4];
                uint32_t addr = st + OFF_B + (wn + np * 16 + b_row) * GROWB + kb + b_kb;
                ldsm_x4(bh4, addr);
                #pragma unroll
                for (int mt = 0; mt < 4; mt++) {
                    mma16816h(c[mt][np*2],   ah[mt], bh4);
                    mma16816h(c[mt][np*2+1], ah[mt], bh4 + 2);
                }
            }
        }
        __syncthreads();
    }

    const int g  = lane >> 2;
    const int cq = (lane & 3) * 2;
    #pragma unroll
    for (int mt = 0; mt < 4; mt++) {
        #pragma unroll
        for (int nt = 0; nt < 4; nt++) {
            int col = n0 + wn + nt * 8 + cq;
            float2 bv = *(const float2*)(bias + col);
            int r0 = m0 + wm + mt * 16 + g;
            float x0 = c[mt][nt][0] + bv.x, y0 = c[mt][nt][1] + bv.y;
            float x1 = c[mt][nt][2] + bv.x, y1 = c[mt][nt][3] + bv.y;
            if (omode == 0) {
                *(float2*)(outf + (size_t)r0 * DMODEL + col) = make_float2(x0, y0);
                *(float2*)(outf + (size_t)(r0 + 8) * DMODEL + col) = make_float2(x1, y1);
            } else {
                outh[((size_t)r0 * DMODEL + col) >> 1] = pack_f16(x0 * scale, y0 * scale);
                outh[(((size_t)(r0 + 8)) * DMODEL + col) >> 1] = pack_f16(x1 * scale, y1 * scale);
            }
        }
    }
}

struct QkvArgs {
    const __nv_bfloat16* a[3];
    const __nv_bfloat16* w[3];
    const float* bias[3];
    uint32_t* o[3];
    float scale[3];
};

__global__ __launch_bounds__(256, 2)
void gemm_qkv_kernel(QkvArgs a)
{
    extern __shared__ char smraw[];
    int z = blockIdx.z;
    gemm_body(a.a[z], a.w[z], a.bias[z], nullptr, a.o[z], a.scale[z], 2,
              smem_u32(smraw));
}

__global__ __launch_bounds__(256, 2)
void gemm_out_kernel(const __nv_bfloat16* __restrict__ Af,
                     const __nv_bfloat16* __restrict__ Wf,
                     const float* __restrict__ bias, float* __restrict__ outf)
{
    extern __shared__ char smraw[];
    gemm_body(Af, Wf, bias, outf, nullptr, 1.0f, 0, smem_u32(smraw));
}

// ---------------------------------------------------------------------------
// FA2 attention (unchanged from R13): all fp16, KV tile 128, 2-stage pipeline.
// ---------------------------------------------------------------------------
#define AROWB 144
#define AQ_B   (128 * AROWB)
#define AKV_B  (128 * AROWB)
#define A_OFF_K  0
#define A_OFF_V  AKV_B
#define A_STAGE_B (2 * AKV_B)
#define ATTN_SMEM (AQ_B + 2 * A_STAGE_B)   // 92160
#define NKT (SEQ / 128)
#define MWORDS (SEQ / 64)

__global__ __launch_bounds__(256, 1)
void attn_mma_kernel(const __nv_bfloat16* __restrict__ qf16,
                     const __nv_bfloat16* __restrict__ kf16,
                     const __nv_bfloat16* __restrict__ vf16,
                     const unsigned long long* __restrict__ bm,
                     uint32_t* __restrict__ jf)
{
    extern __shared__ char smraw[];
    const uint32_t sbase = smem_u32(smraw);
    const int tid  = threadIdx.x;
    const int lane = tid & 31;
    const int wid  = tid >> 5;
    const int wm   = wid * 16;
    const int b    = blockIdx.z;
    const int h    = blockIdx.y;
    const int q0   = blockIdx.x * 128;

    #pragma unroll
    for (int u = tid; u < 1024; u += 256) {
        int r = u >> 3, c16 = u & 7;
        uint32_t d = sbase + r * AROWB + c16 * 16;
        size_t g = ((size_t)(b * SEQ + q0 + r)) * DMODEL + h * HDIM + c16 * 8;
        cp16(d, qf16 + g);
    }
    CP_COMMIT();

    auto load_kv = [&](int kt, int s) {
        uint32_t st = sbase + AQ_B + s * A_STAGE_B;
        int k0 = kt * 128;
        #pragma unroll
        for (int u = tid; u < 1024; u += 256) {
            int r = u >> 3, c16 = u & 7;
            uint32_t d = st + r * AROWB + c16 * 16;
            size_t g = ((size_t)(b * SEQ + k0 + r)) * DMODEL + h * HDIM + c16 * 8;
            cp16(d + A_OFF_K, kf16 + g);
            cp16(d + A_OFF_V, vf16 + g);
        }
    };

    load_kv(0, 0); CP_COMMIT();
    CP_WAIT(1);
    __syncthreads();

    uint32_t aq[4][4];
    {
        const int a_row = lane & 15;
        const int a_kb  = ((lane >> 4) & 1) * 16;
        #pragma unroll
        for (int kc = 0; kc < 4; kc++) {
            uint32_t addr = sbase + (wm + a_row) * AROWB + kc * 32 + a_kb;
            ldsm_x4(aq[kc], addr);
        }
    }

    const int g_    = lane >> 2;
    const int cq    = (lane & 3) * 2;
    const int b_row = (lane & 7) + ((lane >> 4) & 1) * 8;
    const int b_kb  = ((lane >> 3) & 1) * 16;
    const int v_row = lane & 15;
    const int v_col = (lane >> 4) * 8;

    const size_t bmrow0 = ((size_t)b * SEQ + q0 + wm + g_) * MWORDS;
    const size_t bmrow1 = bmrow0 + (size_t)8 * MWORDS;

    float o[8][4];
    #pragma unroll
    for (int i = 0; i < 8; i++)
        #pragma unroll
        for (int j = 0; j < 4; j++) o[i][j] = 0.0f;
    float m0r = -INFINITY, m1r = -INFINITY, l0r = 0.0f, l1r = 0.0f;

    for (int kt = 0; kt < NKT; kt++) {
        int s = kt & 1;
        __syncthreads();
        if (kt + 1 < NKT) {
            load_kv(kt + 1, s ^ 1); CP_COMMIT();
            CP_WAIT(1);
        } else {
            CP_WAIT(0);
        }
        __syncthreads();

        uint32_t st = sbase + AQ_B + s * A_STAGE_B;

        unsigned long long mw0a = __ldg(bm + bmrow0 + 2*kt);
        unsigned long long mw0b = __ldg(bm + bmrow0 + 2*kt + 1);
        unsigned long long mw1a = __ldg(bm + bmrow1 + 2*kt);
        unsigned long long mw1b = __ldg(bm + bmrow1 + 2*kt + 1);

        float sc[16][4];
        #pragma unroll
        for (int i = 0; i < 16; i++)
            #pragma unroll
            for (int j = 0; j < 4; j++) sc[i][j] = 0.0f;

        #pragma unroll
        for (int kc = 0; kc < 4; kc++) {
            #pragma unroll
            for (int np = 0; np < 8; np++) {
                uint32_t kh4[4];
                uint32_t addr = st + A_OFF_K + (np * 16 + b_row) * AROWB + kc * 32 + b_kb;
                ldsm_x4(kh4, addr);
                mma16816h(sc[np*2],   aq[kc], kh4);
                mma16816h(sc[np*2+1], aq[kc], kh4 + 2);
            }
        }

        #pragma unroll
        for (int nt = 0; nt < 16; nt++) {
            unsigned long long w0 = (nt < 8) ? mw0a : mw0b;
            unsigned long long w1 = (nt < 8) ? mw1a : mw1b;
            int c0 = (nt & 7) * 8 + cq;
            if (!((w0 >> c0) & 1))       sc[nt][0] = -1000000000.0f;
            if (!((w0 >> (c0 + 1)) & 1)) sc[nt][1] = -1000000000.0f;
            if (!((w1 >> c0) & 1))       sc[nt][2] = -1000000000.0f;
            if (!((w1 >> (c0 + 1)) & 1)) sc[nt][3] = -1000000000.0f;
        }

        float mx0 = sc[0][0], mx1 = sc[0][2];
        #pragma unroll
        for (int nt = 0; nt < 16; nt++) {
            mx0 = fmaxf(mx0, fmaxf(sc[nt][0], sc[nt][1]));
            mx1 = fmaxf(mx1, fmaxf(sc[nt][2], sc[nt][3]));
        }
        mx0 = fmaxf(mx0, __shfl_xor_sync(0xffffffff, mx0, 1));
        mx0 = fmaxf(mx0, __shfl_xor_sync(0xffffffff, mx0, 2));
        mx1 = fmaxf(mx1, __shfl_xor_sync(0xffffffff, mx1, 1));
        mx1 = fmaxf(mx1, __shfl_xor_sync(0xffffffff, mx1, 2));

        float mn0 = fmaxf(m0r, mx0), mn1 = fmaxf(m1r, mx1);
        float al0 = exp2f(m0r - mn0), al1 = exp2f(m1r - mn1);
        m0r = mn0; m1r = mn1;

        float rs0 = 0.0f, rs1 = 0.0f;
        #pragma unroll
        for (int nt = 0; nt < 16; nt++) {
            sc[nt][0] = exp2f(sc[nt][0] - mn0); rs0 += sc[nt][0];
            sc[nt][1] = exp2f(sc[nt][1] - mn0); rs0 += sc[nt][1];
            sc[nt][2] = exp2f(sc[nt][2] - mn1); rs1 += sc[nt][2];
            sc[nt][3] = exp2f(sc[nt][3] - mn1); rs1 += sc[nt][3];
        }
        rs0 += __shfl_xor_sync(0xffffffff, rs0, 1);
        rs0 += __shfl_xor_sync(0xffffffff, rs0, 2);
        rs1 += __shfl_xor_sync(0xffffffff, rs1, 1);
        rs1 += __shfl_xor_sync(0xffffffff, rs1, 2);
        l0r = l0r * al0 + rs0;
        l1r = l1r * al1 + rs1;

        #pragma unroll
        for (int nt = 0; nt < 8; nt++) {
            o[nt][0] *= al0; o[nt][1] *= al0;
            o[nt][2] *= al1; o[nt][3] *= al1;
        }

        uint32_t ph[8][4];
        #pragma unroll
        for (int tp = 0; tp < 8; tp++) {
            ph[tp][0] = pack_f16(sc[2*tp][0],   sc[2*tp][1]);
            ph[tp][1] = pack_f16(sc[2*tp][2],   sc[2*tp][3]);
            ph[tp][2] = pack_f16(sc[2*tp+1][0], sc[2*tp+1][1]);
            ph[tp][3] = pack_f16(sc[2*tp+1][2], sc[2*tp+1][3]);
        }

        #pragma unroll
        for (int nt2 = 0; nt2 < 4; nt2++) {
            #pragma unroll
            for (int tp = 0; tp < 8; tp++) {
                uint32_t vh4[4];
                uint32_t addr = st + A_OFF_V + (tp * 16 + v_row) * AROWB
                              + (nt2 * 16 + v_col) * 2;
                ldsm_x4_t(vh4, addr);
                mma16816h(o[nt2*2],   ph[tp], vh4);
                mma16816h(o[nt2*2+1], ph[tp], vh4 + 2);
            }
        }
    }

    float inv0 = 1.0f / l0r, inv1 = 1.0f / l1r;
    size_t row0 = ((size_t)(b * SEQ + q0 + wm + g_)) * DMODEL + h * HDIM;
    #pragma unroll
    for (int nt = 0; nt < 8; nt++) {
        int col = nt * 8 + cq;
        jf[(row0 + col) >> 1] = pack_f16(o[nt][0] * inv0, o[nt][1] * inv0);
        jf[(row0 + (size_t)8 * DMODEL + col) >> 1] =
            pack_f16(o[nt][2] * inv1, o[nt][3] * inv1);
    }
}

// ---------------------------------------------------------------------------
extern "C" void kernel_launch(void* const* d_in, const int* in_sizes, int n_in,
                              void* d_out, int out_size)
{
    const float* q    = (const float*)d_in[0];
    const float* k    = (const float*)d_in[1];
    const float* v    = (const float*)d_in[2];
    const int*   mask = (const int*)  d_in[3];
    const float* Wq   = (const float*)d_in[4];
    const float* bq   = (const float*)d_in[5];
    const float* Wk   = (const float*)d_in[6];
    const float* bk   = (const float*)d_in[7];
    const float* Wv   = (const float*)d_in[8];
    const float* bv   = (const float*)d_in[9];
    const float* Wo   = (const float*)d_in[10];
    const float* bo   = (const float*)d_in[11];
    float* out = (float*)d_out;

    void *p_xf16, *p_wf16, *p_qf16, *p_kf16, *p_vf16, *p_jf16, *p_bm;
    cudaGetSymbolAddress(&p_xf16, g_xf16);
    cudaGetSymbolAddress(&p_wf16, g_wf16);
    cudaGetSymbolAddress(&p_qf16, g_qf16);
    cudaGetSymbolAddress(&p_kf16, g_kf16);
    cudaGetSymbolAddress(&p_vf16, g_vf16);
    cudaGetSymbolAddress(&p_jf16, g_jf16);
    cudaGetSymbolAddress(&p_bm, g_maskbits);

    __nv_bfloat16* xf = (__nv_bfloat16*)p_xf16;
    __nv_bfloat16* wf = (__nv_bfloat16*)p_wf16;

    const size_t XN = (size_t)MTOT * DMODEL;
    const size_t WN = (size_t)DMODEL * DMODEL;

    cudaFuncSetAttribute(gemm_qkv_kernel,
                         cudaFuncAttributeMaxDynamicSharedMemorySize, GEMM_SMEM);
    cudaFuncSetAttribute(gemm_out_kernel,
                         cudaFuncAttributeMaxDynamicSharedMemorySize, GEMM_SMEM);
    cudaFuncSetAttribute(attn_mma_kernel,
                         cudaFuncAttributeMaxDynamicSharedMemorySize, ATTN_SMEM);

    // 1. pack mask
    mask_pack_kernel<<<(BATCH*SEQ*SEQ/64)/256, 256>>>((const int4*)mask,
        (unsigned long long*)p_bm);

    // 2. split all to fp16
    SplitAll sa;
    sa.src[0] = (const float4*)q;  sa.src[1] = (const float4*)k;
    sa.src[2] = (const float4*)v;
    sa.src[3] = (const float4*)Wq; sa.src[4] = (const float4*)Wk;
    sa.src[5] = (const float4*)Wv; sa.src[6] = (const float4*)Wo;
    for (int i = 0; i < 3; i++) sa.dst[i] = (uint32_t*)(xf + i * XN);
    for (int i = 0; i < 4; i++) sa.dst[3+i] = (uint32_t*)(wf + i * WN);
    split_all_kernel<<<SPLIT_BLOCKS, 256>>>(sa);

    // 3. fused QKV projections (Q scaled by log2e/8)
    QkvArgs qa;
    qa.a[0] = xf;          qa.a[1] = xf + XN;     qa.a[2] = xf + 2*XN;
    qa.w[0] = wf;          qa.w[1] = wf + WN;     qa.w[2] = wf + 2*WN;
    qa.bias[0] = bq; qa.bias[1] = bk; qa.bias[2] = bv;
    qa.o[0] = (uint32_t*)p_qf16;
    qa.o[1] = (uint32_t*)p_kf16;
    qa.o[2] = (uint32_t*)p_vf16;
    qa.scale[0] = 0.125f * LOG2E; qa.scale[1] = 1.0f; qa.scale[2] = 1.0f;
    dim3 gq(DMODEL / BN, MTOT / BM, 3);   // 8 x 32 x 3
    gemm_qkv_kernel<<<gq, 256, GEMM_SMEM>>>(qa);

    // 4. attention
    dim3 ag(SEQ / 128, NHEADS, BATCH);
    attn_mma_kernel<<<ag, 256, ATTN_SMEM>>>(
        (const __nv_bfloat16*)p_qf16, (const __nv_bfloat16*)p_kf16,
        (const __nv_bfloat16*)p_vf16,
        (const unsigned long long*)p_bm, (uint32_t*)p_jf16);

    // 5. output projection (fp32 out)
    dim3 gg(DMODEL / BN, MTOT / BM);      // 8 x 32
    gemm_out_kernel<<<gg, 256, GEMM_SMEM>>>(
        (const __nv_bfloat16*)p_jf16, wf + 3*WN, bo, out);
}

// round 15
// speedup vs baseline: 2.2910x; 1.0460x over previous
#include <cuda_runtime.h>
#include <cuda_bf16.h>
#include <cuda_fp16.h>
#include <cstdint>
#include <math.h>

#define BATCH 2
#define SEQ   2048
#define DMODEL 1024
#define NHEADS 16
#define HDIM  64
#define MTOT  (BATCH*SEQ)   // 4096
#define LOG2E 1.44269504088896f

// ---------------- scratch (allocation-free rule: device globals) -----------
__device__ __nv_bfloat16 g_xf16[3*MTOT*DMODEL];    // fp16: q,k,v inputs
__device__ __nv_bfloat16 g_wf16[4*DMODEL*DMODEL];  // fp16: Wq,Wk,Wv,Wo
__device__ __nv_bfloat16 g_qf16[MTOT*DMODEL];      // fp16 (scaled Q)
__device__ __nv_bfloat16 g_kf16[MTOT*DMODEL];      // fp16 K
__device__ __nv_bfloat16 g_vf16[MTOT*DMODEL];      // fp16 V
__device__ __nv_bfloat16 g_jf16[MTOT*DMODEL];      // fp16 joint
__device__ unsigned long long g_maskbits[(size_t)BATCH*SEQ*SEQ/64];

// ---------------- helpers ---------------------------------------------------
__device__ __forceinline__ uint32_t smem_u32(const void* p) {
    uint32_t a;
    asm("{ .reg .u64 t; cvta.to.shared.u64 t, %1; cvt.u32.u64 %0, t; }"
        : "=r"(a) : "l"(p));
    return a;
}
__device__ __forceinline__ void cp16(uint32_t s, const void* g) {
    asm volatile("cp.async.cg.shared.global [%0], [%1], 16;" :: "r"(s), "l"(g));
}
#define CP_COMMIT()  asm volatile("cp.async.commit_group;" ::: "memory")
#define CP_WAIT(n)   asm volatile("cp.async.wait_group %0;" :: "n"(n) : "memory")

__device__ __forceinline__ void ldsm_x4(uint32_t* r, uint32_t addr) {
    asm volatile("ldmatrix.sync.aligned.m8n8.x4.shared.b16 {%0,%1,%2,%3}, [%4];"
                 : "=r"(r[0]), "=r"(r[1]), "=r"(r[2]), "=r"(r[3]) : "r"(addr));
}
__device__ __forceinline__ void ldsm_x4_t(uint32_t* r, uint32_t addr) {
    asm volatile("ldmatrix.sync.aligned.m8n8.x4.trans.shared.b16 {%0,%1,%2,%3}, [%4];"
                 : "=r"(r[0]), "=r"(r[1]), "=r"(r[2]), "=r"(r[3]) : "r"(addr));
}
__device__ __forceinline__ void ldsm_x2_t(uint32_t* r, uint32_t addr) {
    asm volatile("ldmatrix.sync.aligned.m8n8.x2.trans.shared.b16 {%0,%1}, [%2];"
                 : "=r"(r[0]), "=r"(r[1]) : "r"(addr));
}
__device__ __forceinline__ void mma16816h(float* d, const uint32_t* a,
                                          const uint32_t* b) {
    asm volatile(
        "mma.sync.aligned.m16n8k16.row.col.f32.f16.f16.f32 "
        "{%0,%1,%2,%3}, {%4,%5,%6,%7}, {%8,%9}, {%0,%1,%2,%3};"
        : "+f"(d[0]), "+f"(d[1]), "+f"(d[2]), "+f"(d[3])
        : "r"(a[0]), "r"(a[1]), "r"(a[2]), "r"(a[3]), "r"(b[0]), "r"(b[1]));
}
__device__ __forceinline__ uint32_t pack_f16(float x, float y) {
    __half2 h = __floats2half2_rn(x, y);
    return *reinterpret_cast<uint32_t*>(&h);
}
__device__ __forceinline__ uint32_t h2ex2(uint32_t h) {
    uint32_t r;
    asm("ex2.approx.f16x2 %0, %1;" : "=r"(r) : "r"(h));
    return r;
}

// ---------------------------------------------------------------------------
// split_all: all 7 tensors -> fp16 single
// ---------------------------------------------------------------------------
struct SplitAll {
    const float4* src[7];
    uint32_t* dst[7];
};
#define NX_BLK 4096
#define NW_BLK 1024
#define SPLIT_BLOCKS (3*NX_BLK + 4*NW_BLK)

__global__ __launch_bounds__(256)
void split_all_kernel(SplitAll a)
{
    int bid = blockIdx.x;
    int seg, idx;
    if (bid < 3 * NX_BLK) { seg = bid / NX_BLK; idx = (bid % NX_BLK) * 256 + threadIdx.x; }
    else { int r = bid - 3 * NX_BLK; seg = 3 + r / NW_BLK; idx = (r % NW_BLK) * 256 + threadIdx.x; }
    float4 v = a.src[seg][idx];
    uint32_t* dst = a.dst[seg];
    dst[2*idx]   = pack_f16(v.x, v.y);
    dst[2*idx+1] = pack_f16(v.z, v.w);
}

// ---------------------------------------------------------------------------
// mask pack
// ---------------------------------------------------------------------------
__global__ __launch_bounds__(256)
void mask_pack_kernel(const int4* __restrict__ mask, unsigned long long* __restrict__ bm)
{
    int i = blockIdx.x * 256 + threadIdx.x;
    const int4* p = mask + (size_t)i * 16;
    unsigned long long w = 0;
    #pragma unroll
    for (int j = 0; j < 16; j++) {
        int4 v = p[j];
        w |= ((unsigned long long)(v.x != 0)) << (j*4);
        w |= ((unsigned long long)(v.y != 0)) << (j*4+1);
        w |= ((unsigned long long)(v.z != 0)) << (j*4+2);
        w |= ((unsigned long long)(v.w != 0)) << (j*4+3);
    }
    bm[i] = w;
}

// ---------------------------------------------------------------------------
// GEMM body: A fp16 x W fp16 -> 1 MMA. CTA 128x128, BK=64.
// 8 warps as 2m x 4n (warp tile 64x32) -> 2 CTAs/SM.
// ---------------------------------------------------------------------------
#define BM 128
#define BN 128
#define BK 64
#define NCHUNK (DMODEL / BK)
#define GROWB 144
#define G_MAT_B (128 * GROWB)
#define OFF_A  0
#define OFF_B  G_MAT_B
#define STAGE_B (2 * G_MAT_B)
#define GEMM_SMEM (2 * STAGE_B)

__device__ __forceinline__ void gemm_body(
    const __nv_bfloat16* __restrict__ Af,
    const __nv_bfloat16* __restrict__ Wf,
    const float* __restrict__ bias,
    float* __restrict__ outf, uint32_t* __restrict__ outh,
    float scale, int omode, uint32_t sbase)
{
    const int tid  = threadIdx.x;
    const int lane = tid & 31;
    const int wid  = tid >> 5;
    const int wm   = (wid & 1) * 64;
    const int wn   = (wid >> 1) * 32;
    const int n0   = blockIdx.x * BN;
    const int m0   = blockIdx.y * BM;

    float c[4][4][4];
    #pragma unroll
    for (int mt = 0; mt < 4; mt++)
        #pragma unroll
        for (int nt = 0; nt < 4; nt++)
            #pragma unroll
            for (int j = 0; j < 4; j++) c[mt][nt][j] = 0.0f;

    auto load_chunk = [&](int ck, int s) {
        uint32_t st = sbase + s * STAGE_B;
        int k0 = ck * BK;
        #pragma unroll
        for (int u = tid; u < 1024; u += 256) {
            int r = u >> 3, c16 = u & 7;
            uint32_t d = st + r * GROWB + c16 * 16;
            size_t g = (size_t)(m0 + r) * DMODEL + k0 + c16 * 8;
            cp16(d + OFF_A, Af + g);
        }
        #pragma unroll
        for (int u = tid; u < 1024; u += 256) {
            int r = u >> 3, c16 = u & 7;
            uint32_t d = st + r * GROWB + c16 * 16;
            size_t g = (size_t)(n0 + r) * DMODEL + k0 + c16 * 8;
            cp16(d + OFF_B, Wf + g);
        }
    };

    load_chunk(0, 0); CP_COMMIT();

    const int a_row  = lane & 15;
    const int a_kb   = ((lane >> 4) & 1) * 16;
    const int b_row  = (lane & 7) + ((lane >> 4) & 1) * 8;
    const int b_kb   = ((lane >> 3) & 1) * 16;

    for (int ck = 0; ck < NCHUNK; ck++) {
        int s = ck & 1;
        if (ck + 1 < NCHUNK) {
            load_chunk(ck + 1, s ^ 1); CP_COMMIT();
            CP_WAIT(1);
        } else {
            CP_WAIT(0);
        }
        __syncthreads();

        uint32_t st = sbase + s * STAGE_B;
        #pragma unroll
        for (int ks = 0; ks < 4; ks++) {
            int kb = ks * 32;
            uint32_t ah[4][4];
            #pragma unroll
            for (int mt = 0; mt < 4; mt++) {
                uint32_t addr = st + OFF_A + (wm + mt * 16 + a_row) * GROWB + kb + a_kb;
                ldsm_x4(ah[mt], addr);
            }
            #pragma unroll
            for (int np = 0; np < 2; np++) {
                uint32_t bh4[4];
                uint32_t addr = st + OFF_B + (wn + np * 16 + b_row) * GROWB + kb + b_kb;
                ldsm_x4(bh4, addr);
                #pragma unroll
                for (int mt = 0; mt < 4; mt++) {
                    mma16816h(c[mt][np*2],   ah[mt], bh4);
                    mma16816h(c[mt][np*2+1], ah[mt], bh4 + 2);
                }
            }
        }
        __syncthreads();
    }

    const int g  = lane >> 2;
    const int cq = (lane & 3) * 2;
    #pragma unroll
    for (int mt = 0; mt < 4; mt++) {
        #pragma unroll
        for (int nt = 0; nt < 4; nt++) {
            int col = n0 + wn + nt * 8 + cq;
            float2 bv = *(const float2*)(bias + col);
            int r0 = m0 + wm + mt * 16 + g;
            float x0 = c[mt][nt][0] + bv.x, y0 = c[mt][nt][1] + bv.y;
            float x1 = c[mt][nt][2] + bv.x, y1 = c[mt][nt][3] + bv.y;
            if (omode == 0) {
                *(float2*)(outf + (size_t)r0 * DMODEL + col) = make_float2(x0, y0);
                *(float2*)(outf + (size_t)(r0 + 8) * DMODEL + col) = make_float2(x1, y1);
            } else {
                outh[((size_t)r0 * DMODEL + col) >> 1] = pack_f16(x0 * scale, y0 * scale);
                outh[(((size_t)(r0 + 8)) * DMODEL + col) >> 1] = pack_f16(x1 * scale, y1 * scale);
            }
        }
    }
}

struct QkvArgs {
    const __nv_bfloat16* a[3];
    const __nv_bfloat16* w[3];
    const float* bias[3];
    uint32_t* o[3];
    float scale[3];
};

__global__ __launch_bounds__(256, 2)
void gemm_qkv_kernel(QkvArgs a)
{
    extern __shared__ char smraw[];
    int z = blockIdx.z;
    gemm_body(a.a[z], a.w[z], a.bias[z], nullptr, a.o[z], a.scale[z], 2,
              smem_u32(smraw));
}

__global__ __launch_bounds__(256, 2)
void gemm_out_kernel(const __nv_bfloat16* __restrict__ Af,
                     const __nv_bfloat16* __restrict__ Wf,
                     const float* __restrict__ bias, float* __restrict__ outf)
{
    extern __shared__ char smraw[];
    gemm_body(Af, Wf, bias, outf, nullptr, 1.0f, 0, smem_u32(smraw));
}

// ---------------------------------------------------------------------------
// FA2 attention: fp16, KV tile 128. P computed via ex2.approx.f16x2 (packed);
// row sums via extra MMA against a ones-column in the V row padding.
// ---------------------------------------------------------------------------
#define AROWB 144
#define AQ_B   (128 * AROWB)
#define AKV_B  (128 * AROWB)
#define A_OFF_K  0
#define A_OFF_V  AKV_B
#define A_STAGE_B (2 * AKV_B)
#define ATTN_SMEM (AQ_B + 2 * A_STAGE_B)   // 92160
#define NKT (SEQ / 128)
#define MWORDS (SEQ / 64)

__global__ __launch_bounds__(256, 1)
void attn_mma_kernel(const __nv_bfloat16* __restrict__ qf16,
                     const __nv_bfloat16* __restrict__ kf16,
                     const __nv_bfloat16* __restrict__ vf16,
                     const unsigned long long* __restrict__ bm,
                     uint32_t* __restrict__ jf)
{
    extern __shared__ char smraw[];
    const uint32_t sbase = smem_u32(smraw);
    const int tid  = threadIdx.x;
    const int lane = tid & 31;
    const int wid  = tid >> 5;
    const int wm   = wid * 16;
    const int b    = blockIdx.z;
    const int h    = blockIdx.y;
    const int q0   = blockIdx.x * 128;

    // ---- load Q tile ----
    #pragma unroll
    for (int u = tid; u < 1024; u += 256) {
        int r = u >> 3, c16 = u & 7;
        uint32_t d = sbase + r * AROWB + c16 * 16;
        size_t g = ((size_t)(b * SEQ + q0 + r)) * DMODEL + h * HDIM + c16 * 8;
        cp16(d, qf16 + g);
    }
    CP_COMMIT();

    // ---- init ones-column in V pad (cols 64..71 = bytes 128..143), both stages
    {
        int stg = tid >> 7, r = tid & 127;
        uint32_t d = sbase + AQ_B + stg * A_STAGE_B + A_OFF_V + r * AROWB + 128;
        uint32_t one2 = 0x3C003C00u;
        asm volatile("st.shared.v4.b32 [%0], {%1, %1, %1, %1};"
                     :: "r"(d), "r"(one2) : "memory");
    }

    auto load_kv = [&](int kt, int s) {
        uint32_t st = sbase + AQ_B + s * A_STAGE_B;
        int k0 = kt * 128;
        #pragma unroll
        for (int u = tid; u < 1024; u += 256) {
            int r = u >> 3, c16 = u & 7;
            uint32_t d = st + r * AROWB + c16 * 16;
            size_t g = ((size_t)(b * SEQ + k0 + r)) * DMODEL + h * HDIM + c16 * 8;
            cp16(d + A_OFF_K, kf16 + g);
            cp16(d + A_OFF_V, vf16 + g);
        }
    };

    load_kv(0, 0); CP_COMMIT();
    CP_WAIT(1);
    __syncthreads();

    uint32_t aq[4][4];
    {
        const int a_row = lane & 15;
        const int a_kb  = ((lane >> 4) & 1) * 16;
        #pragma unroll
        for (int kc = 0; kc < 4; kc++) {
            uint32_t addr = sbase + (wm + a_row) * AROWB + kc * 32 + a_kb;
            ldsm_x4(aq[kc], addr);
        }
    }

    const int g_    = lane >> 2;
    const int cq    = (lane & 3) * 2;
    const int b_row = (lane & 7) + ((lane >> 4) & 1) * 8;
    const int b_kb  = ((lane >> 3) & 1) * 16;
    const int v_row = lane & 15;
    const int v_col = (lane >> 4) * 8;

    const size_t bmrow0 = ((size_t)b * SEQ + q0 + wm + g_) * MWORDS;
    const size_t bmrow1 = bmrow0 + (size_t)8 * MWORDS;

    float o[8][4];
    #pragma unroll
    for (int i = 0; i < 8; i++)
        #pragma unroll
        for (int j = 0; j < 4; j++) o[i][j] = 0.0f;
    float m0r = -INFINITY, m1r = -INFINITY, l0r = 0.0f, l1r = 0.0f;

    for (int kt = 0; kt < NKT; kt++) {
        int s = kt & 1;
        __syncthreads();
        if (kt + 1 < NKT) {
            load_kv(kt + 1, s ^ 1); CP_COMMIT();
            CP_WAIT(1);
        } else {
            CP_WAIT(0);
        }
        __syncthreads();

        uint32_t st = sbase + AQ_B + s * A_STAGE_B;

        unsigned long long mw0a = __ldg(bm + bmrow0 + 2*kt);
        unsigned long long mw0b = __ldg(bm + bmrow0 + 2*kt + 1);
        unsigned long long mw1a = __ldg(bm + bmrow1 + 2*kt);
        unsigned long long mw1b = __ldg(bm + bmrow1 + 2*kt + 1);

        // ---- S = Q K^T ----
        float sc[16][4];
        #pragma unroll
        for (int i = 0; i < 16; i++)
            #pragma unroll
            for (int j = 0; j < 4; j++) sc[i][j] = 0.0f;

        #pragma unroll
        for (int kc = 0; kc < 4; kc++) {
            #pragma unroll
            for (int np = 0; np < 8; np++) {
                uint32_t kh4[4];
                uint32_t addr = st + A_OFF_K + (np * 16 + b_row) * AROWB + kc * 32 + b_kb;
                ldsm_x4(kh4, addr);
                mma16816h(sc[np*2],   aq[kc], kh4);
                mma16816h(sc[np*2+1], aq[kc], kh4 + 2);
            }
        }

        // ---- mask ----
        #pragma unroll
        for (int nt = 0; nt < 16; nt++) {
            unsigned long long w0 = (nt < 8) ? mw0a : mw0b;
            unsigned long long w1 = (nt < 8) ? mw1a : mw1b;
            int c0 = (nt & 7) * 8 + cq;
            if (!((w0 >> c0) & 1))       sc[nt][0] = -1000000000.0f;
            if (!((w0 >> (c0 + 1)) & 1)) sc[nt][1] = -1000000000.0f;
            if (!((w1 >> c0) & 1))       sc[nt][2] = -1000000000.0f;
            if (!((w1 >> (c0 + 1)) & 1)) sc[nt][3] = -1000000000.0f;
        }

        // ---- row max (base-2 domain) ----
        float mx0 = sc[0][0], mx1 = sc[0][2];
        #pragma unroll
        for (int nt = 0; nt < 16; nt++) {
            mx0 = fmaxf(mx0, fmaxf(sc[nt][0], sc[nt][1]));
            mx1 = fmaxf(mx1, fmaxf(sc[nt][2], sc[nt][3]));
        }
        mx0 = fmaxf(mx0, __shfl_xor_sync(0xffffffff, mx0, 1));
        mx0 = fmaxf(mx0, __shfl_xor_sync(0xffffffff, mx0, 2));
        mx1 = fmaxf(mx1, __shfl_xor_sync(0xffffffff, mx1, 1));
        mx1 = fmaxf(mx1, __shfl_xor_sync(0xffffffff, mx1, 2));

        float mn0 = fmaxf(m0r, mx0), mn1 = fmaxf(m1r, mx1);
        float al0 = exp2f(m0r - mn0), al1 = exp2f(m1r - mn1);
        m0r = mn0; m1r = mn1;

        // ---- P = ex2(s - mn) in packed fp16 (MUFU halved, pack fused) ----
        uint32_t ph[8][4];
        #pragma unroll
        for (int tp = 0; tp < 8; tp++) {
            ph[tp][0] = h2ex2(pack_f16(sc[2*tp][0] - mn0,   sc[2*tp][1] - mn0));
            ph[tp][1] = h2ex2(pack_f16(sc[2*tp][2] - mn1,   sc[2*tp][3] - mn1));
            ph[tp][2] = h2ex2(pack_f16(sc[2*tp+1][0] - mn0, sc[2*tp+1][1] - mn0));
            ph[tp][3] = h2ex2(pack_f16(sc[2*tp+1][2] - mn1, sc[2*tp+1][3] - mn1));
        }

        // ---- rescale O ----
        #pragma unroll
        for (int nt = 0; nt < 8; nt++) {
            o[nt][0] *= al0; o[nt][1] *= al0;
            o[nt][2] *= al1; o[nt][3] *= al1;
        }

        // ---- row sums via ones-column MMA + O += P V ----
        float lsum[4] = {0.0f, 0.0f, 0.0f, 0.0f};
        #pragma unroll
        for (int tp = 0; tp < 8; tp++) {
            uint32_t vo2[2];
            uint32_t addr1 = st + A_OFF_V + (tp * 16 + v_row) * AROWB + 128;
            ldsm_x2_t(vo2, addr1);
            mma16816h(lsum, ph[tp], vo2);
        }
        #pragma unroll
        for (int nt2 = 0; nt2 < 4; nt2++) {
            #pragma unroll
            for (int tp = 0; tp < 8; tp++) {
                uint32_t vh4[4];
                uint32_t addr = st + A_OFF_V + (tp * 16 + v_row) * AROWB
                              + (nt2 * 16 + v_col) * 2;
                ldsm_x4_t(vh4, addr);
                mma16816h(o[nt2*2],   ph[tp], vh4);
                mma16816h(o[nt2*2+1], ph[tp], vh4 + 2);
            }
        }

        l0r = l0r * al0 + lsum[0];
        l1r = l1r * al1 + lsum[2];
    }

    // ---- epilogue: joint as fp16 ----
    float inv0 = 1.0f / l0r, inv1 = 1.0f / l1r;
    size_t row0 = ((size_t)(b * SEQ + q0 + wm + g_)) * DMODEL + h * HDIM;
    #pragma unroll
    for (int nt = 0; nt < 8; nt++) {
        int col = nt * 8 + cq;
        jf[(row0 + col) >> 1] = pack_f16(o[nt][0] * inv0, o[nt][1] * inv0);
        jf[(row0 + (size_t)8 * DMODEL + col) >> 1] =
            pack_f16(o[nt][2] * inv1, o[nt][3] * inv1);
    }
}

// ---------------------------------------------------------------------------
extern "C" void kernel_launch(void* const* d_in, const int* in_sizes, int n_in,
                              void* d_out, int out_size)
{
    const float* q    = (const float*)d_in[0];
    const float* k    = (const float*)d_in[1];
    const float* v    = (const float*)d_in[2];
    const int*   mask = (const int*)  d_in[3];
    const float* Wq   = (const float*)d_in[4];
    const float* bq   = (const float*)d_in[5];
    const float* Wk   = (const float*)d_in[6];
    const float* bk   = (const float*)d_in[7];
    const float* Wv   = (const float*)d_in[8];
    const float* bv   = (const float*)d_in[9];
    const float* Wo   = (const float*)d_in[10];
    const float* bo   = (const float*)d_in[11];
    float* out = (float*)d_out;

    void *p_xf16, *p_wf16, *p_qf16, *p_kf16, *p_vf16, *p_jf16, *p_bm;
    cudaGetSymbolAddress(&p_xf16, g_xf16);
    cudaGetSymbolAddress(&p_wf16, g_wf16);
    cudaGetSymbolAddress(&p_qf16, g_qf16);
    cudaGetSymbolAddress(&p_kf16, g_kf16);
    cudaGetSymbolAddress(&p_vf16, g_vf16);
    cudaGetSymbolAddress(&p_jf16, g_jf16);
    cudaGetSymbolAddress(&p_bm, g_maskbits);

    __nv_bfloat16* xf = (__nv_bfloat16*)p_xf16;
    __nv_bfloat16* wf = (__nv_bfloat16*)p_wf16;

    const size_t XN = (size_t)MTOT * DMODEL;
    const size_t WN = (size_t)DMODEL * DMODEL;

    cudaFuncSetAttribute(gemm_qkv_kernel,
                         cudaFuncAttributeMaxDynamicSharedMemorySize, GEMM_SMEM);
    cudaFuncSetAttribute(gemm_out_kernel,
                         cudaFuncAttributeMaxDynamicSharedMemorySize, GEMM_SMEM);
    cudaFuncSetAttribute(attn_mma_kernel,
                         cudaFuncAttributeMaxDynamicSharedMemorySize, ATTN_SMEM);

    // 1. pack mask
    mask_pack_kernel<<<(BATCH*SEQ*SEQ/64)/256, 256>>>((const int4*)mask,
        (unsigned long long*)p_bm);

    // 2. split all to fp16
    SplitAll sa;
    sa.src[0] = (const float4*)q;  sa.src[1] = (const float4*)k;
    sa.src[2] = (const float4*)v;
    sa.src[3] = (const float4*)Wq; sa.src[4] = (const float4*)Wk;
    sa.src[5] = (const float4*)Wv; sa.src[6] = (const float4*)Wo;
    for (int i = 0; i < 3; i++) sa.dst[i] = (uint32_t*)(xf + i * XN);
    for (int i = 0; i < 4; i++) sa.dst[3+i] = (uint32_t*)(wf + i * WN);
    split_all_kernel<<<SPLIT_BLOCKS, 256>>>(sa);

    // 3. fused QKV projections (Q scaled by log2e/8)
    QkvArgs qa;
    qa.a[0] = xf;          qa.a[1] = xf + XN;     qa.a[2] = xf + 2*XN;
    qa.w[0] = wf;          qa.w[1] = wf + WN;     qa.w[2] = wf + 2*WN;
    qa.bias[0] = bq; qa.bias[1] = bk; qa.bias[2] = bv;
    qa.o[0] = (uint32_t*)p_qf16;
    qa.o[1] = (uint32_t*)p_kf16;
    qa.o[2] = (uint32_t*)p_vf16;
    qa.scale[0] = 0.125f * LOG2E; qa.scale[1] = 1.0f; qa.scale[2] = 1.0f;
    dim3 gq(DMODEL / BN, MTOT / BM, 3);
    gemm_qkv_kernel<<<gq, 256, GEMM_SMEM>>>(qa);

    // 4. attention
    dim3 ag(SEQ / 128, NHEADS, BATCH);
    attn_mma_kernel<<<ag, 256, ATTN_SMEM>>>(
        (const __nv_bfloat16*)p_qf16, (const __nv_bfloat16*)p_kf16,
        (const __nv_bfloat16*)p_vf16,
        (const unsigned long long*)p_bm, (uint32_t*)p_jf16);

    // 5. output projection (fp32 out)
    dim3 gg(DMODEL / BN, MTOT / BM);
    gemm_out_kernel<<<gg, 256, GEMM_SMEM>>>(
        (const __nv_bfloat16*)p_jf16, wf + 3*WN, bo, out);
}

// round 16
// speedup vs baseline: 2.5120x; 1.0965x over previous
#include <cuda_runtime.h>
#include <cuda_bf16.h>
#include <cuda_fp16.h>
#include <cstdint>
#include <math.h>

#define BATCH 2
#define SEQ   2048
#define DMODEL 1024
#define NHEADS 16
#define HDIM  64
#define MTOT  (BATCH*SEQ)   // 4096
#define LOG2E 1.44269504088896f

// ---------------- scratch (allocation-free rule: device globals) -----------
__device__ __nv_bfloat16 g_xf16[3*MTOT*DMODEL];    // fp16: q,k,v inputs
__device__ __nv_bfloat16 g_wf16[4*DMODEL*DMODEL];  // fp16: Wq,Wk,Wv,Wo
__device__ __nv_bfloat16 g_qf16[MTOT*DMODEL];      // fp16 (scaled Q)
__device__ __nv_bfloat16 g_kf16[MTOT*DMODEL];      // fp16 K
__device__ __nv_bfloat16 g_vf16[MTOT*DMODEL];      // fp16 V
__device__ __nv_bfloat16 g_jf16[MTOT*DMODEL];      // fp16 joint
__device__ unsigned long long g_maskbits[(size_t)BATCH*SEQ*SEQ/64];

// ---------------- helpers ---------------------------------------------------
__device__ __forceinline__ uint32_t smem_u32(const void* p) {
    uint32_t a;
    asm("{ .reg .u64 t; cvta.to.shared.u64 t, %1; cvt.u32.u64 %0, t; }"
        : "=r"(a) : "l"(p));
    return a;
}
__device__ __forceinline__ void cp16(uint32_t s, const void* g) {
    asm volatile("cp.async.cg.shared.global [%0], [%1], 16;" :: "r"(s), "l"(g));
}
#define CP_COMMIT()  asm volatile("cp.async.commit_group;" ::: "memory")
#define CP_WAIT(n)   asm volatile("cp.async.wait_group %0;" :: "n"(n) : "memory")

__device__ __forceinline__ void ldsm_x4(uint32_t* r, uint32_t addr) {
    asm volatile("ldmatrix.sync.aligned.m8n8.x4.shared.b16 {%0,%1,%2,%3}, [%4];"
                 : "=r"(r[0]), "=r"(r[1]), "=r"(r[2]), "=r"(r[3]) : "r"(addr));
}
__device__ __forceinline__ void ldsm_x4_t(uint32_t* r, uint32_t addr) {
    asm volatile("ldmatrix.sync.aligned.m8n8.x4.trans.shared.b16 {%0,%1,%2,%3}, [%4];"
                 : "=r"(r[0]), "=r"(r[1]), "=r"(r[2]), "=r"(r[3]) : "r"(addr));
}
__device__ __forceinline__ void ldsm_x2_t(uint32_t* r, uint32_t addr) {
    asm volatile("ldmatrix.sync.aligned.m8n8.x2.trans.shared.b16 {%0,%1}, [%2];"
                 : "=r"(r[0]), "=r"(r[1]) : "r"(addr));
}
__device__ __forceinline__ void mma16816h(float* d, const uint32_t* a,
                                          const uint32_t* b) {
    asm volatile(
        "mma.sync.aligned.m16n8k16.row.col.f32.f16.f16.f32 "
        "{%0,%1,%2,%3}, {%4,%5,%6,%7}, {%8,%9}, {%0,%1,%2,%3};"
        : "+f"(d[0]), "+f"(d[1]), "+f"(d[2]), "+f"(d[3])
        : "r"(a[0]), "r"(a[1]), "r"(a[2]), "r"(a[3]), "r"(b[0]), "r"(b[1]));
}
__device__ __forceinline__ uint32_t pack_f16(float x, float y) {
    __half2 h = __floats2half2_rn(x, y);
    return *reinterpret_cast<uint32_t*>(&h);
}
__device__ __forceinline__ uint32_t h2ex2(uint32_t h) {
    uint32_t r;
    asm("ex2.approx.f16x2 %0, %1;" : "=r"(r) : "r"(h));
    return r;
}

// ---------------------------------------------------------------------------
// split_all: all 7 tensors -> fp16 single
// ---------------------------------------------------------------------------
struct SplitAll {
    const float4* src[7];
    uint32_t* dst[7];
};
#define NX_BLK 4096
#define NW_BLK 1024
#define SPLIT_BLOCKS (3*NX_BLK + 4*NW_BLK)

__global__ __launch_bounds__(256)
void split_all_kernel(SplitAll a)
{
    int bid = blockIdx.x;
    int seg, idx;
    if (bid < 3 * NX_BLK) { seg = bid / NX_BLK; idx = (bid % NX_BLK) * 256 + threadIdx.x; }
    else { int r = bid - 3 * NX_BLK; seg = 3 + r / NW_BLK; idx = (r % NW_BLK) * 256 + threadIdx.x; }
    float4 v = a.src[seg][idx];
    uint32_t* dst = a.dst[seg];
    dst[2*idx]   = pack_f16(v.x, v.y);
    dst[2*idx+1] = pack_f16(v.z, v.w);
}

// ---------------------------------------------------------------------------
// mask pack
// ---------------------------------------------------------------------------
__global__ __launch_bounds__(256)
void mask_pack_kernel(const int4* __restrict__ mask, unsigned long long* __restrict__ bm)
{
    int i = blockIdx.x * 256 + threadIdx.x;
    const int4* p = mask + (size_t)i * 16;
    unsigned long long w = 0;
    #pragma unroll
    for (int j = 0; j < 16; j++) {
        int4 v = p[j];
        w |= ((unsigned long long)(v.x != 0)) << (j*4);
        w |= ((unsigned long long)(v.y != 0)) << (j*4+1);
        w |= ((unsigned long long)(v.z != 0)) << (j*4+2);
        w |= ((unsigned long long)(v.w != 0)) << (j*4+3);
    }
    bm[i] = w;
}

// ---------------------------------------------------------------------------
// GEMM body: A fp16 x W fp16 -> 1 MMA. CTA 128x128, BK=64.
// 8 warps as 2m x 4n (warp tile 64x32) -> 2 CTAs/SM.
// ---------------------------------------------------------------------------
#define BM 128
#define BN 128
#define BK 64
#define NCHUNK (DMODEL / BK)
#define GROWB 144
#define G_MAT_B (128 * GROWB)
#define OFF_A  0
#define OFF_B  G_MAT_B
#define STAGE_B (2 * G_MAT_B)
#define GEMM_SMEM (2 * STAGE_B)

__device__ __forceinline__ void gemm_body(
    const __nv_bfloat16* __restrict__ Af,
    const __nv_bfloat16* __restrict__ Wf,
    const float* __restrict__ bias,
    float* __restrict__ outf, uint32_t* __restrict__ outh,
    float scale, int omode, uint32_t sbase)
{
    const int tid  = threadIdx.x;
    const int lane = tid & 31;
    const int wid  = tid >> 5;
    const int wm   = (wid & 1) * 64;
    const int wn   = (wid >> 1) * 32;
    const int n0   = blockIdx.x * BN;
    const int m0   = blockIdx.y * BM;

    float c[4][4][4];
    #pragma unroll
    for (int mt = 0; mt < 4; mt++)
        #pragma unroll
        for (int nt = 0; nt < 4; nt++)
            #pragma unroll
            for (int j = 0; j < 4; j++) c[mt][nt][j] = 0.0f;

    auto load_chunk = [&](int ck, int s) {
        uint32_t st = sbase + s * STAGE_B;
        int k0 = ck * BK;
        #pragma unroll
        for (int u = tid; u < 1024; u += 256) {
            int r = u >> 3, c16 = u & 7;
            uint32_t d = st + r * GROWB + c16 * 16;
            size_t g = (size_t)(m0 + r) * DMODEL + k0 + c16 * 8;
            cp16(d + OFF_A, Af + g);
        }
        #pragma unroll
        for (int u = tid; u < 1024; u += 256) {
            int r = u >> 3, c16 = u & 7;
            uint32_t d = st + r * GROWB + c16 * 16;
            size_t g = (size_t)(n0 + r) * DMODEL + k0 + c16 * 8;
            cp16(d + OFF_B, Wf + g);
        }
    };

    load_chunk(0, 0); CP_COMMIT();

    const int a_row  = lane & 15;
    const int a_kb   = ((lane >> 4) & 1) * 16;
    const int b_row  = (lane & 7) + ((lane >> 4) & 1) * 8;
    const int b_kb   = ((lane >> 3) & 1) * 16;

    for (int ck = 0; ck < NCHUNK; ck++) {
        int s = ck & 1;
        if (ck + 1 < NCHUNK) {
            load_chunk(ck + 1, s ^ 1); CP_COMMIT();
            CP_WAIT(1);
        } else {
            CP_WAIT(0);
        }
        __syncthreads();

        uint32_t st = sbase + s * STAGE_B;
        #pragma unroll
        for (int ks = 0; ks < 4; ks++) {
            int kb = ks * 32;
            uint32_t ah[4][4];
            #pragma unroll
            for (int mt = 0; mt < 4; mt++) {
                uint32_t addr = st + OFF_A + (wm + mt * 16 + a_row) * GROWB + kb + a_kb;
                ldsm_x4(ah[mt], addr);
            }
            #pragma unroll
            for (int np = 0; np < 2; np++) {
                uint32_t bh4[4];
                uint32_t addr = st + OFF_B + (wn + np * 16 + b_row) * GROWB + kb + b_kb;
                ldsm_x4(bh4, addr);
                #pragma unroll
                for (int mt = 0; mt < 4; mt++) {
                    mma16816h(c[mt][np*2],   ah[mt], bh4);
                    mma16816h(c[mt][np*2+1], ah[mt], bh4 + 2);
                }
            }
        }
        __syncthreads();
    }

    const int g  = lane >> 2;
    const int cq = (lane & 3) * 2;
    #pragma unroll
    for (int mt = 0; mt < 4; mt++) {
        #pragma unroll
        for (int nt = 0; nt < 4; nt++) {
            int col = n0 + wn + nt * 8 + cq;
            float2 bv = *(const float2*)(bias + col);
            int r0 = m0 + wm + mt * 16 + g;
            float x0 = c[mt][nt][0] + bv.x, y0 = c[mt][nt][1] + bv.y;
            float x1 = c[mt][nt][2] + bv.x, y1 = c[mt][nt][3] + bv.y;
            if (omode == 0) {
                *(float2*)(outf + (size_t)r0 * DMODEL + col) = make_float2(x0, y0);
                *(float2*)(outf + (size_t)(r0 + 8) * DMODEL + col) = make_float2(x1, y1);
            } else {
                outh[((size_t)r0 * DMODEL + col) >> 1] = pack_f16(x0 * scale, y0 * scale);
                outh[(((size_t)(r0 + 8)) * DMODEL + col) >> 1] = pack_f16(x1 * scale, y1 * scale);
            }
        }
    }
}

struct QkvArgs {
    const __nv_bfloat16* a[3];
    const __nv_bfloat16* w[3];
    const float* bias[3];
    uint32_t* o[3];
    float scale[3];
};

__global__ __launch_bounds__(256, 2)
void gemm_qkv_kernel(QkvArgs a)
{
    extern __shared__ char smraw[];
    int z = blockIdx.z;
    gemm_body(a.a[z], a.w[z], a.bias[z], nullptr, a.o[z], a.scale[z], 2,
              smem_u32(smraw));
}

__global__ __launch_bounds__(256, 2)
void gemm_out_kernel(const __nv_bfloat16* __restrict__ Af,
                     const __nv_bfloat16* __restrict__ Wf,
                     const float* __restrict__ bias, float* __restrict__ outf)
{
    extern __shared__ char smraw[];
    gemm_body(Af, Wf, bias, outf, nullptr, 1.0f, 0, smem_u32(smraw));
}

// ---------------------------------------------------------------------------
// FA2 attention: fp16, CTA = 128 threads (4 warps), Q tile 64 rows, KV tile 64.
// 3 CTAs/SM (launch_bounds). ex2.f16x2 softmax, ones-column MMA row sums.
// ---------------------------------------------------------------------------
#define AROWB 144
#define AQ_B   (64 * AROWB)        // 9216
#define AKV_B  (64 * AROWB)        // 9216
#define A_OFF_K  0
#define A_OFF_V  AKV_B
#define A_STAGE_B (2 * AKV_B)      // 18432
#define ATTN_SMEM (AQ_B + 2 * A_STAGE_B)   // 46080
#define NKT (SEQ / 64)             // 32
#define MWORDS (SEQ / 64)          // 32

__global__ __launch_bounds__(128, 3)
void attn_mma_kernel(const __nv_bfloat16* __restrict__ qf16,
                     const __nv_bfloat16* __restrict__ kf16,
                     const __nv_bfloat16* __restrict__ vf16,
                     const unsigned long long* __restrict__ bm,
                     uint32_t* __restrict__ jf)
{
    extern __shared__ char smraw[];
    const uint32_t sbase = smem_u32(smraw);
    const int tid  = threadIdx.x;
    const int lane = tid & 31;
    const int wid  = tid >> 5;        // 0..3
    const int wm   = wid * 16;
    const int b    = blockIdx.z;
    const int h    = blockIdx.y;
    const int q0   = blockIdx.x * 64;

    // ---- load Q tile: 64 rows x 64 f16 = 512 cp16 ----
    #pragma unroll
    for (int u = tid; u < 512; u += 128) {
        int r = u >> 3, c16 = u & 7;
        uint32_t d = sbase + r * AROWB + c16 * 16;
        size_t g = ((size_t)(b * SEQ + q0 + r)) * DMODEL + h * HDIM + c16 * 8;
        cp16(d, qf16 + g);
    }
    CP_COMMIT();

    // ---- init ones-column in V pad (bytes 128..143), both stages ----
    {
        // 128 threads cover 2 stages x 64 rows
        int stg = tid >> 6, r = tid & 63;
        uint32_t d = sbase + AQ_B + stg * A_STAGE_B + A_OFF_V + r * AROWB + 128;
        uint32_t one2 = 0x3C003C00u;
        asm volatile("st.shared.v4.b32 [%0], {%1, %1, %1, %1};"
                     :: "r"(d), "r"(one2) : "memory");
    }

    auto load_kv = [&](int kt, int s) {
        uint32_t st = sbase + AQ_B + s * A_STAGE_B;
        int k0 = kt * 64;
        #pragma unroll
        for (int u = tid; u < 512; u += 128) {
            int r = u >> 3, c16 = u & 7;
            uint32_t d = st + r * AROWB + c16 * 16;
            size_t g = ((size_t)(b * SEQ + k0 + r)) * DMODEL + h * HDIM + c16 * 8;
            cp16(d + A_OFF_K, kf16 + g);
            cp16(d + A_OFF_V, vf16 + g);
        }
    };

    load_kv(0, 0); CP_COMMIT();
    CP_WAIT(1);
    __syncthreads();

    // ---- preload Q fragments ----
    uint32_t aq[4][4];
    {
        const int a_row = lane & 15;
        const int a_kb  = ((lane >> 4) & 1) * 16;
        #pragma unroll
        for (int kc = 0; kc < 4; kc++) {
            uint32_t addr = sbase + (wm + a_row) * AROWB + kc * 32 + a_kb;
            ldsm_x4(aq[kc], addr);
        }
    }

    const int g_    = lane >> 2;
    const int cq    = (lane & 3) * 2;
    const int b_row = (lane & 7) + ((lane >> 4) & 1) * 8;
    const int b_kb  = ((lane >> 3) & 1) * 16;
    const int v_row = lane & 15;
    const int v_col = (lane >> 4) * 8;

    const size_t bmrow0 = ((size_t)b * SEQ + q0 + wm + g_) * MWORDS;
    const size_t bmrow1 = bmrow0 + (size_t)8 * MWORDS;

    float o[8][4];
    #pragma unroll
    for (int i = 0; i < 8; i++)
        #pragma unroll
        for (int j = 0; j < 4; j++) o[i][j] = 0.0f;
    float m0r = -INFINITY, m1r = -INFINITY, l0r = 0.0f, l1r = 0.0f;

    for (int kt = 0; kt < NKT; kt++) {
        int s = kt & 1;
        __syncthreads();
        if (kt + 1 < NKT) {
            load_kv(kt + 1, s ^ 1); CP_COMMIT();
            CP_WAIT(1);
        } else {
            CP_WAIT(0);
        }
        __syncthreads();

        uint32_t st = sbase + AQ_B + s * A_STAGE_B;

        unsigned long long mw0 = __ldg(bm + bmrow0 + kt);
        unsigned long long mw1 = __ldg(bm + bmrow1 + kt);

        // ---- S = Q K^T (64 cols) ----
        float sc[8][4];
        #pragma unroll
        for (int i = 0; i < 8; i++)
            #pragma unroll
            for (int j = 0; j < 4; j++) sc[i][j] = 0.0f;

        #pragma unroll
        for (int kc = 0; kc < 4; kc++) {
            #pragma unroll
            for (int np = 0; np < 4; np++) {
                uint32_t kh4[4];
                uint32_t addr = st + A_OFF_K + (np * 16 + b_row) * AROWB + kc * 32 + b_kb;
                ldsm_x4(kh4, addr);
                mma16816h(sc[np*2],   aq[kc], kh4);
                mma16816h(sc[np*2+1], aq[kc], kh4 + 2);
            }
        }

        // ---- mask ----
        #pragma unroll
        for (int nt = 0; nt < 8; nt++) {
            int c0 = nt * 8 + cq;
            if (!((mw0 >> c0) & 1))       sc[nt][0] = -1000000000.0f;
            if (!((mw0 >> (c0 + 1)) & 1)) sc[nt][1] = -1000000000.0f;
            if (!((mw1 >> c0) & 1))       sc[nt][2] = -1000000000.0f;
            if (!((mw1 >> (c0 + 1)) & 1)) sc[nt][3] = -1000000000.0f;
        }

        // ---- row max ----
        float mx0 = sc[0][0], mx1 = sc[0][2];
        #pragma unroll
        for (int nt = 0; nt < 8; nt++) {
            mx0 = fmaxf(mx0, fmaxf(sc[nt][0], sc[nt][1]));
            mx1 = fmaxf(mx1, fmaxf(sc[nt][2], sc[nt][3]));
        }
        mx0 = fmaxf(mx0, __shfl_xor_sync(0xffffffff, mx0, 1));
        mx0 = fmaxf(mx0, __shfl_xor_sync(0xffffffff, mx0, 2));
        mx1 = fmaxf(mx1, __shfl_xor_sync(0xffffffff, mx1, 1));
        mx1 = fmaxf(mx1, __shfl_xor_sync(0xffffffff, mx1, 2));

        float mn0 = fmaxf(m0r, mx0), mn1 = fmaxf(m1r, mx1);
        float al0 = exp2f(m0r - mn0), al1 = exp2f(m1r - mn1);
        m0r = mn0; m1r = mn1;

        // ---- P = ex2(s - mn) in packed fp16 ----
        uint32_t ph[4][4];
        #pragma unroll
        for (int tp = 0; tp < 4; tp++) {
            ph[tp][0] = h2ex2(pack_f16(sc[2*tp][0] - mn0,   sc[2*tp][1] - mn0));
            ph[tp][1] = h2ex2(pack_f16(sc[2*tp][2] - mn1,   sc[2*tp][3] - mn1));
            ph[tp][2] = h2ex2(pack_f16(sc[2*tp+1][0] - mn0, sc[2*tp+1][1] - mn0));
            ph[tp][3] = h2ex2(pack_f16(sc[2*tp+1][2] - mn1, sc[2*tp+1][3] - mn1));
        }

        // ---- rescale O ----
        #pragma unroll
        for (int nt = 0; nt < 8; nt++) {
            o[nt][0] *= al0; o[nt][1] *= al0;
            o[nt][2] *= al1; o[nt][3] *= al1;
        }

        // ---- row sums via ones-column MMA + O += P V ----
        float lsum[4] = {0.0f, 0.0f, 0.0f, 0.0f};
        #pragma unroll
        for (int tp = 0; tp < 4; tp++) {
            uint32_t vo2[2];
            uint32_t addr1 = st + A_OFF_V + (tp * 16 + v_row) * AROWB + 128;
            ldsm_x2_t(vo2, addr1);
            mma16816h(lsum, ph[tp], vo2);
        }
        #pragma unroll
        for (int nt2 = 0; nt2 < 4; nt2++) {
            #pragma unroll
            for (int tp = 0; tp < 4; tp++) {
                uint32_t vh4[4];
                uint32_t addr = st + A_OFF_V + (tp * 16 + v_row) * AROWB
                              + (nt2 * 16 + v_col) * 2;
                ldsm_x4_t(vh4, addr);
                mma16816h(o[nt2*2],   ph[tp], vh4);
                mma16816h(o[nt2*2+1], ph[tp], vh4 + 2);
            }
        }

        l0r = l0r * al0 + lsum[0];
        l1r = l1r * al1 + lsum[2];
    }

    // ---- epilogue: joint as fp16 ----
    float inv0 = 1.0f / l0r, inv1 = 1.0f / l1r;
    size_t row0 = ((size_t)(b * SEQ + q0 + wm + g_)) * DMODEL + h * HDIM;
    #pragma unroll
    for (int nt = 0; nt < 8; nt++) {
        int col = nt * 8 + cq;
        jf[(row0 + col) >> 1] = pack_f16(o[nt][0] * inv0, o[nt][1] * inv0);
        jf[(row0 + (size_t)8 * DMODEL + col) >> 1] =
            pack_f16(o[nt][2] * inv1, o[nt][3] * inv1);
    }
}

// ---------------------------------------------------------------------------
extern "C" void kernel_launch(void* const* d_in, const int* in_sizes, int n_in,
                              void* d_out, int out_size)
{
    const float* q    = (const float*)d_in[0];
    const float* k    = (const float*)d_in[1];
    const float* v    = (const float*)d_in[2];
    const int*   mask = (const int*)  d_in[3];
    const float* Wq   = (const float*)d_in[4];
    const float* bq   = (const float*)d_in[5];
    const float* Wk   = (const float*)d_in[6];
    const float* bk   = (const float*)d_in[7];
    const float* Wv   = (const float*)d_in[8];
    const float* bv   = (const float*)d_in[9];
    const float* Wo   = (const float*)d_in[10];
    const float* bo   = (const float*)d_in[11];
    float* out = (float*)d_out;

    void *p_xf16, *p_wf16, *p_qf16, *p_kf16, *p_vf16, *p_jf16, *p_bm;
    cudaGetSymbolAddress(&p_xf16, g_xf16);
    cudaGetSymbolAddress(&p_wf16, g_wf16);
    cudaGetSymbolAddress(&p_qf16, g_qf16);
    cudaGetSymbolAddress(&p_kf16, g_kf16);
    cudaGetSymbolAddress(&p_vf16, g_vf16);
    cudaGetSymbolAddress(&p_jf16, g_jf16);
    cudaGetSymbolAddress(&p_bm, g_maskbits);

    __nv_bfloat16* xf = (__nv_bfloat16*)p_xf16;
    __nv_bfloat16* wf = (__nv_bfloat16*)p_wf16;

    const size_t XN = (size_t)MTOT * DMODEL;
    const size_t WN = (size_t)DMODEL * DMODEL;

    cudaFuncSetAttribute(gemm_qkv_kernel,
                         cudaFuncAttributeMaxDynamicSharedMemorySize, GEMM_SMEM);
    cudaFuncSetAttribute(gemm_out_kernel,
                         cudaFuncAttributeMaxDynamicSharedMemorySize, GEMM_SMEM);
    cudaFuncSetAttribute(attn_mma_kernel,
                         cudaFuncAttributeMaxDynamicSharedMemorySize, ATTN_SMEM);

    // 1. pack mask
    mask_pack_kernel<<<(BATCH*SEQ*SEQ/64)/256, 256>>>((const int4*)mask,
        (unsigned long long*)p_bm);

    // 2. split all to fp16
    SplitAll sa;
    sa.src[0] = (const float4*)q;  sa.src[1] = (const float4*)k;
    sa.src[2] = (const float4*)v;
    sa.src[3] = (const float4*)Wq; sa.src[4] = (const float4*)Wk;
    sa.src[5] = (const float4*)Wv; sa.src[6] = (const float4*)Wo;
    for (int i = 0; i < 3; i++) sa.dst[i] = (uint32_t*)(xf + i * XN);
    for (int i = 0; i < 4; i++) sa.dst[3+i] = (uint32_t*)(wf + i * WN);
    split_all_kernel<<<SPLIT_BLOCKS, 256>>>(sa);

    // 3. fused QKV projections (Q scaled by log2e/8)
    QkvArgs qa;
    qa.a[0] = xf;          qa.a[1] = xf + XN;     qa.a[2] = xf + 2*XN;
    qa.w[0] = wf;          qa.w[1] = wf + WN;     qa.w[2] = wf + 2*WN;
    qa.bias[0] = bq; qa.bias[1] = bk; qa.bias[2] = bv;
    qa.o[0] = (uint32_t*)p_qf16;
    qa.o[1] = (uint32_t*)p_kf16;
    qa.o[2] = (uint32_t*)p_vf16;
    qa.scale[0] = 0.125f * LOG2E; qa.scale[1] = 1.0f; qa.scale[2] = 1.0f;
    dim3 gq(DMODEL / BN, MTOT / BM, 3);
    gemm_qkv_kernel<<<gq, 256, GEMM_SMEM>>>(qa);

    // 4. attention (128-thread CTAs, 3 per SM)
    dim3 ag(SEQ / 64, NHEADS, BATCH);   // 32 x 16 x 2 = 1024
    attn_mma_kernel<<<ag, 128, ATTN_SMEM>>>(
        (const __nv_bfloat16*)p_qf16, (const __nv_bfloat16*)p_kf16,
        (const __nv_bfloat16*)p_vf16,
        (const unsigned long long*)p_bm, (uint32_t*)p_jf16);

    // 5. output projection (fp32 out)
    dim3 gg(DMODEL / BN, MTOT / BM);
    gemm_out_kernel<<<gg, 256, GEMM_SMEM>>>(
        (const __nv_bfloat16*)p_jf16, wf + 3*WN, bo, out);
}

// round 17
// speedup vs baseline: 2.5600x; 1.0191x over previous
#include <cuda_runtime.h>
#include <cuda_bf16.h>
#include <cuda_fp16.h>
#include <cstdint>
#include <math.h>

#define BATCH 2
#define SEQ   2048
#define DMODEL 1024
#define NHEADS 16
#define HDIM  64
#define MTOT  (BATCH*SEQ)   // 4096
#define LOG2E 1.44269504088896f

// ---------------- scratch (allocation-free rule: device globals) -----------
__device__ __nv_bfloat16 g_xf16[3*MTOT*DMODEL];    // fp16: q,k,v inputs
__device__ __nv_bfloat16 g_wf16[4*DMODEL*DMODEL];  // fp16: Wq,Wk,Wv,Wo
__device__ __nv_bfloat16 g_qf16[MTOT*DMODEL];      // fp16 (scaled Q)
__device__ __nv_bfloat16 g_kf16[MTOT*DMODEL];      // fp16 K
__device__ __nv_bfloat16 g_vf16[MTOT*DMODEL];      // fp16 V
__device__ __nv_bfloat16 g_jf16[MTOT*DMODEL];      // fp16 joint
__device__ unsigned long long g_maskbits[(size_t)BATCH*SEQ*SEQ/64];

// ---------------- helpers ---------------------------------------------------
__device__ __forceinline__ uint32_t smem_u32(const void* p) {
    uint32_t a;
    asm("{ .reg .u64 t; cvta.to.shared.u64 t, %1; cvt.u32.u64 %0, t; }"
        : "=r"(a) : "l"(p));
    return a;
}
__device__ __forceinline__ void cp16(uint32_t s, const void* g) {
    asm volatile("cp.async.cg.shared.global [%0], [%1], 16;" :: "r"(s), "l"(g));
}
#define CP_COMMIT()  asm volatile("cp.async.commit_group;" ::: "memory")
#define CP_WAIT(n)   asm volatile("cp.async.wait_group %0;" :: "n"(n) : "memory")

__device__ __forceinline__ void ldsm_x4(uint32_t* r, uint32_t addr) {
    asm volatile("ldmatrix.sync.aligned.m8n8.x4.shared.b16 {%0,%1,%2,%3}, [%4];"
                 : "=r"(r[0]), "=r"(r[1]), "=r"(r[2]), "=r"(r[3]) : "r"(addr));
}
__device__ __forceinline__ void ldsm_x4_t(uint32_t* r, uint32_t addr) {
    asm volatile("ldmatrix.sync.aligned.m8n8.x4.trans.shared.b16 {%0,%1,%2,%3}, [%4];"
                 : "=r"(r[0]), "=r"(r[1]), "=r"(r[2]), "=r"(r[3]) : "r"(addr));
}
__device__ __forceinline__ void ldsm_x2_t(uint32_t* r, uint32_t addr) {
    asm volatile("ldmatrix.sync.aligned.m8n8.x2.trans.shared.b16 {%0,%1}, [%2];"
                 : "=r"(r[0]), "=r"(r[1]) : "r"(addr));
}
__device__ __forceinline__ void mma16816h(float* d, const uint32_t* a,
                                          const uint32_t* b) {
    asm volatile(
        "mma.sync.aligned.m16n8k16.row.col.f32.f16.f16.f32 "
        "{%0,%1,%2,%3}, {%4,%5,%6,%7}, {%8,%9}, {%0,%1,%2,%3};"
        : "+f"(d[0]), "+f"(d[1]), "+f"(d[2]), "+f"(d[3])
        : "r"(a[0]), "r"(a[1]), "r"(a[2]), "r"(a[3]), "r"(b[0]), "r"(b[1]));
}
__device__ __forceinline__ uint32_t pack_f16(float x, float y) {
    __half2 h = __floats2half2_rn(x, y);
    return *reinterpret_cast<uint32_t*>(&h);
}
__device__ __forceinline__ uint32_t h2ex2(uint32_t h) {
    uint32_t r;
    asm("ex2.approx.f16x2 %0, %1;" : "=r"(r) : "r"(h));
    return r;
}

// ---------------------------------------------------------------------------
// split_all: all 7 tensors -> fp16 single
// ---------------------------------------------------------------------------
struct SplitAll {
    const float4* src[7];
    uint32_t* dst[7];
};
#define NX_BLK 4096
#define NW_BLK 1024
#define SPLIT_BLOCKS (3*NX_BLK + 4*NW_BLK)

__global__ __launch_bounds__(256)
void split_all_kernel(SplitAll a)
{
    int bid = blockIdx.x;
    int seg, idx;
    if (bid < 3 * NX_BLK) { seg = bid / NX_BLK; idx = (bid % NX_BLK) * 256 + threadIdx.x; }
    else { int r = bid - 3 * NX_BLK; seg = 3 + r / NW_BLK; idx = (r % NW_BLK) * 256 + threadIdx.x; }
    float4 v = a.src[seg][idx];
    uint32_t* dst = a.dst[seg];
    dst[2*idx]   = pack_f16(v.x, v.y);
    dst[2*idx+1] = pack_f16(v.z, v.w);
}

// ---------------------------------------------------------------------------
// mask pack
// ---------------------------------------------------------------------------
__global__ __launch_bounds__(256)
void mask_pack_kernel(const int4* __restrict__ mask, unsigned long long* __restrict__ bm)
{
    int i = blockIdx.x * 256 + threadIdx.x;
    const int4* p = mask + (size_t)i * 16;
    unsigned long long w = 0;
    #pragma unroll
    for (int j = 0; j < 16; j++) {
        int4 v = p[j];
        w |= ((unsigned long long)(v.x != 0)) << (j*4);
        w |= ((unsigned long long)(v.y != 0)) << (j*4+1);
        w |= ((unsigned long long)(v.z != 0)) << (j*4+2);
        w |= ((unsigned long long)(v.w != 0)) << (j*4+3);
    }
    bm[i] = w;
}

// ---------------------------------------------------------------------------
// GEMM body: A fp16 x W fp16 -> 1 MMA. CTA tile 64x128, BK=64.
// 128 threads (4 warps), warp tile 64x32 -> 4 CTAs/SM.
// omode: 0=fp32 out, 2=f16 single out (scaled)
// ---------------------------------------------------------------------------
#define BM 64
#define BN 128
#define BK 64
#define NCHUNK (DMODEL / BK)          // 16
#define GROWB 144
#define A_TILE_B (64 * GROWB)         // 9216
#define B_TILE_B (128 * GROWB)        // 18432
#define OFF_A  0
#define OFF_B  A_TILE_B
#define STAGE_B (A_TILE_B + B_TILE_B) // 27648
#define GEMM_SMEM (2 * STAGE_B)       // 55296

__device__ __forceinline__ void gemm_body(
    const __nv_bfloat16* __restrict__ Af,
    const __nv_bfloat16* __restrict__ Wf,
    const float* __restrict__ bias,
    float* __restrict__ outf, uint32_t* __restrict__ outh,
    float scale, int omode, uint32_t sbase)
{
    const int tid  = threadIdx.x;
    const int lane = tid & 31;
    const int wid  = tid >> 5;        // 0..3
    const int wn   = wid * 32;        // 4 n-warps (32 cols each), full m
    const int n0   = blockIdx.x * BN;
    const int m0   = blockIdx.y * BM;

    float c[4][4][4];
    #pragma unroll
    for (int mt = 0; mt < 4; mt++)
        #pragma unroll
        for (int nt = 0; nt < 4; nt++)
            #pragma unroll
            for (int j = 0; j < 4; j++) c[mt][nt][j] = 0.0f;

    auto load_chunk = [&](int ck, int s) {
        uint32_t st = sbase + s * STAGE_B;
        int k0 = ck * BK;
        #pragma unroll
        for (int u = tid; u < 512; u += 128) {       // A: 64 x 64 f16
            int r = u >> 3, c16 = u & 7;
            uint32_t d = st + r * GROWB + c16 * 16;
            size_t g = (size_t)(m0 + r) * DMODEL + k0 + c16 * 8;
            cp16(d + OFF_A, Af + g);
        }
        #pragma unroll
        for (int u = tid; u < 1024; u += 128) {      // W: 128 x 64 f16
            int r = u >> 3, c16 = u & 7;
            uint32_t d = st + r * GROWB + c16 * 16;
            size_t g = (size_t)(n0 + r) * DMODEL + k0 + c16 * 8;
            cp16(d + OFF_B, Wf + g);
        }
    };

    load_chunk(0, 0); CP_COMMIT();

    const int a_row  = lane & 15;
    const int a_kb   = ((lane >> 4) & 1) * 16;
    const int b_row  = (lane & 7) + ((lane >> 4) & 1) * 8;
    const int b_kb   = ((lane >> 3) & 1) * 16;

    for (int ck = 0; ck < NCHUNK; ck++) {
        int s = ck & 1;
        if (ck + 1 < NCHUNK) {
            load_chunk(ck + 1, s ^ 1); CP_COMMIT();
            CP_WAIT(1);
        } else {
            CP_WAIT(0);
        }
        __syncthreads();

        uint32_t st = sbase + s * STAGE_B;
        #pragma unroll
        for (int ks = 0; ks < 4; ks++) {
            int kb = ks * 32;
            uint32_t ah[4][4];
            #pragma unroll
            for (int mt = 0; mt < 4; mt++) {
                uint32_t addr = st + OFF_A + (mt * 16 + a_row) * GROWB + kb + a_kb;
                ldsm_x4(ah[mt], addr);
            }
            #pragma unroll
            for (int np = 0; np < 2; np++) {
                uint32_t bh4[4];
                uint32_t addr = st + OFF_B + (wn + np * 16 + b_row) * GROWB + kb + b_kb;
                ldsm_x4(bh4, addr);
                #pragma unroll
                for (int mt = 0; mt < 4; mt++) {
                    mma16816h(c[mt][np*2],   ah[mt], bh4);
                    mma16816h(c[mt][np*2+1], ah[mt], bh4 + 2);
                }
            }
        }
        __syncthreads();
    }

    const int g  = lane >> 2;
    const int cq = (lane & 3) * 2;
    #pragma unroll
    for (int mt = 0; mt < 4; mt++) {
        #pragma unroll
        for (int nt = 0; nt < 4; nt++) {
            int col = n0 + wn + nt * 8 + cq;
            float2 bv = *(const float2*)(bias + col);
            int r0 = m0 + mt * 16 + g;
            float x0 = c[mt][nt][0] + bv.x, y0 = c[mt][nt][1] + bv.y;
            float x1 = c[mt][nt][2] + bv.x, y1 = c[mt][nt][3] + bv.y;
            if (omode == 0) {
                *(float2*)(outf + (size_t)r0 * DMODEL + col) = make_float2(x0, y0);
                *(float2*)(outf + (size_t)(r0 + 8) * DMODEL + col) = make_float2(x1, y1);
            } else {
                outh[((size_t)r0 * DMODEL + col) >> 1] = pack_f16(x0 * scale, y0 * scale);
                outh[(((size_t)(r0 + 8)) * DMODEL + col) >> 1] = pack_f16(x1 * scale, y1 * scale);
            }
        }
    }
}

struct QkvArgs {
    const __nv_bfloat16* a[3];
    const __nv_bfloat16* w[3];
    const float* bias[3];
    uint32_t* o[3];
    float scale[3];
};

__global__ __launch_bounds__(128, 4)
void gemm_qkv_kernel(QkvArgs a)
{
    extern __shared__ char smraw[];
    int z = blockIdx.z;
    gemm_body(a.a[z], a.w[z], a.bias[z], nullptr, a.o[z], a.scale[z], 2,
              smem_u32(smraw));
}

__global__ __launch_bounds__(128, 4)
void gemm_out_kernel(const __nv_bfloat16* __restrict__ Af,
                     const __nv_bfloat16* __restrict__ Wf,
                     const float* __restrict__ bias, float* __restrict__ outf)
{
    extern __shared__ char smraw[];
    gemm_body(Af, Wf, bias, outf, nullptr, 1.0f, 0, smem_u32(smraw));
}

// ---------------------------------------------------------------------------
// FA2 attention (R16 config): fp16, 128-thread CTAs, Q tile 64, KV tile 64,
// 3 CTAs/SM. ex2.f16x2 softmax, ones-column MMA row sums.
// ---------------------------------------------------------------------------
#define AROWB 144
#define AQ_B   (64 * AROWB)
#define AKV_B  (64 * AROWB)
#define A_OFF_K  0
#define A_OFF_V  AKV_B
#define A_STAGE_B (2 * AKV_B)
#define ATTN_SMEM (AQ_B + 2 * A_STAGE_B)   // 46080
#define NKT (SEQ / 64)
#define MWORDS (SEQ / 64)

__global__ __launch_bounds__(128, 3)
void attn_mma_kernel(const __nv_bfloat16* __restrict__ qf16,
                     const __nv_bfloat16* __restrict__ kf16,
                     const __nv_bfloat16* __restrict__ vf16,
                     const unsigned long long* __restrict__ bm,
                     uint32_t* __restrict__ jf)
{
    extern __shared__ char smraw[];
    const uint32_t sbase = smem_u32(smraw);
    const int tid  = threadIdx.x;
    const int lane = tid & 31;
    const int wid  = tid >> 5;
    const int wm   = wid * 16;
    const int b    = blockIdx.z;
    const int h    = blockIdx.y;
    const int q0   = blockIdx.x * 64;

    #pragma unroll
    for (int u = tid; u < 512; u += 128) {
        int r = u >> 3, c16 = u & 7;
        uint32_t d = sbase + r * AROWB + c16 * 16;
        size_t g = ((size_t)(b * SEQ + q0 + r)) * DMODEL + h * HDIM + c16 * 8;
        cp16(d, qf16 + g);
    }
    CP_COMMIT();

    {
        int stg = tid >> 6, r = tid & 63;
        uint32_t d = sbase + AQ_B + stg * A_STAGE_B + A_OFF_V + r * AROWB + 128;
        uint32_t one2 = 0x3C003C00u;
        asm volatile("st.shared.v4.b32 [%0], {%1, %1, %1, %1};"
                     :: "r"(d), "r"(one2) : "memory");
    }

    auto load_kv = [&](int kt, int s) {
        uint32_t st = sbase + AQ_B + s * A_STAGE_B;
        int k0 = kt * 64;
        #pragma unroll
        for (int u = tid; u < 512; u += 128) {
            int r = u >> 3, c16 = u & 7;
            uint32_t d = st + r * AROWB + c16 * 16;
            size_t g = ((size_t)(b * SEQ + k0 + r)) * DMODEL + h * HDIM + c16 * 8;
            cp16(d + A_OFF_K, kf16 + g);
            cp16(d + A_OFF_V, vf16 + g);
        }
    };

    load_kv(0, 0); CP_COMMIT();
    CP_WAIT(1);
    __syncthreads();

    uint32_t aq[4][4];
    {
        const int a_row = lane & 15;
        const int a_kb  = ((lane >> 4) & 1) * 16;
        #pragma unroll
        for (int kc = 0; kc < 4; kc++) {
            uint32_t addr = sbase + (wm + a_row) * AROWB + kc * 32 + a_kb;
            ldsm_x4(aq[kc], addr);
        }
    }

    const int g_    = lane >> 2;
    const int cq    = (lane & 3) * 2;
    const int b_row = (lane & 7) + ((lane >> 4) & 1) * 8;
    const int b_kb  = ((lane >> 3) & 1) * 16;
    const int v_row = lane & 15;
    const int v_col = (lane >> 4) * 8;

    const size_t bmrow0 = ((size_t)b * SEQ + q0 + wm + g_) * MWORDS;
    const size_t bmrow1 = bmrow0 + (size_t)8 * MWORDS;

    float o[8][4];
    #pragma unroll
    for (int i = 0; i < 8; i++)
        #pragma unroll
        for (int j = 0; j < 4; j++) o[i][j] = 0.0f;
    float m0r = -INFINITY, m1r = -INFINITY, l0r = 0.0f, l1r = 0.0f;

    for (int kt = 0; kt < NKT; kt++) {
        int s = kt & 1;
        __syncthreads();
        if (kt + 1 < NKT) {
            load_kv(kt + 1, s ^ 1); CP_COMMIT();
            CP_WAIT(1);
        } else {
            CP_WAIT(0);
        }
        __syncthreads();

        uint32_t st = sbase + AQ_B + s * A_STAGE_B;

        unsigned long long mw0 = __ldg(bm + bmrow0 + kt);
        unsigned long long mw1 = __ldg(bm + bmrow1 + kt);

        float sc[8][4];
        #pragma unroll
        for (int i = 0; i < 8; i++)
            #pragma unroll
            for (int j = 0; j < 4; j++) sc[i][j] = 0.0f;

        #pragma unroll
        for (int kc = 0; kc < 4; kc++) {
            #pragma unroll
            for (int np = 0; np < 4; np++) {
                uint32_t kh4[4];
                uint32_t addr = st + A_OFF_K + (np * 16 + b_row) * AROWB + kc * 32 + b_kb;
                ldsm_x4(kh4, addr);
                mma16816h(sc[np*2],   aq[kc], kh4);
                mma16816h(sc[np*2+1], aq[kc], kh4 + 2);
            }
        }

        #pragma unroll
        for (int nt = 0; nt < 8; nt++) {
            int c0 = nt * 8 + cq;
            if (!((mw0 >> c0) & 1))       sc[nt][0] = -1000000000.0f;
            if (!((mw0 >> (c0 + 1)) & 1)) sc[nt][1] = -1000000000.0f;
            if (!((mw1 >> c0) & 1))       sc[nt][2] = -1000000000.0f;
            if (!((mw1 >> (c0 + 1)) & 1)) sc[nt][3] = -1000000000.0f;
        }

        float mx0 = sc[0][0], mx1 = sc[0][2];
        #pragma unroll
        for (int nt = 0; nt < 8; nt++) {
            mx0 = fmaxf(mx0, fmaxf(sc[nt][0], sc[nt][1]));
            mx1 = fmaxf(mx1, fmaxf(sc[nt][2], sc[nt][3]));
        }
        mx0 = fmaxf(mx0, __shfl_xor_sync(0xffffffff, mx0, 1));
        mx0 = fmaxf(mx0, __shfl_xor_sync(0xffffffff, mx0, 2));
        mx1 = fmaxf(mx1, __shfl_xor_sync(0xffffffff, mx1, 1));
        mx1 = fmaxf(mx1, __shfl_xor_sync(0xffffffff, mx1, 2));

        float mn0 = fmaxf(m0r, mx0), mn1 = fmaxf(m1r, mx1);
        float al0 = exp2f(m0r - mn0), al1 = exp2f(m1r - mn1);
        m0r = mn0; m1r = mn1;

        uint32_t ph[4][4];
        #pragma unroll
        for (int tp = 0; tp < 4; tp++) {
            ph[tp][0] = h2ex2(pack_f16(sc[2*tp][0] - mn0,   sc[2*tp][1] - mn0));
            ph[tp][1] = h2ex2(pack_f16(sc[2*tp][2] - mn1,   sc[2*tp][3] - mn1));
            ph[tp][2] = h2ex2(pack_f16(sc[2*tp+1][0] - mn0, sc[2*tp+1][1] - mn0));
            ph[tp][3] = h2ex2(pack_f16(sc[2*tp+1][2] - mn1, sc[2*tp+1][3] - mn1));
        }

        #pragma unroll
        for (int nt = 0; nt < 8; nt++) {
            o[nt][0] *= al0; o[nt][1] *= al0;
            o[nt][2] *= al1; o[nt][3] *= al1;
        }

        float lsum[4] = {0.0f, 0.0f, 0.0f, 0.0f};
        #pragma unroll
        for (int tp = 0; tp < 4; tp++) {
            uint32_t vo2[2];
            uint32_t addr1 = st + A_OFF_V + (tp * 16 + v_row) * AROWB + 128;
            ldsm_x2_t(vo2, addr1);
            mma16816h(lsum, ph[tp], vo2);
        }
        #pragma unroll
        for (int nt2 = 0; nt2 < 4; nt2++) {
            #pragma unroll
            for (int tp = 0; tp < 4; tp++) {
                uint32_t vh4[4];
                uint32_t addr = st + A_OFF_V + (tp * 16 + v_row) * AROWB
                              + (nt2 * 16 + v_col) * 2;
                ldsm_x4_t(vh4, addr);
                mma16816h(o[nt2*2],   ph[tp], vh4);
                mma16816h(o[nt2*2+1], ph[tp], vh4 + 2);
            }
        }

        l0r = l0r * al0 + lsum[0];
        l1r = l1r * al1 + lsum[2];
    }

    float inv0 = 1.0f / l0r, inv1 = 1.0f / l1r;
    size_t row0 = ((size_t)(b * SEQ + q0 + wm + g_)) * DMODEL + h * HDIM;
    #pragma unroll
    for (int nt = 0; nt < 8; nt++) {
        int col = nt * 8 + cq;
        jf[(row0 + col) >> 1] = pack_f16(o[nt][0] * inv0, o[nt][1] * inv0);
        jf[(row0 + (size_t)8 * DMODEL + col) >> 1] =
            pack_f16(o[nt][2] * inv1, o[nt][3] * inv1);
    }
}

// ---------------------------------------------------------------------------
extern "C" void kernel_launch(void* const* d_in, const int* in_sizes, int n_in,
                              void* d_out, int out_size)
{
    const float* q    = (const float*)d_in[0];
    const float* k    = (const float*)d_in[1];
    const float* v    = (const float*)d_in[2];
    const int*   mask = (const int*)  d_in[3];
    const float* Wq   = (const float*)d_in[4];
    const float* bq   = (const float*)d_in[5];
    const float* Wk   = (const float*)d_in[6];
    const float* bk   = (const float*)d_in[7];
    const float* Wv   = (const float*)d_in[8];
    const float* bv   = (const float*)d_in[9];
    const float* Wo   = (const float*)d_in[10];
    const float* bo   = (const float*)d_in[11];
    float* out = (float*)d_out;

    void *p_xf16, *p_wf16, *p_qf16, *p_kf16, *p_vf16, *p_jf16, *p_bm;
    cudaGetSymbolAddress(&p_xf16, g_xf16);
    cudaGetSymbolAddress(&p_wf16, g_wf16);
    cudaGetSymbolAddress(&p_qf16, g_qf16);
    cudaGetSymbolAddress(&p_kf16, g_kf16);
    cudaGetSymbolAddress(&p_vf16, g_vf16);
    cudaGetSymbolAddress(&p_jf16, g_jf16);
    cudaGetSymbolAddress(&p_bm, g_maskbits);

    __nv_bfloat16* xf = (__nv_bfloat16*)p_xf16;
    __nv_bfloat16* wf = (__nv_bfloat16*)p_wf16;

    const size_t XN = (size_t)MTOT * DMODEL;
    const size_t WN = (size_t)DMODEL * DMODEL;

    cudaFuncSetAttribute(gemm_qkv_kernel,
                         cudaFuncAttributeMaxDynamicSharedMemorySize, GEMM_SMEM);
    cudaFuncSetAttribute(gemm_out_kernel,
                         cudaFuncAttributeMaxDynamicSharedMemorySize, GEMM_SMEM);
    cudaFuncSetAttribute(attn_mma_kernel,
                         cudaFuncAttributeMaxDynamicSharedMemorySize, ATTN_SMEM);

    // 1. pack mask
    mask_pack_kernel<<<(BATCH*SEQ*SEQ/64)/256, 256>>>((const int4*)mask,
        (unsigned long long*)p_bm);

    // 2. split all to fp16
    SplitAll sa;
    sa.src[0] = (const float4*)q;  sa.src[1] = (const float4*)k;
    sa.src[2] = (const float4*)v;
    sa.src[3] = (const float4*)Wq; sa.src[4] = (const float4*)Wk;
    sa.src[5] = (const float4*)Wv; sa.src[6] = (const float4*)Wo;
    for (int i = 0; i < 3; i++) sa.dst[i] = (uint32_t*)(xf + i * XN);
    for (int i = 0; i < 4; i++) sa.dst[3+i] = (uint32_t*)(wf + i * WN);
    split_all_kernel<<<SPLIT_BLOCKS, 256>>>(sa);

    // 3. fused QKV projections (Q scaled by log2e/8)
    QkvArgs qa;
    qa.a[0] = xf;          qa.a[1] = xf + XN;     qa.a[2] = xf + 2*XN;
    qa.w[0] = wf;          qa.w[1] = wf + WN;     qa.w[2] = wf + 2*WN;
    qa.bias[0] = bq; qa.bias[1] = bk; qa.bias[2] = bv;
    qa.o[0] = (uint32_t*)p_qf16;
    qa.o[1] = (uint32_t*)p_kf16;
    qa.o[2] = (uint32_t*)p_vf16;
    qa.scale[0] = 0.125f * LOG2E; qa.scale[1] = 1.0f; qa.scale[2] = 1.0f;
    dim3 gq(DMODEL / BN, MTOT / BM, 3);   // 8 x 64 x 3
    gemm_qkv_kernel<<<gq, 128, GEMM_SMEM>>>(qa);

    // 4. attention (128-thread CTAs, 3 per SM)
    dim3 ag(SEQ / 64, NHEADS, BATCH);
    attn_mma_kernel<<<ag, 128, ATTN_SMEM>>>(
        (const __nv_bfloat16*)p_qf16, (const __nv_bfloat16*)p_kf16,
        (const __nv_bfloat16*)p_vf16,
        (const unsigned long long*)p_bm, (uint32_t*)p_jf16);

    // 5. output projection (fp32 out)
    dim3 gg(DMODEL / BN, MTOT / BM);      // 8 x 64
    gemm_out_kernel<<<gg, 128, GEMM_SMEM>>>(
        (const __nv_bfloat16*)p_jf16, wf + 3*WN, bo, out);
}